// round 10
// baseline (speedup 1.0000x reference)
#include <cuda_runtime.h>
#include <cuda_bf16.h>
#include <math.h>
#include <stdint.h>

#define NQ    100000
#define NL    32
#define NN    100032
#define QD    384
#define LD    1024
#define H     128
#define EE    1000000
#define ESEE  750000
#define EPRED 250000
#define BN_EPS 1e-5f
#define SCAN_B 391               // ceil(NN/256)

// mma tile config: BM=64 x BN=128, 8 warps (4 m x 2 n), warp tile 16x64
#define BM 64
#define BK 32
#define GRID_PQ 1563             // ceil(100000/64)
#define GRID_LG 1563             // 100032/64
#define A_STRIDE_B 80            // (32+8) bf16 * 2
#define B_STRIDE_B 272           // (128+8) bf16 * 2
#define ABUF 5120                // 64 * 80
#define BBUF 8704                // 32 * 272
#define AHI_OFF 0                // 2 bufs
#define ALO_OFF 10240
#define BHI_OFF 20480            // 2 bufs
#define BLO_OFF 37888
#define SMEM_MMA 55296

// ---------------- scratch ------------------------------------------------
__device__ __align__(16) float g_xini[NN * H];
__device__ __align__(16) float g_agg [NN * H];
__device__ __align__(16) float g_x1  [NN * H];
__device__ int    g_src[ESEE];
__device__ int    g_dst[ESEE];
__device__ int    g_esrc[ESEE];
__device__ int    g_off[NN + 1];
__device__ int    g_cursor[NN];
__device__ int    g_blk[SCAN_B];
__device__ __align__(8) float2 g_degew[NN];
__device__ __align__(8) float2 g_colstats2[H];
__device__ float g_scale1[H], g_shift1[H];
__device__ float g_scale2[H], g_shift2[H];
__device__ __align__(16) __nv_bfloat16 g_wqhi[QD * H], g_wqlo[QD * H];
__device__ __align__(16) __nv_bfloat16 g_w1hi[H * H],  g_w1lo[H * H];
__device__ __align__(16) __nv_bfloat16 g_w2hi[H * H],  g_w2lo[H * H];

// ---------------- ptx helpers ----------------------------------------------
__device__ __forceinline__ unsigned smem_u32(const void* p) {
    return (unsigned)__cvta_generic_to_shared(p);
}
__device__ __forceinline__ void cp16(unsigned dst, const void* src) {
    asm volatile("cp.async.ca.shared.global [%0], [%1], 16;" :: "r"(dst), "l"(src));
}
#define CP_COMMIT() asm volatile("cp.async.commit_group;")

#define LDSM_X4(r0, r1, r2, r3, addr) \
    asm volatile("ldmatrix.sync.aligned.m8n8.x4.shared.b16 {%0,%1,%2,%3}, [%4];" \
                 : "=r"(r0), "=r"(r1), "=r"(r2), "=r"(r3) : "r"(addr))
#define LDSM_X4T(r0, r1, r2, r3, addr) \
    asm volatile("ldmatrix.sync.aligned.m8n8.x4.trans.shared.b16 {%0,%1,%2,%3}, [%4];" \
                 : "=r"(r0), "=r"(r1), "=r"(r2), "=r"(r3) : "r"(addr))
#define MMA_BF16(c, a, b) \
    asm volatile("mma.sync.aligned.m16n8k16.row.col.f32.bf16.bf16.f32 " \
                 "{%0,%1,%2,%3}, {%4,%5,%6,%7}, {%8,%9}, {%0,%1,%2,%3};" \
                 : "+f"((c)[0]), "+f"((c)[1]), "+f"((c)[2]), "+f"((c)[3]) \
                 : "r"((a)[0]), "r"((a)[1]), "r"((a)[2]), "r"((a)[3]), \
                   "r"((b)[0]), "r"((b)[1]))

__device__ __forceinline__ void split_store(char* smg, int off_hi, int off_lo,
                                            int row, int c4, float4 v) {
    __nv_bfloat16 h0 = __float2bfloat16(v.x);
    __nv_bfloat16 h1 = __float2bfloat16(v.y);
    __nv_bfloat16 h2 = __float2bfloat16(v.z);
    __nv_bfloat16 h3 = __float2bfloat16(v.w);
    __nv_bfloat16 l0 = __float2bfloat16(v.x - __bfloat162float(h0));
    __nv_bfloat16 l1 = __float2bfloat16(v.y - __bfloat162float(h1));
    __nv_bfloat16 l2 = __float2bfloat16(v.z - __bfloat162float(h2));
    __nv_bfloat16 l3 = __float2bfloat16(v.w - __bfloat162float(h3));
    uint2 hp, lp;
    hp.x = ((uint32_t)__bfloat16_as_ushort(h1) << 16) | __bfloat16_as_ushort(h0);
    hp.y = ((uint32_t)__bfloat16_as_ushort(h3) << 16) | __bfloat16_as_ushort(h2);
    lp.x = ((uint32_t)__bfloat16_as_ushort(l1) << 16) | __bfloat16_as_ushort(l0);
    lp.y = ((uint32_t)__bfloat16_as_ushort(l3) << 16) | __bfloat16_as_ushort(l2);
    *(uint2*)(smg + off_hi + row * A_STRIDE_B + c4 * 8) = hp;
    *(uint2*)(smg + off_lo + row * A_STRIDE_B + c4 * 8) = lp;
}

// ---------------- W prep ------------------------------------------------------
__global__ void prep_all_kernel(const float* __restrict__ Wq,
                                const float* __restrict__ W1,
                                const float* __restrict__ W2) {
    int idx = blockIdx.x * blockDim.x + threadIdx.x;
    const int NQW = QD * H, NW = H * H;
    float w;
    __nv_bfloat16 *dhi, *dlo;
    int j;
    if (idx < NQW)                { w = Wq[idx]; dhi = g_wqhi; dlo = g_wqlo; j = idx; }
    else if (idx < NQW + NW)      { j = idx - NQW; w = W1[j]; dhi = g_w1hi; dlo = g_w1lo; }
    else if (idx < NQW + 2 * NW)  { j = idx - NQW - NW; w = W2[j]; dhi = g_w2hi; dlo = g_w2lo; }
    else return;
    __nv_bfloat16 hi = __float2bfloat16(w);
    dhi[j] = hi;
    dlo[j] = __float2bfloat16(w - __bfloat162float(hi));
}

// ---------------- edge prep (+ zero colstats) ---------------------------------
__global__ void edge_prep_kernel(const int* __restrict__ ei,
                                 const int* __restrict__ ecs,
                                 const float* __restrict__ ewt,
                                 const float* __restrict__ Wem,
                                 const float* __restrict__ bem) {
    int i = blockIdx.x * blockDim.x + threadIdx.x;
    if (blockIdx.x == 0 && threadIdx.x < H)
        g_colstats2[threadIdx.x] = make_float2(0.f, 0.f);
    if (i >= ESEE) return;
    int e = ecs[i];
    int s = ei[e];
    int d = ei[EE + e];
    g_src[i] = s;
    g_dst[i] = d;
    float v = ewt[e] * Wem[0] + bem[0];
    v = v > 0.f ? v : 0.01f * v;
    asm volatile("red.global.add.v2.f32 [%0], {%1, %2};"
                 :: "l"(&g_degew[d]), "f"(1.0f), "f"(v) : "memory");
}

// ---------------- counting-sort scan trio --------------------------------------
__global__ void scan1_kernel() {
    __shared__ int red[256];
    int t = threadIdx.x;
    int i = blockIdx.x * 256 + t;
    int c = (i < NN) ? (int)g_degew[i].x : 0;
    red[t] = c;
    __syncthreads();
#pragma unroll
    for (int o = 128; o > 0; o >>= 1) {
        if (t < o) red[t] += red[t + o];
        __syncthreads();
    }
    if (t == 0) g_blk[blockIdx.x] = red[0];
}

__global__ void scan2_kernel() {
    __shared__ int s[512];
    int t = threadIdx.x;
    int c = (t < SCAN_B) ? g_blk[t] : 0;
    s[t] = c;
    __syncthreads();
    for (int o = 1; o < 512; o <<= 1) {
        int v = (t >= o) ? s[t - o] : 0;
        __syncthreads();
        s[t] += v;
        __syncthreads();
    }
    if (t < SCAN_B) g_blk[t] = s[t] - c;
}

__global__ void scan3_kernel() {
    __shared__ int s[256];
    int t = threadIdx.x;
    int i = blockIdx.x * 256 + t;
    int c = (i < NN) ? (int)g_degew[i].x : 0;
    s[t] = c;
    __syncthreads();
    for (int o = 1; o < 256; o <<= 1) {
        int v = (t >= o) ? s[t - o] : 0;
        __syncthreads();
        s[t] += v;
        __syncthreads();
    }
    if (i < NN) {
        int off = g_blk[blockIdx.x] + s[t] - c;
        g_off[i] = off;
        g_cursor[i] = off;
    }
    if (i == 0) g_off[NN] = ESEE;
}

__global__ void placement_kernel() {
    int i = blockIdx.x * blockDim.x + threadIdx.x;
    if (i >= ESEE) return;
    int d = g_dst[i];
    int pos = atomicAdd(&g_cursor[d], 1);
    g_esrc[pos] = g_src[i];
}

// ---------------- gather aggregation -------------------------------------------
__global__ void __launch_bounds__(256) gather_kernel(const float* __restrict__ x,
                                                     float* __restrict__ outbuf,
                                                     const float* __restrict__ sc,
                                                     const float* __restrict__ sh,
                                                     int bn) {
    int wid = threadIdx.x >> 5;
    int lane = threadIdx.x & 31;
    int node = blockIdx.x * 8 + wid;
    if (node >= NN) return;
    int o0 = g_off[node];
    int o1 = g_off[node + 1];
    float4 s4 = make_float4(1.f, 1.f, 1.f, 1.f);
    float4 h4 = make_float4(0.f, 0.f, 0.f, 0.f);
    if (bn) {
        s4 = *(const float4*)&sc[lane * 4];
        h4 = *(const float4*)&sh[lane * 4];
    }
    float4 a0 = make_float4(0.f, 0.f, 0.f, 0.f);
    float4 a1 = make_float4(0.f, 0.f, 0.f, 0.f);
    int e = o0;
    for (; e + 2 <= o1; e += 2) {
        int s0 = g_esrc[e], s1 = g_esrc[e + 1];
        float4 v0 = *(const float4*)&x[(long)s0 * H + lane * 4];
        float4 v1 = *(const float4*)&x[(long)s1 * H + lane * 4];
        if (bn) {
            v0.x = fmaf(v0.x, s4.x, h4.x); v0.x = v0.x > 0.f ? v0.x : 0.01f * v0.x;
            v0.y = fmaf(v0.y, s4.y, h4.y); v0.y = v0.y > 0.f ? v0.y : 0.01f * v0.y;
            v0.z = fmaf(v0.z, s4.z, h4.z); v0.z = v0.z > 0.f ? v0.z : 0.01f * v0.z;
            v0.w = fmaf(v0.w, s4.w, h4.w); v0.w = v0.w > 0.f ? v0.w : 0.01f * v0.w;
            v1.x = fmaf(v1.x, s4.x, h4.x); v1.x = v1.x > 0.f ? v1.x : 0.01f * v1.x;
            v1.y = fmaf(v1.y, s4.y, h4.y); v1.y = v1.y > 0.f ? v1.y : 0.01f * v1.y;
            v1.z = fmaf(v1.z, s4.z, h4.z); v1.z = v1.z > 0.f ? v1.z : 0.01f * v1.z;
            v1.w = fmaf(v1.w, s4.w, h4.w); v1.w = v1.w > 0.f ? v1.w : 0.01f * v1.w;
        }
        a0.x += v0.x; a0.y += v0.y; a0.z += v0.z; a0.w += v0.w;
        a1.x += v1.x; a1.y += v1.y; a1.z += v1.z; a1.w += v1.w;
    }
    if (e < o1) {
        int s0 = g_esrc[e];
        float4 v0 = *(const float4*)&x[(long)s0 * H + lane * 4];
        if (bn) {
            v0.x = fmaf(v0.x, s4.x, h4.x); v0.x = v0.x > 0.f ? v0.x : 0.01f * v0.x;
            v0.y = fmaf(v0.y, s4.y, h4.y); v0.y = v0.y > 0.f ? v0.y : 0.01f * v0.y;
            v0.z = fmaf(v0.z, s4.z, h4.z); v0.z = v0.z > 0.f ? v0.z : 0.01f * v0.z;
            v0.w = fmaf(v0.w, s4.w, h4.w); v0.w = v0.w > 0.f ? v0.w : 0.01f * v0.w;
        }
        a0.x += v0.x; a0.y += v0.y; a0.z += v0.z; a0.w += v0.w;
    }
    a0.x += a1.x; a0.y += a1.y; a0.z += a1.z; a0.w += a1.w;
    *(float4*)&outbuf[(long)node * H + lane * 4] = a0;
}

// ---------------- proj_q via mma.sync bf16x3 (BM=64, 2 CTA/SM) ----------------
__global__ void __launch_bounds__(256, 2) proj_q_mma(const float* __restrict__ A,
                                                     const float* __restrict__ bias,
                                                     float* __restrict__ out) {
    extern __shared__ char sm[];
    uint32_t sb = smem_u32(sm);
    char* smg = sm;
    int tid = threadIdx.x;
    int wid = tid >> 5;
    int lane = tid & 31;
    int wm = wid & 3;        // rows wm*16
    int wn = wid >> 2;       // cols wn*64
    int row0 = blockIdx.x * BM;

    float acc[8][4];
#pragma unroll
    for (int nt = 0; nt < 8; nt++)
#pragma unroll
        for (int j = 0; j < 4; j++) acc[nt][j] = 0.f;

    // A loader: 64x32 floats = 512 float4, 2 per thread
    int af_row[2], af_c4[2];
#pragma unroll
    for (int i = 0; i < 2; i++) {
        int f = tid + i * 256;
        af_row[i] = f >> 3;
        af_c4[i] = f & 7;
    }

    float4 av[2];
#pragma unroll
    for (int i = 0; i < 2; i++) {
        int grow = row0 + af_row[i];
        if (grow >= NQ) grow = 0;
        av[i] = *(const float4*)&A[(long)grow * QD + af_c4[i] * 4];
    }
#pragma unroll
    for (int i = 0; i < 2; i++) {
        int seg = tid + i * 256;
        int br = seg >> 4, c16 = seg & 15;
        cp16(sb + BHI_OFF + br * B_STRIDE_B + c16 * 16, g_wqhi + br * H + c16 * 8);
        cp16(sb + BLO_OFF + br * B_STRIDE_B + c16 * 16, g_wqlo + br * H + c16 * 8);
    }
    CP_COMMIT();
#pragma unroll
    for (int i = 0; i < 2; i++)
        split_store(smg, AHI_OFF, ALO_OFF, af_row[i], af_c4[i], av[i]);

    const int TST = QD / BK;  // 12
    for (int t = 0; t < TST; t++) {
        int buf = t & 1;
        int have_next = (t + 1 < TST);
        if (have_next) {
            int k0 = (t + 1) * BK;
            int nb = buf ^ 1;
#pragma unroll
            for (int i = 0; i < 2; i++) {
                int grow = row0 + af_row[i];
                if (grow >= NQ) grow = 0;
                av[i] = *(const float4*)&A[(long)grow * QD + k0 + af_c4[i] * 4];
            }
#pragma unroll
            for (int i = 0; i < 2; i++) {
                int seg = tid + i * 256;
                int br = seg >> 4, c16 = seg & 15;
                cp16(sb + BHI_OFF + nb * BBUF + br * B_STRIDE_B + c16 * 16,
                     g_wqhi + (k0 + br) * H + c16 * 8);
                cp16(sb + BLO_OFF + nb * BBUF + br * B_STRIDE_B + c16 * 16,
                     g_wqlo + (k0 + br) * H + c16 * 8);
            }
            CP_COMMIT();
            asm volatile("cp.async.wait_group 1;");
        } else {
            asm volatile("cp.async.wait_group 0;");
        }
        __syncthreads();

        uint32_t abase_hi = sb + AHI_OFF + buf * ABUF;
        uint32_t abase_lo = sb + ALO_OFF + buf * ABUF;
        uint32_t bbase_hi = sb + BHI_OFF + buf * BBUF;
        uint32_t bbase_lo = sb + BLO_OFF + buf * BBUF;
#pragma unroll
        for (int ks = 0; ks < 2; ks++) {
            uint32_t ah[4], al[4], bh[8][2], bl[8][2];
            uint32_t roff = (uint32_t)((wm * 16 + (lane & 15)) * A_STRIDE_B
                                       + ks * 32 + (lane >> 4) * 16);
            LDSM_X4(ah[0], ah[1], ah[2], ah[3], abase_hi + roff);
            LDSM_X4(al[0], al[1], al[2], al[3], abase_lo + roff);
#pragma unroll
            for (int np = 0; np < 4; np++) {
                uint32_t boff = (uint32_t)((ks * 16 + (lane & 15)) * B_STRIDE_B
                                           + (wn * 64 + np * 16 + (lane >> 4) * 8) * 2);
                LDSM_X4T(bh[np * 2][0], bh[np * 2][1], bh[np * 2 + 1][0], bh[np * 2 + 1][1],
                         bbase_hi + boff);
                LDSM_X4T(bl[np * 2][0], bl[np * 2][1], bl[np * 2 + 1][0], bl[np * 2 + 1][1],
                         bbase_lo + boff);
            }
#pragma unroll
            for (int nt = 0; nt < 8; nt++) {
                MMA_BF16(acc[nt], ah, bh[nt]);
                MMA_BF16(acc[nt], al, bh[nt]);
                MMA_BF16(acc[nt], ah, bl[nt]);
            }
        }
        __syncthreads();

        if (have_next) {
            int nb = buf ^ 1;
#pragma unroll
            for (int i = 0; i < 2; i++)
                split_store(smg, AHI_OFF + nb * ABUF, ALO_OFF + nb * ABUF,
                            af_row[i], af_c4[i], av[i]);
        }
    }

    int m0r = row0 + wm * 16 + (lane >> 2);
    int m1r = m0r + 8;
#pragma unroll
    for (int nt = 0; nt < 8; nt++) {
        int n = wn * 64 + nt * 8 + (lane & 3) * 2;
        float2 bv = *(const float2*)&bias[n];
        if (m0r < NQ) {
            float2 o = make_float2(acc[nt][0] + bv.x, acc[nt][1] + bv.y);
            *(float2*)&out[(long)m0r * H + n] = o;
        }
        if (m1r < NQ) {
            float2 o = make_float2(acc[nt][2] + bv.x, acc[nt][3] + bv.y);
            *(float2*)&out[(long)m1r * H + n] = o;
        }
    }
}

// ---------------- layer GEMM via mma.sync bf16x3 (BM=64, 2 CTA/SM) ------------
__global__ void __launch_bounds__(256, 2) layer_gemm_mma(
        const float* __restrict__ Ain,
        const __nv_bfloat16* __restrict__ Whi,
        const __nv_bfloat16* __restrict__ Wlo,
        const float* __restrict__ bm, const float* __restrict__ be,
        const float* __restrict__ We,
        const float* __restrict__ xprev,
        const float* __restrict__ psc, const float* __restrict__ psh,
        int prev_bn,
        float* __restrict__ out) {
    extern __shared__ char sm[];
    uint32_t sb = smem_u32(sm);
    char* smg = sm;
    int tid = threadIdx.x;
    int wid = tid >> 5;
    int lane = tid & 31;
    int wm = wid & 3;
    int wn = wid >> 2;
    int row0 = blockIdx.x * BM;

    float acc[8][4];
#pragma unroll
    for (int nt = 0; nt < 8; nt++)
#pragma unroll
        for (int j = 0; j < 4; j++) acc[nt][j] = 0.f;

    int af_row[2], af_c4[2];
#pragma unroll
    for (int i = 0; i < 2; i++) {
        int f = tid + i * 256;
        af_row[i] = f >> 3;
        af_c4[i] = f & 7;
    }

    float4 av[2];
#pragma unroll
    for (int i = 0; i < 2; i++)
        av[i] = *(const float4*)&Ain[(long)(row0 + af_row[i]) * H + af_c4[i] * 4];
#pragma unroll
    for (int i = 0; i < 2; i++) {
        int seg = tid + i * 256;
        int br = seg >> 4, c16 = seg & 15;
        cp16(sb + BHI_OFF + br * B_STRIDE_B + c16 * 16, Whi + br * H + c16 * 8);
        cp16(sb + BLO_OFF + br * B_STRIDE_B + c16 * 16, Wlo + br * H + c16 * 8);
    }
    CP_COMMIT();
#pragma unroll
    for (int i = 0; i < 2; i++)
        split_store(smg, AHI_OFF, ALO_OFF, af_row[i], af_c4[i], av[i]);

    const int TST = H / BK;  // 4
    for (int t = 0; t < TST; t++) {
        int buf = t & 1;
        int have_next = (t + 1 < TST);
        if (have_next) {
            int k0 = (t + 1) * BK;
            int nb = buf ^ 1;
#pragma unroll
            for (int i = 0; i < 2; i++)
                av[i] = *(const float4*)&Ain[(long)(row0 + af_row[i]) * H + k0 + af_c4[i] * 4];
#pragma unroll
            for (int i = 0; i < 2; i++) {
                int seg = tid + i * 256;
                int br = seg >> 4, c16 = seg & 15;
                cp16(sb + BHI_OFF + nb * BBUF + br * B_STRIDE_B + c16 * 16,
                     Whi + (k0 + br) * H + c16 * 8);
                cp16(sb + BLO_OFF + nb * BBUF + br * B_STRIDE_B + c16 * 16,
                     Wlo + (k0 + br) * H + c16 * 8);
            }
            CP_COMMIT();
            asm volatile("cp.async.wait_group 1;");
        } else {
            asm volatile("cp.async.wait_group 0;");
        }
        __syncthreads();

        uint32_t abase_hi = sb + AHI_OFF + buf * ABUF;
        uint32_t abase_lo = sb + ALO_OFF + buf * ABUF;
        uint32_t bbase_hi = sb + BHI_OFF + buf * BBUF;
        uint32_t bbase_lo = sb + BLO_OFF + buf * BBUF;
#pragma unroll
        for (int ks = 0; ks < 2; ks++) {
            uint32_t ah[4], al[4], bh[8][2], bl[8][2];
            uint32_t roff = (uint32_t)((wm * 16 + (lane & 15)) * A_STRIDE_B
                                       + ks * 32 + (lane >> 4) * 16);
            LDSM_X4(ah[0], ah[1], ah[2], ah[3], abase_hi + roff);
            LDSM_X4(al[0], al[1], al[2], al[3], abase_lo + roff);
#pragma unroll
            for (int np = 0; np < 4; np++) {
                uint32_t boff = (uint32_t)((ks * 16 + (lane & 15)) * B_STRIDE_B
                                           + (wn * 64 + np * 16 + (lane >> 4) * 8) * 2);
                LDSM_X4T(bh[np * 2][0], bh[np * 2][1], bh[np * 2 + 1][0], bh[np * 2 + 1][1],
                         bbase_hi + boff);
                LDSM_X4T(bl[np * 2][0], bl[np * 2][1], bl[np * 2 + 1][0], bl[np * 2 + 1][1],
                         bbase_lo + boff);
            }
#pragma unroll
            for (int nt = 0; nt < 8; nt++) {
                MMA_BF16(acc[nt], ah, bh[nt]);
                MMA_BF16(acc[nt], al, bh[nt]);
                MMA_BF16(acc[nt], ah, bl[nt]);
            }
        }
        __syncthreads();

        if (have_next) {
            int nb = buf ^ 1;
#pragma unroll
            for (int i = 0; i < 2; i++)
                split_store(smg, AHI_OFF + nb * ABUF, ALO_OFF + nb * ABUF,
                            af_row[i], af_c4[i], av[i]);
        }
    }

    // ---- fused epilogue: deg/sumew/residual + BN column stats ----
    int lq = lane & 3;
    int lr = lane >> 2;
    float2 ds[2];
#pragma unroll
    for (int hf = 0; hf < 2; hf++) {
        int row = row0 + wm * 16 + hf * 8 + lr;
        ds[hf] = g_degew[row];
    }

#pragma unroll
    for (int nt = 0; nt < 8; nt++) {
        int n = wn * 64 + nt * 8 + lq * 2;
        float2 cb2 = make_float2(bm[n] + be[n], bm[n + 1] + be[n + 1]);
        float2 we2 = *(const float2*)&We[n];
        float2 sc2 = make_float2(0.f, 0.f), sh2 = make_float2(0.f, 0.f);
        if (prev_bn) {
            sc2 = make_float2(psc[n], psc[n + 1]);
            sh2 = make_float2(psh[n], psh[n + 1]);
        }
        float cs0 = 0.f, cs1 = 0.f, cq0 = 0.f, cq1 = 0.f;
#pragma unroll
        for (int hf = 0; hf < 2; hf++) {
            int row = row0 + wm * 16 + hf * 8 + lr;
            float2 xp = *(const float2*)&xprev[(long)row * H + n];
            if (prev_bn) {
                float u0 = fmaf(xp.x, sc2.x, sh2.x);
                float u1 = fmaf(xp.y, sc2.y, sh2.y);
                xp.x = u0 > 0.f ? u0 : 0.01f * u0;
                xp.y = u1 > 0.f ? u1 : 0.01f * u1;
            }
            float2 dd = ds[hf];
            float v0 = acc[nt][hf * 2 + 0] + dd.x * cb2.x + dd.y * we2.x + xp.x;
            float v1 = acc[nt][hf * 2 + 1] + dd.x * cb2.y + dd.y * we2.y + xp.y;
            *(float2*)&out[(long)row * H + n] = make_float2(v0, v1);
            cs0 += v0; cq0 += v0 * v0;
            cs1 += v1; cq1 += v1 * v1;
        }
#pragma unroll
        for (int off = 4; off <= 16; off <<= 1) {
            cs0 += __shfl_xor_sync(0xffffffffu, cs0, off);
            cq0 += __shfl_xor_sync(0xffffffffu, cq0, off);
            cs1 += __shfl_xor_sync(0xffffffffu, cs1, off);
            cq1 += __shfl_xor_sync(0xffffffffu, cq1, off);
        }
        if (lr == 0) {
            asm volatile("red.global.add.v2.f32 [%0], {%1, %2};"
                         :: "l"(&g_colstats2[n]), "f"(cs0), "f"(cq0) : "memory");
            asm volatile("red.global.add.v2.f32 [%0], {%1, %2};"
                         :: "l"(&g_colstats2[n + 1]), "f"(cs1), "f"(cq1) : "memory");
        }
    }
}

// ---------------- llm projection ----------------------------------------------
__global__ void proj_l_kernel(const float* __restrict__ A,
                              const float* __restrict__ W,
                              const float* __restrict__ b) {
    int i = blockIdx.x;
    int j = threadIdx.x;
    float acc = b[j];
    for (int k = 0; k < LD; k++) acc += A[i * LD + k] * W[k * H + j];
    g_xini[(NQ + i) * H + j] = acc;
}

// ---------------- BN stat finalize (+ self-zero) -------------------------------
__global__ void finalize_kernel(const float* __restrict__ g,
                                const float* __restrict__ beta,
                                float* __restrict__ sc_out,
                                float* __restrict__ sh_out) {
    int j = threadIdx.x;
    float2 s = g_colstats2[j];
    float mu = s.x * (1.f / (float)NN);
    float var = s.y * (1.f / (float)NN) - mu * mu;
    float rstd = rsqrtf(var + BN_EPS);
    float sc = g[j] * rstd;
    sc_out[j] = sc;
    sh_out[j] = beta[j] - mu * sc;
    g_colstats2[j] = make_float2(0.f, 0.f);
}

// ---------------- edge prediction (BN2 inline) ----------------------------------
__global__ void predict_kernel(const int* __restrict__ ei,
                               const int* __restrict__ em,
                               const float* __restrict__ x2raw,
                               const float* __restrict__ sc,
                               const float* __restrict__ sh,
                               float* __restrict__ out) {
    int warp = (blockIdx.x * blockDim.x + threadIdx.x) >> 5;
    int lane = threadIdx.x & 31;
    if (warp >= EPRED) return;
    float4 s2 = *(const float4*)&sc[lane * 4];
    float4 h2 = *(const float4*)&sh[lane * 4];
    int e = em[warp];
    int s = ei[e];
    int t = ei[EE + e];
    float4 a = *(const float4*)&g_xini[s * H + lane * 4];
    float4 b = *(const float4*)&x2raw[t * H + lane * 4];
    b.x = fmaf(b.x, s2.x, h2.x);
    b.y = fmaf(b.y, s2.y, h2.y);
    b.z = fmaf(b.z, s2.z, h2.z);
    b.w = fmaf(b.w, s2.w, h2.w);
    float d = a.x * b.x + a.y * b.y + a.z * b.z + a.w * b.w;
#pragma unroll
    for (int o = 16; o; o >>= 1) d += __shfl_xor_sync(0xffffffffu, d, o);
    if (lane == 0) out[warp] = 1.f / (1.f + expf(-d * (1.f / 128.f)));
}

// ---------------- launch -----------------------------------------------------
extern "C" void kernel_launch(void* const* d_in, const int* in_sizes, int n_in,
                              void* d_out, int out_size) {
    const float* qf  = (const float*)d_in[0];
    const float* lf  = (const float*)d_in[1];
    const int*   ei  = (const int*)d_in[2];
    const int*   em  = (const int*)d_in[3];
    const int*   ecs = (const int*)d_in[4];
    const float* ewt = (const float*)d_in[5];
    const float* Wq  = (const float*)d_in[6];
    const float* bq  = (const float*)d_in[7];
    const float* Wl  = (const float*)d_in[8];
    const float* bl  = (const float*)d_in[9];
    const float* Wem = (const float*)d_in[10];
    const float* bem = (const float*)d_in[11];
    const float* W1m = (const float*)d_in[12];
    const float* b1m = (const float*)d_in[13];
    const float* W1e = (const float*)d_in[14];
    const float* b1e = (const float*)d_in[15];
    const float* W2m = (const float*)d_in[16];
    const float* b2m = (const float*)d_in[17];
    const float* W2e = (const float*)d_in[18];
    const float* b2e = (const float*)d_in[19];
    const float* g1    = (const float*)d_in[20];
    const float* beta1 = (const float*)d_in[21];
    const float* g2    = (const float*)d_in[22];
    const float* beta2 = (const float*)d_in[23];
    float* out = (float*)d_out;

    void *p_agg, *p_xini, *p_x1, *p_degew;
    void *p_sc1, *p_sh1, *p_sc2, *p_sh2;
    void *p_w1hi, *p_w1lo, *p_w2hi, *p_w2lo;
    cudaGetSymbolAddress(&p_agg, g_agg);
    cudaGetSymbolAddress(&p_xini, g_xini);
    cudaGetSymbolAddress(&p_x1, g_x1);
    cudaGetSymbolAddress(&p_degew, g_degew);
    cudaGetSymbolAddress(&p_sc1, g_scale1);
    cudaGetSymbolAddress(&p_sh1, g_shift1);
    cudaGetSymbolAddress(&p_sc2, g_scale2);
    cudaGetSymbolAddress(&p_sh2, g_shift2);
    cudaGetSymbolAddress(&p_w1hi, g_w1hi);
    cudaGetSymbolAddress(&p_w1lo, g_w1lo);
    cudaGetSymbolAddress(&p_w2hi, g_w2hi);
    cudaGetSymbolAddress(&p_w2lo, g_w2lo);

    static int smem_set = 0;
    if (!smem_set) {
        cudaFuncSetAttribute(proj_q_mma, cudaFuncAttributeMaxDynamicSharedMemorySize,
                             SMEM_MMA);
        cudaFuncSetAttribute(layer_gemm_mma, cudaFuncAttributeMaxDynamicSharedMemorySize,
                             SMEM_MMA);
        smem_set = 1;
    }

    cudaMemsetAsync(p_degew, 0, NN * sizeof(float2));                       // 0
    prep_all_kernel<<<(QD * H + 2 * H * H + 255) / 256, 256>>>(Wq, W1m, W2m); // 1
    edge_prep_kernel<<<(ESEE + 255) / 256, 256>>>(ei, ecs, ewt, Wem, bem);  // 2
    scan1_kernel<<<SCAN_B, 256>>>();                                        // 3
    scan2_kernel<<<1, 512>>>();                                             // 4
    scan3_kernel<<<SCAN_B, 256>>>();                                        // 5
    placement_kernel<<<(ESEE + 255) / 256, 256>>>();                        // 6
    proj_l_kernel<<<NL, H>>>(lf, Wl, bl);                                   // 7
    proj_q_mma<<<GRID_PQ, 256, SMEM_MMA>>>(qf, bq, (float*)p_xini);         // 8

    // ---- layer 1 ----
    gather_kernel<<<(NN + 7) / 8, 256>>>((const float*)p_xini, (float*)p_agg,
                                         nullptr, nullptr, 0);              // 9
    layer_gemm_mma<<<GRID_LG, 256, SMEM_MMA>>>(                             // 10
        (const float*)p_agg, (const __nv_bfloat16*)p_w1hi, (const __nv_bfloat16*)p_w1lo,
        b1m, b1e, W1e, (const float*)p_xini,
        nullptr, nullptr, 0, (float*)p_agg);
    finalize_kernel<<<1, H>>>(g1, beta1, (float*)p_sc1, (float*)p_sh1);     // 11

    // ---- layer 2 ----
    gather_kernel<<<(NN + 7) / 8, 256>>>((const float*)p_agg, (float*)p_x1,
                                         (const float*)p_sc1, (const float*)p_sh1, 1); // 12
    layer_gemm_mma<<<GRID_LG, 256, SMEM_MMA>>>(                             // 13
        (const float*)p_x1, (const __nv_bfloat16*)p_w2hi, (const __nv_bfloat16*)p_w2lo,
        b2m, b2e, W2e, (const float*)p_agg,
        (const float*)p_sc1, (const float*)p_sh1, 1, (float*)p_x1);
    finalize_kernel<<<1, H>>>(g2, beta2, (float*)p_sc2, (float*)p_sh2);     // 14
    predict_kernel<<<EPRED / 8, 256>>>(ei, em, (const float*)p_x1,          // 15
                                       (const float*)p_sc2, (const float*)p_sh2, out);
}

// round 11
// speedup vs baseline: 1.1122x; 1.1122x over previous
#include <cuda_runtime.h>
#include <cuda_bf16.h>
#include <math.h>
#include <stdint.h>

#define NQ    100000
#define NL    32
#define NN    100032
#define QD    384
#define LD    1024
#define H     128
#define EE    1000000
#define ESEE  750000
#define EPRED 250000
#define BN_EPS 1e-5f
#define SCAN_B 391               // ceil(NN/256)

// mma tile config (R9-proven): BM=128 x BN=128, 8 warps (4m x 2n), warp tile 32x64
#define BM 128
#define BK 32
#define GRID_TC 782
#define A_STRIDE_B 80            // (32+8) bf16 * 2
#define B_STRIDE_B 272           // (128+8) bf16 * 2
#define AHI_OFF 0                // 2 bufs * 10240
#define ALO_OFF 20480
#define BHI_OFF 40960            // 2 bufs * 8704
#define BLO_OFF 58368
#define SMEM_MMA 75776

// ---------------- scratch ------------------------------------------------
__device__ __align__(16) float g_xini[NN * H];
__device__ __align__(16) float g_agg [NN * H];
__device__ __align__(16) float g_x1  [NN * H];
__device__ int    g_src[ESEE];
__device__ int    g_dst[ESEE];
__device__ int    g_esrc[ESEE];
__device__ int    g_off[NN + 1];
__device__ int    g_cursor[NN];
__device__ int    g_blk[SCAN_B];
__device__ __align__(8) float2 g_degew[NN];
__device__ __align__(8) float2 g_colstats2[H];
__device__ float g_scale1[H], g_shift1[H];
__device__ float g_scale2[H], g_shift2[H];
__device__ __align__(16) __nv_bfloat16 g_wqhi[QD * H], g_wqlo[QD * H];
__device__ __align__(16) __nv_bfloat16 g_w1hi[H * H],  g_w1lo[H * H];
__device__ __align__(16) __nv_bfloat16 g_w2hi[H * H],  g_w2lo[H * H];

// ---------------- ptx helpers ----------------------------------------------
__device__ __forceinline__ unsigned smem_u32(const void* p) {
    return (unsigned)__cvta_generic_to_shared(p);
}
__device__ __forceinline__ void cp16(unsigned dst, const void* src) {
    asm volatile("cp.async.ca.shared.global [%0], [%1], 16;" :: "r"(dst), "l"(src));
}
#define CP_COMMIT() asm volatile("cp.async.commit_group;")

#define LDSM_X4(r0, r1, r2, r3, addr) \
    asm volatile("ldmatrix.sync.aligned.m8n8.x4.shared.b16 {%0,%1,%2,%3}, [%4];" \
                 : "=r"(r0), "=r"(r1), "=r"(r2), "=r"(r3) : "r"(addr))
#define LDSM_X4T(r0, r1, r2, r3, addr) \
    asm volatile("ldmatrix.sync.aligned.m8n8.x4.trans.shared.b16 {%0,%1,%2,%3}, [%4];" \
                 : "=r"(r0), "=r"(r1), "=r"(r2), "=r"(r3) : "r"(addr))
#define MMA_BF16(c, a, b) \
    asm volatile("mma.sync.aligned.m16n8k16.row.col.f32.bf16.bf16.f32 " \
                 "{%0,%1,%2,%3}, {%4,%5,%6,%7}, {%8,%9}, {%0,%1,%2,%3};" \
                 : "+f"((c)[0]), "+f"((c)[1]), "+f"((c)[2]), "+f"((c)[3]) \
                 : "r"((a)[0]), "r"((a)[1]), "r"((a)[2]), "r"((a)[3]), \
                   "r"((b)[0]), "r"((b)[1]))

__device__ __forceinline__ void split_store(char* smg, int off_hi, int off_lo,
                                            int row, int c4, float4 v) {
    __nv_bfloat16 h0 = __float2bfloat16(v.x);
    __nv_bfloat16 h1 = __float2bfloat16(v.y);
    __nv_bfloat16 h2 = __float2bfloat16(v.z);
    __nv_bfloat16 h3 = __float2bfloat16(v.w);
    __nv_bfloat16 l0 = __float2bfloat16(v.x - __bfloat162float(h0));
    __nv_bfloat16 l1 = __float2bfloat16(v.y - __bfloat162float(h1));
    __nv_bfloat16 l2 = __float2bfloat16(v.z - __bfloat162float(h2));
    __nv_bfloat16 l3 = __float2bfloat16(v.w - __bfloat162float(h3));
    uint2 hp, lp;
    hp.x = ((uint32_t)__bfloat16_as_ushort(h1) << 16) | __bfloat16_as_ushort(h0);
    hp.y = ((uint32_t)__bfloat16_as_ushort(h3) << 16) | __bfloat16_as_ushort(h2);
    lp.x = ((uint32_t)__bfloat16_as_ushort(l1) << 16) | __bfloat16_as_ushort(l0);
    lp.y = ((uint32_t)__bfloat16_as_ushort(l3) << 16) | __bfloat16_as_ushort(l2);
    *(uint2*)(smg + off_hi + row * A_STRIDE_B + c4 * 8) = hp;
    *(uint2*)(smg + off_lo + row * A_STRIDE_B + c4 * 8) = lp;
}

// ---------------- W prep ------------------------------------------------------
__global__ void prep_all_kernel(const float* __restrict__ Wq,
                                const float* __restrict__ W1,
                                const float* __restrict__ W2) {
    int idx = blockIdx.x * blockDim.x + threadIdx.x;
    const int NQW = QD * H, NW = H * H;
    float w;
    __nv_bfloat16 *dhi, *dlo;
    int j;
    if (idx < NQW)                { w = Wq[idx]; dhi = g_wqhi; dlo = g_wqlo; j = idx; }
    else if (idx < NQW + NW)      { j = idx - NQW; w = W1[j]; dhi = g_w1hi; dlo = g_w1lo; }
    else if (idx < NQW + 2 * NW)  { j = idx - NQW - NW; w = W2[j]; dhi = g_w2hi; dlo = g_w2lo; }
    else return;
    __nv_bfloat16 hi = __float2bfloat16(w);
    dhi[j] = hi;
    dlo[j] = __float2bfloat16(w - __bfloat162float(hi));
}

// ---------------- llm projection (split-K, 512 thr) ---------------------------
__global__ void proj_l_kernel(const float* __restrict__ A,
                              const float* __restrict__ W,
                              const float* __restrict__ b) {
    __shared__ float red[4][H];
    int i = blockIdx.x;
    int t = threadIdx.x;
    int j = t & 127;
    int seg = t >> 7;          // 0..3, k range seg*256..+256
    float acc = 0.f;
    const float* arow = A + i * LD + seg * 256;
    const float* wcol = W + (seg * 256) * H + j;
    for (int k = 0; k < 256; k++) acc += arow[k] * wcol[k * H];
    red[seg][j] = acc;
    __syncthreads();
    if (seg == 0)
        g_xini[(NQ + i) * H + j] = red[0][j] + red[1][j] + red[2][j] + red[3][j] + b[j];
}

// ---------------- edge prep (+ zero colstats) ---------------------------------
__global__ void edge_prep_kernel(const int* __restrict__ ei,
                                 const int* __restrict__ ecs,
                                 const float* __restrict__ ewt,
                                 const float* __restrict__ Wem,
                                 const float* __restrict__ bem) {
    int i = blockIdx.x * blockDim.x + threadIdx.x;
    if (blockIdx.x == 0 && threadIdx.x < H)
        g_colstats2[threadIdx.x] = make_float2(0.f, 0.f);
    if (i >= ESEE) return;
    int e = ecs[i];
    int s = ei[e];
    int d = ei[EE + e];
    g_src[i] = s;
    g_dst[i] = d;
    float v = ewt[e] * Wem[0] + bem[0];
    v = v > 0.f ? v : 0.01f * v;
    asm volatile("red.global.add.v2.f32 [%0], {%1, %2};"
                 :: "l"(&g_degew[d]), "f"(1.0f), "f"(v) : "memory");
}

// ---------------- counting-sort scan trio --------------------------------------
__global__ void scan1_kernel() {
    __shared__ int red[256];
    int t = threadIdx.x;
    int i = blockIdx.x * 256 + t;
    int c = (i < NN) ? (int)g_degew[i].x : 0;
    red[t] = c;
    __syncthreads();
#pragma unroll
    for (int o = 128; o > 0; o >>= 1) {
        if (t < o) red[t] += red[t + o];
        __syncthreads();
    }
    if (t == 0) g_blk[blockIdx.x] = red[0];
}

__global__ void scan2_kernel() {
    __shared__ int s[512];
    int t = threadIdx.x;
    int c = (t < SCAN_B) ? g_blk[t] : 0;
    s[t] = c;
    __syncthreads();
    for (int o = 1; o < 512; o <<= 1) {
        int v = (t >= o) ? s[t - o] : 0;
        __syncthreads();
        s[t] += v;
        __syncthreads();
    }
    if (t < SCAN_B) g_blk[t] = s[t] - c;
}

__global__ void scan3_kernel() {
    __shared__ int s[256];
    int t = threadIdx.x;
    int i = blockIdx.x * 256 + t;
    int c = (i < NN) ? (int)g_degew[i].x : 0;
    s[t] = c;
    __syncthreads();
    for (int o = 1; o < 256; o <<= 1) {
        int v = (t >= o) ? s[t - o] : 0;
        __syncthreads();
        s[t] += v;
        __syncthreads();
    }
    if (i < NN) {
        int off = g_blk[blockIdx.x] + s[t] - c;
        g_off[i] = off;
        g_cursor[i] = off;
    }
    if (i == 0) g_off[NN] = ESEE;
}

__global__ void placement_kernel() {
    int i = blockIdx.x * blockDim.x + threadIdx.x;
    if (i >= ESEE) return;
    int d = g_dst[i];
    int pos = atomicAdd(&g_cursor[d], 1);
    g_esrc[pos] = g_src[i];
}

// ---------------- gather aggregation (4-wide unroll) ---------------------------
__device__ __forceinline__ float4 bn_lrelu4(float4 v, float4 s4, float4 h4) {
    v.x = fmaf(v.x, s4.x, h4.x); v.x = v.x > 0.f ? v.x : 0.01f * v.x;
    v.y = fmaf(v.y, s4.y, h4.y); v.y = v.y > 0.f ? v.y : 0.01f * v.y;
    v.z = fmaf(v.z, s4.z, h4.z); v.z = v.z > 0.f ? v.z : 0.01f * v.z;
    v.w = fmaf(v.w, s4.w, h4.w); v.w = v.w > 0.f ? v.w : 0.01f * v.w;
    return v;
}
__global__ void __launch_bounds__(256) gather_kernel(const float* __restrict__ x,
                                                     float* __restrict__ outbuf,
                                                     const float* __restrict__ sc,
                                                     const float* __restrict__ sh,
                                                     int bn) {
    int wid = threadIdx.x >> 5;
    int lane = threadIdx.x & 31;
    int node = blockIdx.x * 8 + wid;
    if (node >= NN) return;
    int o0 = g_off[node];
    int o1 = g_off[node + 1];
    float4 s4 = make_float4(1.f, 1.f, 1.f, 1.f);
    float4 h4 = make_float4(0.f, 0.f, 0.f, 0.f);
    if (bn) {
        s4 = *(const float4*)&sc[lane * 4];
        h4 = *(const float4*)&sh[lane * 4];
    }
    float4 a0 = make_float4(0.f, 0.f, 0.f, 0.f);
    float4 a1 = make_float4(0.f, 0.f, 0.f, 0.f);
    float4 a2 = make_float4(0.f, 0.f, 0.f, 0.f);
    float4 a3 = make_float4(0.f, 0.f, 0.f, 0.f);
    int e = o0;
    for (; e + 4 <= o1; e += 4) {
        int s0 = g_esrc[e], s1 = g_esrc[e + 1], s2 = g_esrc[e + 2], s3 = g_esrc[e + 3];
        float4 v0 = *(const float4*)&x[(long)s0 * H + lane * 4];
        float4 v1 = *(const float4*)&x[(long)s1 * H + lane * 4];
        float4 v2 = *(const float4*)&x[(long)s2 * H + lane * 4];
        float4 v3 = *(const float4*)&x[(long)s3 * H + lane * 4];
        if (bn) {
            v0 = bn_lrelu4(v0, s4, h4); v1 = bn_lrelu4(v1, s4, h4);
            v2 = bn_lrelu4(v2, s4, h4); v3 = bn_lrelu4(v3, s4, h4);
        }
        a0.x += v0.x; a0.y += v0.y; a0.z += v0.z; a0.w += v0.w;
        a1.x += v1.x; a1.y += v1.y; a1.z += v1.z; a1.w += v1.w;
        a2.x += v2.x; a2.y += v2.y; a2.z += v2.z; a2.w += v2.w;
        a3.x += v3.x; a3.y += v3.y; a3.z += v3.z; a3.w += v3.w;
    }
    for (; e < o1; e++) {
        int s0 = g_esrc[e];
        float4 v0 = *(const float4*)&x[(long)s0 * H + lane * 4];
        if (bn) v0 = bn_lrelu4(v0, s4, h4);
        a0.x += v0.x; a0.y += v0.y; a0.z += v0.z; a0.w += v0.w;
    }
    a0.x += a1.x + a2.x + a3.x;
    a0.y += a1.y + a2.y + a3.y;
    a0.z += a1.z + a2.z + a3.z;
    a0.w += a1.w + a2.w + a3.w;
    *(float4*)&outbuf[(long)node * H + lane * 4] = a0;
}

// ---------------- proj_q via mma.sync bf16x3 (BM=128) --------------------------
__global__ void __launch_bounds__(256, 1) proj_q_mma(const float* __restrict__ A,
                                                     const float* __restrict__ bias,
                                                     float* __restrict__ out) {
    extern __shared__ char sm[];
    uint32_t sb = smem_u32(sm);
    char* smg = sm;
    int tid = threadIdx.x;
    int wid = tid >> 5;
    int lane = tid & 31;
    int wm = wid & 3;
    int wn = wid >> 2;
    int row0 = blockIdx.x * BM;

    float acc[2][8][4];
#pragma unroll
    for (int mt = 0; mt < 2; mt++)
#pragma unroll
        for (int nt = 0; nt < 8; nt++)
#pragma unroll
            for (int j = 0; j < 4; j++) acc[mt][nt][j] = 0.f;

    int af_row[4], af_c4[4];
#pragma unroll
    for (int i = 0; i < 4; i++) {
        int f = tid + i * 256;
        af_row[i] = f >> 3;
        af_c4[i] = f & 7;
    }

    float4 av[4];
#pragma unroll
    for (int i = 0; i < 4; i++) {
        int grow = row0 + af_row[i];
        if (grow >= NQ) grow = 0;
        av[i] = *(const float4*)&A[(long)grow * QD + af_c4[i] * 4];
    }
#pragma unroll
    for (int i = 0; i < 2; i++) {
        int seg = tid + i * 256;
        int br = seg >> 4, c16 = seg & 15;
        cp16(sb + BHI_OFF + br * B_STRIDE_B + c16 * 16, g_wqhi + br * H + c16 * 8);
        cp16(sb + BLO_OFF + br * B_STRIDE_B + c16 * 16, g_wqlo + br * H + c16 * 8);
    }
    CP_COMMIT();
#pragma unroll
    for (int i = 0; i < 4; i++)
        split_store(smg, AHI_OFF, ALO_OFF, af_row[i], af_c4[i], av[i]);

    const int TST = QD / BK;  // 12
    for (int t = 0; t < TST; t++) {
        int buf = t & 1;
        int have_next = (t + 1 < TST);
        if (have_next) {
            int k0 = (t + 1) * BK;
            int nb = buf ^ 1;
#pragma unroll
            for (int i = 0; i < 4; i++) {
                int grow = row0 + af_row[i];
                if (grow >= NQ) grow = 0;
                av[i] = *(const float4*)&A[(long)grow * QD + k0 + af_c4[i] * 4];
            }
#pragma unroll
            for (int i = 0; i < 2; i++) {
                int seg = tid + i * 256;
                int br = seg >> 4, c16 = seg & 15;
                cp16(sb + BHI_OFF + nb * 8704 + br * B_STRIDE_B + c16 * 16,
                     g_wqhi + (k0 + br) * H + c16 * 8);
                cp16(sb + BLO_OFF + nb * 8704 + br * B_STRIDE_B + c16 * 16,
                     g_wqlo + (k0 + br) * H + c16 * 8);
            }
            CP_COMMIT();
            asm volatile("cp.async.wait_group 1;");
        } else {
            asm volatile("cp.async.wait_group 0;");
        }
        __syncthreads();

        uint32_t abase_hi = sb + AHI_OFF + buf * 10240;
        uint32_t abase_lo = sb + ALO_OFF + buf * 10240;
        uint32_t bbase_hi = sb + BHI_OFF + buf * 8704;
        uint32_t bbase_lo = sb + BLO_OFF + buf * 8704;
#pragma unroll
        for (int ks = 0; ks < 2; ks++) {
            uint32_t ah[2][4], al[2][4], bh[8][2], bl[8][2];
#pragma unroll
            for (int mt = 0; mt < 2; mt++) {
                uint32_t roff = (uint32_t)((wm * 32 + mt * 16 + (lane & 15)) * A_STRIDE_B
                                           + ks * 32 + (lane >> 4) * 16);
                LDSM_X4(ah[mt][0], ah[mt][1], ah[mt][2], ah[mt][3], abase_hi + roff);
                LDSM_X4(al[mt][0], al[mt][1], al[mt][2], al[mt][3], abase_lo + roff);
            }
#pragma unroll
            for (int np = 0; np < 4; np++) {
                uint32_t boff = (uint32_t)((ks * 16 + (lane & 15)) * B_STRIDE_B
                                           + (wn * 64 + np * 16 + (lane >> 4) * 8) * 2);
                LDSM_X4T(bh[np * 2][0], bh[np * 2][1], bh[np * 2 + 1][0], bh[np * 2 + 1][1],
                         bbase_hi + boff);
                LDSM_X4T(bl[np * 2][0], bl[np * 2][1], bl[np * 2 + 1][0], bl[np * 2 + 1][1],
                         bbase_lo + boff);
            }
#pragma unroll
            for (int mt = 0; mt < 2; mt++)
#pragma unroll
                for (int nt = 0; nt < 8; nt++) {
                    MMA_BF16(acc[mt][nt], ah[mt], bh[nt]);
                    MMA_BF16(acc[mt][nt], al[mt], bh[nt]);
                    MMA_BF16(acc[mt][nt], ah[mt], bl[nt]);
                }
        }
        __syncthreads();

        if (have_next) {
            int nb = buf ^ 1;
#pragma unroll
            for (int i = 0; i < 4; i++)
                split_store(smg, AHI_OFF + nb * 10240, ALO_OFF + nb * 10240,
                            af_row[i], af_c4[i], av[i]);
        }
    }

#pragma unroll
    for (int mt = 0; mt < 2; mt++) {
        int m0r = row0 + wm * 32 + mt * 16 + (lane >> 2);
        int m1r = m0r + 8;
#pragma unroll
        for (int nt = 0; nt < 8; nt++) {
            int n = wn * 64 + nt * 8 + (lane & 3) * 2;
            float2 bv = *(const float2*)&bias[n];
            if (m0r < NQ) {
                float2 o = make_float2(acc[mt][nt][0] + bv.x, acc[mt][nt][1] + bv.y);
                *(float2*)&out[(long)m0r * H + n] = o;
            }
            if (m1r < NQ) {
                float2 o = make_float2(acc[mt][nt][2] + bv.x, acc[mt][nt][3] + bv.y);
                *(float2*)&out[(long)m1r * H + n] = o;
            }
        }
    }
}

// ---------------- layer GEMM via mma.sync bf16x3 (BM=128) ----------------------
__global__ void __launch_bounds__(256, 1) layer_gemm_mma(
        const float* __restrict__ Ain,
        const __nv_bfloat16* __restrict__ Whi,
        const __nv_bfloat16* __restrict__ Wlo,
        const float* __restrict__ bm, const float* __restrict__ be,
        const float* __restrict__ We,
        const float* __restrict__ xprev,
        const float* __restrict__ psc, const float* __restrict__ psh,
        int prev_bn,
        float* __restrict__ out) {
    extern __shared__ char sm[];
    uint32_t sb = smem_u32(sm);
    char* smg = sm;
    int tid = threadIdx.x;
    int wid = tid >> 5;
    int lane = tid & 31;
    int wm = wid & 3;
    int wn = wid >> 2;
    int row0 = blockIdx.x * BM;

    float acc[2][8][4];
#pragma unroll
    for (int mt = 0; mt < 2; mt++)
#pragma unroll
        for (int nt = 0; nt < 8; nt++)
#pragma unroll
            for (int j = 0; j < 4; j++) acc[mt][nt][j] = 0.f;

    int af_row[4], af_c4[4];
#pragma unroll
    for (int i = 0; i < 4; i++) {
        int f = tid + i * 256;
        af_row[i] = f >> 3;
        af_c4[i] = f & 7;
    }

    float4 av[4];
#pragma unroll
    for (int i = 0; i < 4; i++) {
        int grow = row0 + af_row[i];
        if (grow >= NN) grow = 0;
        av[i] = *(const float4*)&Ain[(long)grow * H + af_c4[i] * 4];
    }
#pragma unroll
    for (int i = 0; i < 2; i++) {
        int seg = tid + i * 256;
        int br = seg >> 4, c16 = seg & 15;
        cp16(sb + BHI_OFF + br * B_STRIDE_B + c16 * 16, Whi + br * H + c16 * 8);
        cp16(sb + BLO_OFF + br * B_STRIDE_B + c16 * 16, Wlo + br * H + c16 * 8);
    }
    CP_COMMIT();
#pragma unroll
    for (int i = 0; i < 4; i++)
        split_store(smg, AHI_OFF, ALO_OFF, af_row[i], af_c4[i], av[i]);

    const int TST = H / BK;  // 4
    for (int t = 0; t < TST; t++) {
        int buf = t & 1;
        int have_next = (t + 1 < TST);
        if (have_next) {
            int k0 = (t + 1) * BK;
            int nb = buf ^ 1;
#pragma unroll
            for (int i = 0; i < 4; i++) {
                int grow = row0 + af_row[i];
                if (grow >= NN) grow = 0;
                av[i] = *(const float4*)&Ain[(long)grow * H + k0 + af_c4[i] * 4];
            }
#pragma unroll
            for (int i = 0; i < 2; i++) {
                int seg = tid + i * 256;
                int br = seg >> 4, c16 = seg & 15;
                cp16(sb + BHI_OFF + nb * 8704 + br * B_STRIDE_B + c16 * 16,
                     Whi + (k0 + br) * H + c16 * 8);
                cp16(sb + BLO_OFF + nb * 8704 + br * B_STRIDE_B + c16 * 16,
                     Wlo + (k0 + br) * H + c16 * 8);
            }
            CP_COMMIT();
            asm volatile("cp.async.wait_group 1;");
        } else {
            asm volatile("cp.async.wait_group 0;");
        }
        __syncthreads();

        uint32_t abase_hi = sb + AHI_OFF + buf * 10240;
        uint32_t abase_lo = sb + ALO_OFF + buf * 10240;
        uint32_t bbase_hi = sb + BHI_OFF + buf * 8704;
        uint32_t bbase_lo = sb + BLO_OFF + buf * 8704;
#pragma unroll
        for (int ks = 0; ks < 2; ks++) {
            uint32_t ah[2][4], al[2][4], bh[8][2], bl[8][2];
#pragma unroll
            for (int mt = 0; mt < 2; mt++) {
                uint32_t roff = (uint32_t)((wm * 32 + mt * 16 + (lane & 15)) * A_STRIDE_B
                                           + ks * 32 + (lane >> 4) * 16);
                LDSM_X4(ah[mt][0], ah[mt][1], ah[mt][2], ah[mt][3], abase_hi + roff);
                LDSM_X4(al[mt][0], al[mt][1], al[mt][2], al[mt][3], abase_lo + roff);
            }
#pragma unroll
            for (int np = 0; np < 4; np++) {
                uint32_t boff = (uint32_t)((ks * 16 + (lane & 15)) * B_STRIDE_B
                                           + (wn * 64 + np * 16 + (lane >> 4) * 8) * 2);
                LDSM_X4T(bh[np * 2][0], bh[np * 2][1], bh[np * 2 + 1][0], bh[np * 2 + 1][1],
                         bbase_hi + boff);
                LDSM_X4T(bl[np * 2][0], bl[np * 2][1], bl[np * 2 + 1][0], bl[np * 2 + 1][1],
                         bbase_lo + boff);
            }
#pragma unroll
            for (int mt = 0; mt < 2; mt++)
#pragma unroll
                for (int nt = 0; nt < 8; nt++) {
                    MMA_BF16(acc[mt][nt], ah[mt], bh[nt]);
                    MMA_BF16(acc[mt][nt], al[mt], bh[nt]);
                    MMA_BF16(acc[mt][nt], ah[mt], bl[nt]);
                }
        }
        __syncthreads();

        if (have_next) {
            int nb = buf ^ 1;
#pragma unroll
            for (int i = 0; i < 4; i++)
                split_store(smg, AHI_OFF + nb * 10240, ALO_OFF + nb * 10240,
                            af_row[i], af_c4[i], av[i]);
        }
    }

    // ---- fused epilogue ----
    int lq = lane & 3;
    int lr = lane >> 2;
    float2 ds[2][2];
    bool rv[2][2];
#pragma unroll
    for (int mt = 0; mt < 2; mt++)
#pragma unroll
        for (int hf = 0; hf < 2; hf++) {
            int row = row0 + wm * 32 + mt * 16 + hf * 8 + lr;
            rv[mt][hf] = (row < NN);
            ds[mt][hf] = rv[mt][hf] ? g_degew[row] : make_float2(0.f, 0.f);
        }

#pragma unroll
    for (int nt = 0; nt < 8; nt++) {
        int n = wn * 64 + nt * 8 + lq * 2;
        float2 cb2 = make_float2(bm[n] + be[n], bm[n + 1] + be[n + 1]);
        float2 we2 = *(const float2*)&We[n];
        float2 sc2 = make_float2(0.f, 0.f), sh2 = make_float2(0.f, 0.f);
        if (prev_bn) {
            sc2 = make_float2(psc[n], psc[n + 1]);
            sh2 = make_float2(psh[n], psh[n + 1]);
        }
        float cs0 = 0.f, cs1 = 0.f, cq0 = 0.f, cq1 = 0.f;
#pragma unroll
        for (int mt = 0; mt < 2; mt++)
#pragma unroll
            for (int hf = 0; hf < 2; hf++) {
                if (rv[mt][hf]) {
                    int row = row0 + wm * 32 + mt * 16 + hf * 8 + lr;
                    float2 xp = *(const float2*)&xprev[(long)row * H + n];
                    if (prev_bn) {
                        float u0 = fmaf(xp.x, sc2.x, sh2.x);
                        float u1 = fmaf(xp.y, sc2.y, sh2.y);
                        xp.x = u0 > 0.f ? u0 : 0.01f * u0;
                        xp.y = u1 > 0.f ? u1 : 0.01f * u1;
                    }
                    float2 dd = ds[mt][hf];
                    float v0 = acc[mt][nt][hf * 2 + 0] + dd.x * cb2.x + dd.y * we2.x + xp.x;
                    float v1 = acc[mt][nt][hf * 2 + 1] + dd.x * cb2.y + dd.y * we2.y + xp.y;
                    *(float2*)&out[(long)row * H + n] = make_float2(v0, v1);
                    cs0 += v0; cq0 += v0 * v0;
                    cs1 += v1; cq1 += v1 * v1;
                }
            }
#pragma unroll
        for (int off = 4; off <= 16; off <<= 1) {
            cs0 += __shfl_xor_sync(0xffffffffu, cs0, off);
            cq0 += __shfl_xor_sync(0xffffffffu, cq0, off);
            cs1 += __shfl_xor_sync(0xffffffffu, cs1, off);
            cq1 += __shfl_xor_sync(0xffffffffu, cq1, off);
        }
        if (lr == 0) {
            asm volatile("red.global.add.v2.f32 [%0], {%1, %2};"
                         :: "l"(&g_colstats2[n]), "f"(cs0), "f"(cq0) : "memory");
            asm volatile("red.global.add.v2.f32 [%0], {%1, %2};"
                         :: "l"(&g_colstats2[n + 1]), "f"(cs1), "f"(cq1) : "memory");
        }
    }
}

// ---------------- BN stat finalize (+ self-zero) -------------------------------
__global__ void finalize_kernel(const float* __restrict__ g,
                                const float* __restrict__ beta,
                                float* __restrict__ sc_out,
                                float* __restrict__ sh_out) {
    int j = threadIdx.x;
    float2 s = g_colstats2[j];
    float mu = s.x * (1.f / (float)NN);
    float var = s.y * (1.f / (float)NN) - mu * mu;
    float rstd = rsqrtf(var + BN_EPS);
    float sc = g[j] * rstd;
    sc_out[j] = sc;
    sh_out[j] = beta[j] - mu * sc;
    g_colstats2[j] = make_float2(0.f, 0.f);
}

// ---------------- edge prediction (BN2 inline) ----------------------------------
__global__ void predict_kernel(const int* __restrict__ ei,
                               const int* __restrict__ em,
                               const float* __restrict__ x2raw,
                               const float* __restrict__ sc,
                               const float* __restrict__ sh,
                               float* __restrict__ out) {
    int warp = (blockIdx.x * blockDim.x + threadIdx.x) >> 5;
    int lane = threadIdx.x & 31;
    if (warp >= EPRED) return;
    float4 s2 = *(const float4*)&sc[lane * 4];
    float4 h2 = *(const float4*)&sh[lane * 4];
    int e = em[warp];
    int s = ei[e];
    int t = ei[EE + e];
    float4 a = *(const float4*)&g_xini[s * H + lane * 4];
    float4 b = *(const float4*)&x2raw[t * H + lane * 4];
    b.x = fmaf(b.x, s2.x, h2.x);
    b.y = fmaf(b.y, s2.y, h2.y);
    b.z = fmaf(b.z, s2.z, h2.z);
    b.w = fmaf(b.w, s2.w, h2.w);
    float d = a.x * b.x + a.y * b.y + a.z * b.z + a.w * b.w;
#pragma unroll
    for (int o = 16; o; o >>= 1) d += __shfl_xor_sync(0xffffffffu, d, o);
    if (lane == 0) out[warp] = 1.f / (1.f + expf(-d * (1.f / 128.f)));
}

// ---------------- launch -----------------------------------------------------
extern "C" void kernel_launch(void* const* d_in, const int* in_sizes, int n_in,
                              void* d_out, int out_size) {
    const float* qf  = (const float*)d_in[0];
    const float* lf  = (const float*)d_in[1];
    const int*   ei  = (const int*)d_in[2];
    const int*   em  = (const int*)d_in[3];
    const int*   ecs = (const int*)d_in[4];
    const float* ewt = (const float*)d_in[5];
    const float* Wq  = (const float*)d_in[6];
    const float* bq  = (const float*)d_in[7];
    const float* Wl  = (const float*)d_in[8];
    const float* bl  = (const float*)d_in[9];
    const float* Wem = (const float*)d_in[10];
    const float* bem = (const float*)d_in[11];
    const float* W1m = (const float*)d_in[12];
    const float* b1m = (const float*)d_in[13];
    const float* W1e = (const float*)d_in[14];
    const float* b1e = (const float*)d_in[15];
    const float* W2m = (const float*)d_in[16];
    const float* b2m = (const float*)d_in[17];
    const float* W2e = (const float*)d_in[18];
    const float* b2e = (const float*)d_in[19];
    const float* g1    = (const float*)d_in[20];
    const float* beta1 = (const float*)d_in[21];
    const float* g2    = (const float*)d_in[22];
    const float* beta2 = (const float*)d_in[23];
    float* out = (float*)d_out;

    void *p_agg, *p_xini, *p_x1, *p_degew;
    void *p_sc1, *p_sh1, *p_sc2, *p_sh2;
    void *p_w1hi, *p_w1lo, *p_w2hi, *p_w2lo;
    cudaGetSymbolAddress(&p_agg, g_agg);
    cudaGetSymbolAddress(&p_xini, g_xini);
    cudaGetSymbolAddress(&p_x1, g_x1);
    cudaGetSymbolAddress(&p_degew, g_degew);
    cudaGetSymbolAddress(&p_sc1, g_scale1);
    cudaGetSymbolAddress(&p_sh1, g_shift1);
    cudaGetSymbolAddress(&p_sc2, g_scale2);
    cudaGetSymbolAddress(&p_sh2, g_shift2);
    cudaGetSymbolAddress(&p_w1hi, g_w1hi);
    cudaGetSymbolAddress(&p_w1lo, g_w1lo);
    cudaGetSymbolAddress(&p_w2hi, g_w2hi);
    cudaGetSymbolAddress(&p_w2lo, g_w2lo);

    static int smem_set = 0;
    if (!smem_set) {
        cudaFuncSetAttribute(proj_q_mma, cudaFuncAttributeMaxDynamicSharedMemorySize,
                             SMEM_MMA);
        cudaFuncSetAttribute(layer_gemm_mma, cudaFuncAttributeMaxDynamicSharedMemorySize,
                             SMEM_MMA);
        smem_set = 1;
    }

    // kernel indices (memsets excluded): edge_prep = 3 -> profiled by ncu
    cudaMemsetAsync(p_degew, 0, NN * sizeof(float2));
    prep_all_kernel<<<(QD * H + 2 * H * H + 255) / 256, 256>>>(Wq, W1m, W2m); // k0
    proj_l_kernel<<<NL, 512>>>(lf, Wl, bl);                                   // k1
    proj_q_mma<<<GRID_TC, 256, SMEM_MMA>>>(qf, bq, (float*)p_xini);           // k2
    edge_prep_kernel<<<(ESEE + 255) / 256, 256>>>(ei, ecs, ewt, Wem, bem);    // k3 <- profiled
    scan1_kernel<<<SCAN_B, 256>>>();                                          // k4
    scan2_kernel<<<1, 512>>>();                                               // k5
    scan3_kernel<<<SCAN_B, 256>>>();                                          // k6
    placement_kernel<<<(ESEE + 255) / 256, 256>>>();                          // k7

    // ---- layer 1 ----
    gather_kernel<<<(NN + 7) / 8, 256>>>((const float*)p_xini, (float*)p_agg,
                                         nullptr, nullptr, 0);                // k8
    layer_gemm_mma<<<GRID_TC, 256, SMEM_MMA>>>(                               // k9
        (const float*)p_agg, (const __nv_bfloat16*)p_w1hi, (const __nv_bfloat16*)p_w1lo,
        b1m, b1e, W1e, (const float*)p_xini,
        nullptr, nullptr, 0, (float*)p_agg);
    finalize_kernel<<<1, H>>>(g1, beta1, (float*)p_sc1, (float*)p_sh1);       // k10

    // ---- layer 2 ----
    gather_kernel<<<(NN + 7) / 8, 256>>>((const float*)p_agg, (float*)p_x1,
                                         (const float*)p_sc1, (const float*)p_sh1, 1); // k11
    layer_gemm_mma<<<GRID_TC, 256, SMEM_MMA>>>(                               // k12
        (const float*)p_x1, (const __nv_bfloat16*)p_w2hi, (const __nv_bfloat16*)p_w2lo,
        b2m, b2e, W2e, (const float*)p_agg,
        (const float*)p_sc1, (const float*)p_sh1, 1, (float*)p_x1);
    finalize_kernel<<<1, H>>>(g2, beta2, (float*)p_sc2, (float*)p_sh2);       // k13
    predict_kernel<<<EPRED / 8, 256>>>(ei, em, (const float*)p_x1,            // k14
                                       (const float*)p_sc2, (const float*)p_sh2, out);
}

// round 12
// speedup vs baseline: 1.1368x; 1.0221x over previous
#include <cuda_runtime.h>
#include <cuda_bf16.h>
#include <math.h>
#include <stdint.h>

#define NQ    100000
#define NL    32
#define NN    100032
#define QD    384
#define LD    1024
#define H     128
#define EE    1000000
#define ESEE  750000
#define EPRED 250000
#define BN_EPS 1e-5f
#define SCAN_B 391               // ceil(NN/256)

// mma tile config: BM=128 x BN=128, 8 warps (4m x 2n), warp tile 32x64
#define BM 128
#define BK 32
#define GRID_TC 782
#define A_STRIDE_B 80            // (32+8) bf16 * 2
#define B_STRIDE_B 272           // (128+8) bf16 * 2
#define AHI_OFF 0                // 2 bufs * 10240
#define ALO_OFF 20480
#define BHI_OFF 40960            // 2 bufs * 8704
#define BLO_OFF 58368
#define SMEM_MMA 75776

// ---------------- scratch ------------------------------------------------
__device__ __align__(16) float g_xini[NN * H];
__device__ __align__(16) float g_agg [NN * H];
__device__ __align__(16) float g_x1  [NN * H];
__device__ int    g_src[ESEE];
__device__ int    g_dst[ESEE];
__device__ int    g_esrc[ESEE];
__device__ int    g_off[NN + 1];
__device__ int    g_cursor[NN];
__device__ int    g_blk[SCAN_B];
__device__ __align__(8) float2 g_degew[NN];
__device__ __align__(8) float2 g_colstats2[H];
__device__ float g_scale1[H], g_shift1[H];
__device__ float g_scale2[H], g_shift2[H];
__device__ __align__(16) __nv_bfloat16 g_wqhi[QD * H], g_wqlo[QD * H];
__device__ __align__(16) __nv_bfloat16 g_w1hi[H * H],  g_w1lo[H * H];
__device__ __align__(16) __nv_bfloat16 g_w2hi[H * H],  g_w2lo[H * H];

// ---------------- ptx helpers ----------------------------------------------
__device__ __forceinline__ unsigned smem_u32(const void* p) {
    return (unsigned)__cvta_generic_to_shared(p);
}
__device__ __forceinline__ void cp16(unsigned dst, const void* src) {
    asm volatile("cp.async.ca.shared.global [%0], [%1], 16;" :: "r"(dst), "l"(src));
}
#define CP_COMMIT() asm volatile("cp.async.commit_group;")

#define LDSM_X4(r0, r1, r2, r3, addr) \
    asm volatile("ldmatrix.sync.aligned.m8n8.x4.shared.b16 {%0,%1,%2,%3}, [%4];" \
                 : "=r"(r0), "=r"(r1), "=r"(r2), "=r"(r3) : "r"(addr))
#define LDSM_X4T(r0, r1, r2, r3, addr) \
    asm volatile("ldmatrix.sync.aligned.m8n8.x4.trans.shared.b16 {%0,%1,%2,%3}, [%4];" \
                 : "=r"(r0), "=r"(r1), "=r"(r2), "=r"(r3) : "r"(addr))
#define MMA_BF16(c, a, b) \
    asm volatile("mma.sync.aligned.m16n8k16.row.col.f32.bf16.bf16.f32 " \
                 "{%0,%1,%2,%3}, {%4,%5,%6,%7}, {%8,%9}, {%0,%1,%2,%3};" \
                 : "+f"((c)[0]), "+f"((c)[1]), "+f"((c)[2]), "+f"((c)[3]) \
                 : "r"((a)[0]), "r"((a)[1]), "r"((a)[2]), "r"((a)[3]), \
                   "r"((b)[0]), "r"((b)[1]))

__device__ __forceinline__ void split_store(char* smg, int off_hi, int off_lo,
                                            int row, int c4, float4 v) {
    __nv_bfloat16 h0 = __float2bfloat16(v.x);
    __nv_bfloat16 h1 = __float2bfloat16(v.y);
    __nv_bfloat16 h2 = __float2bfloat16(v.z);
    __nv_bfloat16 h3 = __float2bfloat16(v.w);
    __nv_bfloat16 l0 = __float2bfloat16(v.x - __bfloat162float(h0));
    __nv_bfloat16 l1 = __float2bfloat16(v.y - __bfloat162float(h1));
    __nv_bfloat16 l2 = __float2bfloat16(v.z - __bfloat162float(h2));
    __nv_bfloat16 l3 = __float2bfloat16(v.w - __bfloat162float(h3));
    uint2 hp, lp;
    hp.x = ((uint32_t)__bfloat16_as_ushort(h1) << 16) | __bfloat16_as_ushort(h0);
    hp.y = ((uint32_t)__bfloat16_as_ushort(h3) << 16) | __bfloat16_as_ushort(h2);
    lp.x = ((uint32_t)__bfloat16_as_ushort(l1) << 16) | __bfloat16_as_ushort(l0);
    lp.y = ((uint32_t)__bfloat16_as_ushort(l3) << 16) | __bfloat16_as_ushort(l2);
    *(uint2*)(smg + off_hi + row * A_STRIDE_B + c4 * 8) = hp;
    *(uint2*)(smg + off_lo + row * A_STRIDE_B + c4 * 8) = lp;
}

// ---------------- W prep ------------------------------------------------------
__global__ void prep_all_kernel(const float* __restrict__ Wq,
                                const float* __restrict__ W1,
                                const float* __restrict__ W2) {
    int idx = blockIdx.x * blockDim.x + threadIdx.x;
    const int NQW = QD * H, NW = H * H;
    float w;
    __nv_bfloat16 *dhi, *dlo;
    int j;
    if (idx < NQW)                { w = Wq[idx]; dhi = g_wqhi; dlo = g_wqlo; j = idx; }
    else if (idx < NQW + NW)      { j = idx - NQW; w = W1[j]; dhi = g_w1hi; dlo = g_w1lo; }
    else if (idx < NQW + 2 * NW)  { j = idx - NQW - NW; w = W2[j]; dhi = g_w2hi; dlo = g_w2lo; }
    else return;
    __nv_bfloat16 hi = __float2bfloat16(w);
    dhi[j] = hi;
    dlo[j] = __float2bfloat16(w - __bfloat162float(hi));
}

// ---------------- llm projection (split-K, 512 thr) ---------------------------
__global__ void proj_l_kernel(const float* __restrict__ A,
                              const float* __restrict__ W,
                              const float* __restrict__ b) {
    __shared__ float red[4][H];
    int i = blockIdx.x;
    int t = threadIdx.x;
    int j = t & 127;
    int seg = t >> 7;
    float acc = 0.f;
    const float* arow = A + i * LD + seg * 256;
    const float* wcol = W + (seg * 256) * H + j;
    for (int k = 0; k < 256; k++) acc += arow[k] * wcol[k * H];
    red[seg][j] = acc;
    __syncthreads();
    if (seg == 0)
        g_xini[(NQ + i) * H + j] = red[0][j] + red[1][j] + red[2][j] + red[3][j] + b[j];
}

// ---------------- edge prep (+ zero colstats) ---------------------------------
__global__ void edge_prep_kernel(const int* __restrict__ ei,
                                 const int* __restrict__ ecs,
                                 const float* __restrict__ ewt,
                                 const float* __restrict__ Wem,
                                 const float* __restrict__ bem) {
    int i = blockIdx.x * blockDim.x + threadIdx.x;
    if (blockIdx.x == 0 && threadIdx.x < H)
        g_colstats2[threadIdx.x] = make_float2(0.f, 0.f);
    if (i >= ESEE) return;
    int e = ecs[i];
    int s = ei[e];
    int d = ei[EE + e];
    g_src[i] = s;
    g_dst[i] = d;
    float v = ewt[e] * Wem[0] + bem[0];
    v = v > 0.f ? v : 0.01f * v;
    asm volatile("red.global.add.v2.f32 [%0], {%1, %2};"
                 :: "l"(&g_degew[d]), "f"(1.0f), "f"(v) : "memory");
}

// ---------------- counting-sort scan trio --------------------------------------
__global__ void scan1_kernel() {
    __shared__ int red[256];
    int t = threadIdx.x;
    int i = blockIdx.x * 256 + t;
    int c = (i < NN) ? (int)g_degew[i].x : 0;
    red[t] = c;
    __syncthreads();
#pragma unroll
    for (int o = 128; o > 0; o >>= 1) {
        if (t < o) red[t] += red[t + o];
        __syncthreads();
    }
    if (t == 0) g_blk[blockIdx.x] = red[0];
}

__global__ void scan2_kernel() {
    __shared__ int s[512];
    int t = threadIdx.x;
    int c = (t < SCAN_B) ? g_blk[t] : 0;
    s[t] = c;
    __syncthreads();
    for (int o = 1; o < 512; o <<= 1) {
        int v = (t >= o) ? s[t - o] : 0;
        __syncthreads();
        s[t] += v;
        __syncthreads();
    }
    if (t < SCAN_B) g_blk[t] = s[t] - c;
}

__global__ void scan3_kernel() {
    __shared__ int s[256];
    int t = threadIdx.x;
    int i = blockIdx.x * 256 + t;
    int c = (i < NN) ? (int)g_degew[i].x : 0;
    s[t] = c;
    __syncthreads();
    for (int o = 1; o < 256; o <<= 1) {
        int v = (t >= o) ? s[t - o] : 0;
        __syncthreads();
        s[t] += v;
        __syncthreads();
    }
    if (i < NN) {
        int off = g_blk[blockIdx.x] + s[t] - c;
        g_off[i] = off;
        g_cursor[i] = off;
    }
    if (i == 0) g_off[NN] = ESEE;
}

__global__ void placement_kernel() {
    int i = blockIdx.x * blockDim.x + threadIdx.x;
    if (i >= ESEE) return;
    int d = g_dst[i];
    int pos = atomicAdd(&g_cursor[d], 1);
    g_esrc[pos] = g_src[i];
}

// ---------------- gather aggregation (4-wide unroll) ---------------------------
__device__ __forceinline__ float4 bn_lrelu4(float4 v, float4 s4, float4 h4) {
    v.x = fmaf(v.x, s4.x, h4.x); v.x = v.x > 0.f ? v.x : 0.01f * v.x;
    v.y = fmaf(v.y, s4.y, h4.y); v.y = v.y > 0.f ? v.y : 0.01f * v.y;
    v.z = fmaf(v.z, s4.z, h4.z); v.z = v.z > 0.f ? v.z : 0.01f * v.z;
    v.w = fmaf(v.w, s4.w, h4.w); v.w = v.w > 0.f ? v.w : 0.01f * v.w;
    return v;
}
__global__ void __launch_bounds__(256) gather_kernel(const float* __restrict__ x,
                                                     float* __restrict__ outbuf,
                                                     const float* __restrict__ sc,
                                                     const float* __restrict__ sh,
                                                     int bn) {
    int wid = threadIdx.x >> 5;
    int lane = threadIdx.x & 31;
    int node = blockIdx.x * 8 + wid;
    if (node >= NN) return;
    int o0 = g_off[node];
    int o1 = g_off[node + 1];
    float4 s4 = make_float4(1.f, 1.f, 1.f, 1.f);
    float4 h4 = make_float4(0.f, 0.f, 0.f, 0.f);
    if (bn) {
        s4 = *(const float4*)&sc[lane * 4];
        h4 = *(const float4*)&sh[lane * 4];
    }
    float4 a0 = make_float4(0.f, 0.f, 0.f, 0.f);
    float4 a1 = make_float4(0.f, 0.f, 0.f, 0.f);
    float4 a2 = make_float4(0.f, 0.f, 0.f, 0.f);
    float4 a3 = make_float4(0.f, 0.f, 0.f, 0.f);
    int e = o0;
    for (; e + 4 <= o1; e += 4) {
        int s0 = g_esrc[e], s1 = g_esrc[e + 1], s2 = g_esrc[e + 2], s3 = g_esrc[e + 3];
        float4 v0 = *(const float4*)&x[(long)s0 * H + lane * 4];
        float4 v1 = *(const float4*)&x[(long)s1 * H + lane * 4];
        float4 v2 = *(const float4*)&x[(long)s2 * H + lane * 4];
        float4 v3 = *(const float4*)&x[(long)s3 * H + lane * 4];
        if (bn) {
            v0 = bn_lrelu4(v0, s4, h4); v1 = bn_lrelu4(v1, s4, h4);
            v2 = bn_lrelu4(v2, s4, h4); v3 = bn_lrelu4(v3, s4, h4);
        }
        a0.x += v0.x; a0.y += v0.y; a0.z += v0.z; a0.w += v0.w;
        a1.x += v1.x; a1.y += v1.y; a1.z += v1.z; a1.w += v1.w;
        a2.x += v2.x; a2.y += v2.y; a2.z += v2.z; a2.w += v2.w;
        a3.x += v3.x; a3.y += v3.y; a3.z += v3.z; a3.w += v3.w;
    }
    for (; e < o1; e++) {
        int s0 = g_esrc[e];
        float4 v0 = *(const float4*)&x[(long)s0 * H + lane * 4];
        if (bn) v0 = bn_lrelu4(v0, s4, h4);
        a0.x += v0.x; a0.y += v0.y; a0.z += v0.z; a0.w += v0.w;
    }
    a0.x += a1.x + a2.x + a3.x;
    a0.y += a1.y + a2.y + a3.y;
    a0.z += a1.z + a2.z + a3.z;
    a0.w += a1.w + a2.w + a3.w;
    *(float4*)&outbuf[(long)node * H + lane * 4] = a0;
}

// ---------------- proj_q via mma.sync bf16x3 (BM=128) --------------------------
__global__ void __launch_bounds__(256, 1) proj_q_mma(const float* __restrict__ A,
                                                     const float* __restrict__ bias,
                                                     float* __restrict__ out) {
    extern __shared__ char sm[];
    uint32_t sb = smem_u32(sm);
    char* smg = sm;
    int tid = threadIdx.x;
    int wid = tid >> 5;
    int lane = tid & 31;
    int wm = wid & 3;
    int wn = wid >> 2;
    int row0 = blockIdx.x * BM;

    float acc[2][8][4];
#pragma unroll
    for (int mt = 0; mt < 2; mt++)
#pragma unroll
        for (int nt = 0; nt < 8; nt++)
#pragma unroll
            for (int j = 0; j < 4; j++) acc[mt][nt][j] = 0.f;

    int af_row[4], af_c4[4];
#pragma unroll
    for (int i = 0; i < 4; i++) {
        int f = tid + i * 256;
        af_row[i] = f >> 3;
        af_c4[i] = f & 7;
    }

    float4 av[4];
#pragma unroll
    for (int i = 0; i < 4; i++) {
        int grow = row0 + af_row[i];
        if (grow >= NQ) grow = 0;
        av[i] = *(const float4*)&A[(long)grow * QD + af_c4[i] * 4];
    }
#pragma unroll
    for (int i = 0; i < 2; i++) {
        int seg = tid + i * 256;
        int br = seg >> 4, c16 = seg & 15;
        cp16(sb + BHI_OFF + br * B_STRIDE_B + c16 * 16, g_wqhi + br * H + c16 * 8);
        cp16(sb + BLO_OFF + br * B_STRIDE_B + c16 * 16, g_wqlo + br * H + c16 * 8);
    }
    CP_COMMIT();
#pragma unroll
    for (int i = 0; i < 4; i++)
        split_store(smg, AHI_OFF, ALO_OFF, af_row[i], af_c4[i], av[i]);

    const int TST = QD / BK;  // 12
    for (int t = 0; t < TST; t++) {
        int buf = t & 1;
        int have_next = (t + 1 < TST);
        if (have_next) {
            int k0 = (t + 1) * BK;
            int nb = buf ^ 1;
#pragma unroll
            for (int i = 0; i < 4; i++) {
                int grow = row0 + af_row[i];
                if (grow >= NQ) grow = 0;
                av[i] = *(const float4*)&A[(long)grow * QD + k0 + af_c4[i] * 4];
            }
#pragma unroll
            for (int i = 0; i < 2; i++) {
                int seg = tid + i * 256;
                int br = seg >> 4, c16 = seg & 15;
                cp16(sb + BHI_OFF + nb * 8704 + br * B_STRIDE_B + c16 * 16,
                     g_wqhi + (k0 + br) * H + c16 * 8);
                cp16(sb + BLO_OFF + nb * 8704 + br * B_STRIDE_B + c16 * 16,
                     g_wqlo + (k0 + br) * H + c16 * 8);
            }
            CP_COMMIT();
            asm volatile("cp.async.wait_group 1;");
        } else {
            asm volatile("cp.async.wait_group 0;");
        }
        __syncthreads();

        uint32_t abase_hi = sb + AHI_OFF + buf * 10240;
        uint32_t abase_lo = sb + ALO_OFF + buf * 10240;
        uint32_t bbase_hi = sb + BHI_OFF + buf * 8704;
        uint32_t bbase_lo = sb + BLO_OFF + buf * 8704;
#pragma unroll
        for (int ks = 0; ks < 2; ks++) {
            uint32_t ah[2][4], al[2][4], bh[8][2], bl[8][2];
#pragma unroll
            for (int mt = 0; mt < 2; mt++) {
                uint32_t roff = (uint32_t)((wm * 32 + mt * 16 + (lane & 15)) * A_STRIDE_B
                                           + ks * 32 + (lane >> 4) * 16);
                LDSM_X4(ah[mt][0], ah[mt][1], ah[mt][2], ah[mt][3], abase_hi + roff);
                LDSM_X4(al[mt][0], al[mt][1], al[mt][2], al[mt][3], abase_lo + roff);
            }
#pragma unroll
            for (int np = 0; np < 4; np++) {
                uint32_t boff = (uint32_t)((ks * 16 + (lane & 15)) * B_STRIDE_B
                                           + (wn * 64 + np * 16 + (lane >> 4) * 8) * 2);
                LDSM_X4T(bh[np * 2][0], bh[np * 2][1], bh[np * 2 + 1][0], bh[np * 2 + 1][1],
                         bbase_hi + boff);
                LDSM_X4T(bl[np * 2][0], bl[np * 2][1], bl[np * 2 + 1][0], bl[np * 2 + 1][1],
                         bbase_lo + boff);
            }
#pragma unroll
            for (int mt = 0; mt < 2; mt++)
#pragma unroll
                for (int nt = 0; nt < 8; nt++) {
                    MMA_BF16(acc[mt][nt], ah[mt], bh[nt]);
                    MMA_BF16(acc[mt][nt], al[mt], bh[nt]);
                    MMA_BF16(acc[mt][nt], ah[mt], bl[nt]);
                }
        }
        __syncthreads();

        if (have_next) {
            int nb = buf ^ 1;
#pragma unroll
            for (int i = 0; i < 4; i++)
                split_store(smg, AHI_OFF + nb * 10240, ALO_OFF + nb * 10240,
                            af_row[i], af_c4[i], av[i]);
        }
    }

#pragma unroll
    for (int mt = 0; mt < 2; mt++) {
        int m0r = row0 + wm * 32 + mt * 16 + (lane >> 2);
        int m1r = m0r + 8;
#pragma unroll
        for (int nt = 0; nt < 8; nt++) {
            int n = wn * 64 + nt * 8 + (lane & 3) * 2;
            float2 bv = *(const float2*)&bias[n];
            if (m0r < NQ) {
                float2 o = make_float2(acc[mt][nt][0] + bv.x, acc[mt][nt][1] + bv.y);
                *(float2*)&out[(long)m0r * H + n] = o;
            }
            if (m1r < NQ) {
                float2 o = make_float2(acc[mt][nt][2] + bv.x, acc[mt][nt][3] + bv.y);
                *(float2*)&out[(long)m1r * H + n] = o;
            }
        }
    }
}

// ---------------- layer GEMM via mma.sync bf16x3 (BM=128) ----------------------
__global__ void __launch_bounds__(256, 1) layer_gemm_mma(
        const float* __restrict__ Ain,
        const __nv_bfloat16* __restrict__ Whi,
        const __nv_bfloat16* __restrict__ Wlo,
        const float* __restrict__ bm, const float* __restrict__ be,
        const float* __restrict__ We,
        const float* __restrict__ xprev,
        const float* __restrict__ psc, const float* __restrict__ psh,
        int prev_bn,
        float* __restrict__ out) {
    extern __shared__ char sm[];
    uint32_t sb = smem_u32(sm);
    char* smg = sm;
    int tid = threadIdx.x;
    int wid = tid >> 5;
    int lane = tid & 31;
    int wm = wid & 3;
    int wn = wid >> 2;
    int row0 = blockIdx.x * BM;

    float acc[2][8][4];
#pragma unroll
    for (int mt = 0; mt < 2; mt++)
#pragma unroll
        for (int nt = 0; nt < 8; nt++)
#pragma unroll
            for (int j = 0; j < 4; j++) acc[mt][nt][j] = 0.f;

    int af_row[4], af_c4[4];
#pragma unroll
    for (int i = 0; i < 4; i++) {
        int f = tid + i * 256;
        af_row[i] = f >> 3;
        af_c4[i] = f & 7;
    }

    float4 av[4];
#pragma unroll
    for (int i = 0; i < 4; i++) {
        int grow = row0 + af_row[i];
        if (grow >= NN) grow = 0;
        av[i] = *(const float4*)&Ain[(long)grow * H + af_c4[i] * 4];
    }
#pragma unroll
    for (int i = 0; i < 2; i++) {
        int seg = tid + i * 256;
        int br = seg >> 4, c16 = seg & 15;
        cp16(sb + BHI_OFF + br * B_STRIDE_B + c16 * 16, Whi + br * H + c16 * 8);
        cp16(sb + BLO_OFF + br * B_STRIDE_B + c16 * 16, Wlo + br * H + c16 * 8);
    }
    CP_COMMIT();
#pragma unroll
    for (int i = 0; i < 4; i++)
        split_store(smg, AHI_OFF, ALO_OFF, af_row[i], af_c4[i], av[i]);

    const int TST = H / BK;  // 4
    for (int t = 0; t < TST; t++) {
        int buf = t & 1;
        int have_next = (t + 1 < TST);
        if (have_next) {
            int k0 = (t + 1) * BK;
            int nb = buf ^ 1;
#pragma unroll
            for (int i = 0; i < 4; i++) {
                int grow = row0 + af_row[i];
                if (grow >= NN) grow = 0;
                av[i] = *(const float4*)&Ain[(long)grow * H + k0 + af_c4[i] * 4];
            }
#pragma unroll
            for (int i = 0; i < 2; i++) {
                int seg = tid + i * 256;
                int br = seg >> 4, c16 = seg & 15;
                cp16(sb + BHI_OFF + nb * 8704 + br * B_STRIDE_B + c16 * 16,
                     Whi + (k0 + br) * H + c16 * 8);
                cp16(sb + BLO_OFF + nb * 8704 + br * B_STRIDE_B + c16 * 16,
                     Wlo + (k0 + br) * H + c16 * 8);
            }
            CP_COMMIT();
            asm volatile("cp.async.wait_group 1;");
        } else {
            asm volatile("cp.async.wait_group 0;");
        }
        __syncthreads();

        uint32_t abase_hi = sb + AHI_OFF + buf * 10240;
        uint32_t abase_lo = sb + ALO_OFF + buf * 10240;
        uint32_t bbase_hi = sb + BHI_OFF + buf * 8704;
        uint32_t bbase_lo = sb + BLO_OFF + buf * 8704;
#pragma unroll
        for (int ks = 0; ks < 2; ks++) {
            uint32_t ah[2][4], al[2][4], bh[8][2], bl[8][2];
#pragma unroll
            for (int mt = 0; mt < 2; mt++) {
                uint32_t roff = (uint32_t)((wm * 32 + mt * 16 + (lane & 15)) * A_STRIDE_B
                                           + ks * 32 + (lane >> 4) * 16);
                LDSM_X4(ah[mt][0], ah[mt][1], ah[mt][2], ah[mt][3], abase_hi + roff);
                LDSM_X4(al[mt][0], al[mt][1], al[mt][2], al[mt][3], abase_lo + roff);
            }
#pragma unroll
            for (int np = 0; np < 4; np++) {
                uint32_t boff = (uint32_t)((ks * 16 + (lane & 15)) * B_STRIDE_B
                                           + (wn * 64 + np * 16 + (lane >> 4) * 8) * 2);
                LDSM_X4T(bh[np * 2][0], bh[np * 2][1], bh[np * 2 + 1][0], bh[np * 2 + 1][1],
                         bbase_hi + boff);
                LDSM_X4T(bl[np * 2][0], bl[np * 2][1], bl[np * 2 + 1][0], bl[np * 2 + 1][1],
                         bbase_lo + boff);
            }
#pragma unroll
            for (int mt = 0; mt < 2; mt++)
#pragma unroll
                for (int nt = 0; nt < 8; nt++) {
                    MMA_BF16(acc[mt][nt], ah[mt], bh[nt]);
                    MMA_BF16(acc[mt][nt], al[mt], bh[nt]);
                    MMA_BF16(acc[mt][nt], ah[mt], bl[nt]);
                }
        }
        __syncthreads();

        if (have_next) {
            int nb = buf ^ 1;
#pragma unroll
            for (int i = 0; i < 4; i++)
                split_store(smg, AHI_OFF + nb * 10240, ALO_OFF + nb * 10240,
                            af_row[i], af_c4[i], av[i]);
        }
    }

    // ---- fused epilogue ----
    int lq = lane & 3;
    int lr = lane >> 2;
    float2 ds[2][2];
    bool rv[2][2];
#pragma unroll
    for (int mt = 0; mt < 2; mt++)
#pragma unroll
        for (int hf = 0; hf < 2; hf++) {
            int row = row0 + wm * 32 + mt * 16 + hf * 8 + lr;
            rv[mt][hf] = (row < NN);
            ds[mt][hf] = rv[mt][hf] ? g_degew[row] : make_float2(0.f, 0.f);
        }

#pragma unroll
    for (int nt = 0; nt < 8; nt++) {
        int n = wn * 64 + nt * 8 + lq * 2;
        float2 cb2 = make_float2(bm[n] + be[n], bm[n + 1] + be[n + 1]);
        float2 we2 = *(const float2*)&We[n];
        float2 sc2 = make_float2(0.f, 0.f), sh2 = make_float2(0.f, 0.f);
        if (prev_bn) {
            sc2 = make_float2(psc[n], psc[n + 1]);
            sh2 = make_float2(psh[n], psh[n + 1]);
        }
        float cs0 = 0.f, cs1 = 0.f, cq0 = 0.f, cq1 = 0.f;
#pragma unroll
        for (int mt = 0; mt < 2; mt++)
#pragma unroll
            for (int hf = 0; hf < 2; hf++) {
                if (rv[mt][hf]) {
                    int row = row0 + wm * 32 + mt * 16 + hf * 8 + lr;
                    float2 xp = *(const float2*)&xprev[(long)row * H + n];
                    if (prev_bn) {
                        float u0 = fmaf(xp.x, sc2.x, sh2.x);
                        float u1 = fmaf(xp.y, sc2.y, sh2.y);
                        xp.x = u0 > 0.f ? u0 : 0.01f * u0;
                        xp.y = u1 > 0.f ? u1 : 0.01f * u1;
                    }
                    float2 dd = ds[mt][hf];
                    float v0 = acc[mt][nt][hf * 2 + 0] + dd.x * cb2.x + dd.y * we2.x + xp.x;
                    float v1 = acc[mt][nt][hf * 2 + 1] + dd.x * cb2.y + dd.y * we2.y + xp.y;
                    *(float2*)&out[(long)row * H + n] = make_float2(v0, v1);
                    cs0 += v0; cq0 += v0 * v0;
                    cs1 += v1; cq1 += v1 * v1;
                }
            }
#pragma unroll
        for (int off = 4; off <= 16; off <<= 1) {
            cs0 += __shfl_xor_sync(0xffffffffu, cs0, off);
            cq0 += __shfl_xor_sync(0xffffffffu, cq0, off);
            cs1 += __shfl_xor_sync(0xffffffffu, cs1, off);
            cq1 += __shfl_xor_sync(0xffffffffu, cq1, off);
        }
        if (lr == 0) {
            asm volatile("red.global.add.v2.f32 [%0], {%1, %2};"
                         :: "l"(&g_colstats2[n]), "f"(cs0), "f"(cq0) : "memory");
            asm volatile("red.global.add.v2.f32 [%0], {%1, %2};"
                         :: "l"(&g_colstats2[n + 1]), "f"(cs1), "f"(cq1) : "memory");
        }
    }
}

// ---------------- BN stat finalize (+ self-zero) -------------------------------
__global__ void finalize_kernel(const float* __restrict__ g,
                                const float* __restrict__ beta,
                                float* __restrict__ sc_out,
                                float* __restrict__ sh_out) {
    int j = threadIdx.x;
    float2 s = g_colstats2[j];
    float mu = s.x * (1.f / (float)NN);
    float var = s.y * (1.f / (float)NN) - mu * mu;
    float rstd = rsqrtf(var + BN_EPS);
    float sc = g[j] * rstd;
    sc_out[j] = sc;
    sh_out[j] = beta[j] - mu * sc;
    g_colstats2[j] = make_float2(0.f, 0.f);
}

// ---------------- edge prediction (BN2 inline) ----------------------------------
__global__ void predict_kernel(const int* __restrict__ ei,
                               const int* __restrict__ em,
                               const float* __restrict__ x2raw,
                               const float* __restrict__ sc,
                               const float* __restrict__ sh,
                               float* __restrict__ out) {
    int warp = (blockIdx.x * blockDim.x + threadIdx.x) >> 5;
    int lane = threadIdx.x & 31;
    if (warp >= EPRED) return;
    float4 s2 = *(const float4*)&sc[lane * 4];
    float4 h2 = *(const float4*)&sh[lane * 4];
    int e = em[warp];
    int s = ei[e];
    int t = ei[EE + e];
    float4 a = *(const float4*)&g_xini[s * H + lane * 4];
    float4 b = *(const float4*)&x2raw[t * H + lane * 4];
    b.x = fmaf(b.x, s2.x, h2.x);
    b.y = fmaf(b.y, s2.y, h2.y);
    b.z = fmaf(b.z, s2.z, h2.z);
    b.w = fmaf(b.w, s2.w, h2.w);
    float d = a.x * b.x + a.y * b.y + a.z * b.z + a.w * b.w;
#pragma unroll
    for (int o = 16; o; o >>= 1) d += __shfl_xor_sync(0xffffffffu, d, o);
    if (lane == 0) out[warp] = 1.f / (1.f + expf(-d * (1.f / 128.f)));
}

// ---------------- launch -----------------------------------------------------
extern "C" void kernel_launch(void* const* d_in, const int* in_sizes, int n_in,
                              void* d_out, int out_size) {
    const float* qf  = (const float*)d_in[0];
    const float* lf  = (const float*)d_in[1];
    const int*   ei  = (const int*)d_in[2];
    const int*   em  = (const int*)d_in[3];
    const int*   ecs = (const int*)d_in[4];
    const float* ewt = (const float*)d_in[5];
    const float* Wq  = (const float*)d_in[6];
    const float* bq  = (const float*)d_in[7];
    const float* Wl  = (const float*)d_in[8];
    const float* bl  = (const float*)d_in[9];
    const float* Wem = (const float*)d_in[10];
    const float* bem = (const float*)d_in[11];
    const float* W1m = (const float*)d_in[12];
    const float* b1m = (const float*)d_in[13];
    const float* W1e = (const float*)d_in[14];
    const float* b1e = (const float*)d_in[15];
    const float* W2m = (const float*)d_in[16];
    const float* b2m = (const float*)d_in[17];
    const float* W2e = (const float*)d_in[18];
    const float* b2e = (const float*)d_in[19];
    const float* g1    = (const float*)d_in[20];
    const float* beta1 = (const float*)d_in[21];
    const float* g2    = (const float*)d_in[22];
    const float* beta2 = (const float*)d_in[23];
    float* out = (float*)d_out;

    void *p_agg, *p_xini, *p_x1, *p_degew;
    void *p_sc1, *p_sh1, *p_sc2, *p_sh2;
    void *p_w1hi, *p_w1lo, *p_w2hi, *p_w2lo;
    cudaGetSymbolAddress(&p_agg, g_agg);
    cudaGetSymbolAddress(&p_xini, g_xini);
    cudaGetSymbolAddress(&p_x1, g_x1);
    cudaGetSymbolAddress(&p_degew, g_degew);
    cudaGetSymbolAddress(&p_sc1, g_scale1);
    cudaGetSymbolAddress(&p_sh1, g_shift1);
    cudaGetSymbolAddress(&p_sc2, g_scale2);
    cudaGetSymbolAddress(&p_sh2, g_shift2);
    cudaGetSymbolAddress(&p_w1hi, g_w1hi);
    cudaGetSymbolAddress(&p_w1lo, g_w1lo);
    cudaGetSymbolAddress(&p_w2hi, g_w2hi);
    cudaGetSymbolAddress(&p_w2lo, g_w2lo);

    static int init_done = 0;
    static cudaStream_t s_edge;
    static cudaEvent_t ev_fork, ev_edge;
    if (!init_done) {
        cudaFuncSetAttribute(proj_q_mma, cudaFuncAttributeMaxDynamicSharedMemorySize,
                             SMEM_MMA);
        cudaFuncSetAttribute(layer_gemm_mma, cudaFuncAttributeMaxDynamicSharedMemorySize,
                             SMEM_MMA);
        cudaStreamCreateWithFlags(&s_edge, cudaStreamNonBlocking);
        cudaEventCreateWithFlags(&ev_fork, cudaEventDisableTiming);
        cudaEventCreateWithFlags(&ev_edge, cudaEventDisableTiming);
        init_done = 1;
    }

    // ---- main stream: degew zero feeds BOTH chains, so do it before fork ----
    cudaMemsetAsync(p_degew, 0, NN * sizeof(float2));

    // ---- fork edge-sort chain onto side stream ----
    cudaEventRecord(ev_fork, 0);
    cudaStreamWaitEvent(s_edge, ev_fork, 0);
    edge_prep_kernel<<<(ESEE + 255) / 256, 256, 0, s_edge>>>(ei, ecs, ewt, Wem, bem);
    scan1_kernel<<<SCAN_B, 256, 0, s_edge>>>();
    scan2_kernel<<<1, 512, 0, s_edge>>>();
    scan3_kernel<<<SCAN_B, 256, 0, s_edge>>>();
    placement_kernel<<<(ESEE + 255) / 256, 256, 0, s_edge>>>();
    cudaEventRecord(ev_edge, s_edge);

    // ---- main stream: projection chain (runs concurrently) ----
    prep_all_kernel<<<(QD * H + 2 * H * H + 255) / 256, 256>>>(Wq, W1m, W2m);
    proj_l_kernel<<<NL, 512>>>(lf, Wl, bl);
    proj_q_mma<<<GRID_TC, 256, SMEM_MMA>>>(qf, bq, (float*)p_xini);

    // ---- join: gather needs both xini (main) and esrc/off/degew (edge) ----
    cudaStreamWaitEvent(0, ev_edge, 0);

    // ---- layer 1 ----
    gather_kernel<<<(NN + 7) / 8, 256>>>((const float*)p_xini, (float*)p_agg,
                                         nullptr, nullptr, 0);
    layer_gemm_mma<<<GRID_TC, 256, SMEM_MMA>>>(
        (const float*)p_agg, (const __nv_bfloat16*)p_w1hi, (const __nv_bfloat16*)p_w1lo,
        b1m, b1e, W1e, (const float*)p_xini,
        nullptr, nullptr, 0, (float*)p_agg);
    finalize_kernel<<<1, H>>>(g1, beta1, (float*)p_sc1, (float*)p_sh1);

    // ---- layer 2 ----
    gather_kernel<<<(NN + 7) / 8, 256>>>((const float*)p_agg, (float*)p_x1,
                                         (const float*)p_sc1, (const float*)p_sh1, 1);
    layer_gemm_mma<<<GRID_TC, 256, SMEM_MMA>>>(
        (const float*)p_x1, (const __nv_bfloat16*)p_w2hi, (const __nv_bfloat16*)p_w2lo,
        b2m, b2e, W2e, (const float*)p_agg,
        (const float*)p_sc1, (const float*)p_sh1, 1, (float*)p_x1);
    finalize_kernel<<<1, H>>>(g2, beta2, (float*)p_sc2, (float*)p_sh2);
    predict_kernel<<<EPRED / 8, 256>>>(ei, em, (const float*)p_x1,
                                       (const float*)p_sc2, (const float*)p_sh2, out);
}

// round 13
// speedup vs baseline: 1.3764x; 1.2108x over previous
#include <cuda_runtime.h>
#include <cuda_fp16.h>
#include <math.h>
#include <stdint.h>

#define NQ    100000
#define NL    32
#define NN    100032
#define QD    384
#define LD    1024
#define H     128
#define EE    1000000
#define ESEE  750000
#define EPRED 250000
#define BN_EPS 1e-5f
#define SCAN_B 391               // ceil(NN/256)

// mma tile config: BM=128 x BN=128, 8 warps (4m x 2n), warp tile 32x64
// fp16 asymmetric split: A = fp16 hi only; B = fp16 hi+lo. 2 MMAs per (mt,nt).
#define BM 128
#define BK 32
#define GRID_TC 782
#define A_STRIDE_B 80            // (32+8) fp16 * 2
#define B_STRIDE_B 272           // (128+8) fp16 * 2
#define ABUF 10240               // 128 * 80
#define BBUF 8704                // 32 * 272
#define AH_OFF 0                 // 2 bufs
#define BH_OFF 20480             // 2 bufs
#define BL_OFF 37888             // 2 bufs
#define SMEM_MMA 55296

// ---------------- scratch ------------------------------------------------
__device__ __align__(16) float g_xini[NN * H];
__device__ __align__(16) float g_agg [NN * H];      // t1 (fp32 layer-1 out)
__device__ __align__(16) float g_x1  [NN * H];      // t2 (fp32 layer-2 out)
__device__ __align__(16) __half g_aggh[NN * H];     // fp16 gather output (GEMM A)
__device__ int    g_src[ESEE];
__device__ int    g_dst[ESEE];
__device__ int    g_esrc[ESEE];
__device__ int    g_off[NN + 1];
__device__ int    g_cursor[NN];
__device__ int    g_blk[SCAN_B];
__device__ __align__(8) float2 g_degew[NN];
__device__ __align__(8) float2 g_colstats2[H];
__device__ float g_scale1[H], g_shift1[H];
__device__ float g_scale2[H], g_shift2[H];
__device__ __align__(16) __half g_wqhi[QD * H], g_wqlo[QD * H];
__device__ __align__(16) __half g_w1hi[H * H],  g_w1lo[H * H];
__device__ __align__(16) __half g_w2hi[H * H],  g_w2lo[H * H];

// ---------------- ptx helpers ----------------------------------------------
__device__ __forceinline__ unsigned smem_u32(const void* p) {
    return (unsigned)__cvta_generic_to_shared(p);
}
__device__ __forceinline__ void cp16(unsigned dst, const void* src) {
    asm volatile("cp.async.ca.shared.global [%0], [%1], 16;" :: "r"(dst), "l"(src));
}
#define CP_COMMIT() asm volatile("cp.async.commit_group;")

#define LDSM_X4(r0, r1, r2, r3, addr) \
    asm volatile("ldmatrix.sync.aligned.m8n8.x4.shared.b16 {%0,%1,%2,%3}, [%4];" \
                 : "=r"(r0), "=r"(r1), "=r"(r2), "=r"(r3) : "r"(addr))
#define LDSM_X4T(r0, r1, r2, r3, addr) \
    asm volatile("ldmatrix.sync.aligned.m8n8.x4.trans.shared.b16 {%0,%1,%2,%3}, [%4];" \
                 : "=r"(r0), "=r"(r1), "=r"(r2), "=r"(r3) : "r"(addr))
#define MMA_F16(c, a, b) \
    asm volatile("mma.sync.aligned.m16n8k16.row.col.f32.f16.f16.f32 " \
                 "{%0,%1,%2,%3}, {%4,%5,%6,%7}, {%8,%9}, {%0,%1,%2,%3};" \
                 : "+f"((c)[0]), "+f"((c)[1]), "+f"((c)[2]), "+f"((c)[3]) \
                 : "r"((a)[0]), "r"((a)[1]), "r"((a)[2]), "r"((a)[3]), \
                   "r"((b)[0]), "r"((b)[1]))

__device__ __forceinline__ uint32_t pack_h2(float x, float y) {
    __half hx = __float2half_rn(x);
    __half hy = __float2half_rn(y);
    return ((uint32_t)__half_as_ushort(hy) << 16) | __half_as_ushort(hx);
}
// convert fp32x4 -> fp16x4 and store 8B into A tile
__device__ __forceinline__ void a_store_h(char* smg, int off, int row, int c4, float4 v) {
    uint2 hp;
    hp.x = pack_h2(v.x, v.y);
    hp.y = pack_h2(v.z, v.w);
    *(uint2*)(smg + off + row * A_STRIDE_B + c4 * 8) = hp;
}

// ---------------- W prep: fp32 -> fp16 hi/lo pairs -----------------------------
__global__ void prep_all_kernel(const float* __restrict__ Wq,
                                const float* __restrict__ W1,
                                const float* __restrict__ W2) {
    int idx = blockIdx.x * blockDim.x + threadIdx.x;
    const int NQW = QD * H, NW = H * H;
    float w;
    __half *dhi, *dlo;
    int j;
    if (idx < NQW)                { w = Wq[idx]; dhi = g_wqhi; dlo = g_wqlo; j = idx; }
    else if (idx < NQW + NW)      { j = idx - NQW; w = W1[j]; dhi = g_w1hi; dlo = g_w1lo; }
    else if (idx < NQW + 2 * NW)  { j = idx - NQW - NW; w = W2[j]; dhi = g_w2hi; dlo = g_w2lo; }
    else return;
    __half hi = __float2half_rn(w);
    dhi[j] = hi;
    dlo[j] = __float2half_rn(w - __half2float(hi));
}

// ---------------- llm projection (split-K, 512 thr) ---------------------------
__global__ void proj_l_kernel(const float* __restrict__ A,
                              const float* __restrict__ W,
                              const float* __restrict__ b) {
    __shared__ float red[4][H];
    int i = blockIdx.x;
    int t = threadIdx.x;
    int j = t & 127;
    int seg = t >> 7;
    float acc = 0.f;
    const float* arow = A + i * LD + seg * 256;
    const float* wcol = W + (seg * 256) * H + j;
    for (int k = 0; k < 256; k++) acc += arow[k] * wcol[k * H];
    red[seg][j] = acc;
    __syncthreads();
    if (seg == 0)
        g_xini[(NQ + i) * H + j] = red[0][j] + red[1][j] + red[2][j] + red[3][j] + b[j];
}

// ---------------- edge prep (+ zero colstats) ---------------------------------
__global__ void edge_prep_kernel(const int* __restrict__ ei,
                                 const int* __restrict__ ecs,
                                 const float* __restrict__ ewt,
                                 const float* __restrict__ Wem,
                                 const float* __restrict__ bem) {
    int i = blockIdx.x * blockDim.x + threadIdx.x;
    if (blockIdx.x == 0 && threadIdx.x < H)
        g_colstats2[threadIdx.x] = make_float2(0.f, 0.f);
    if (i >= ESEE) return;
    int e = ecs[i];
    int s = ei[e];
    int d = ei[EE + e];
    g_src[i] = s;
    g_dst[i] = d;
    float v = ewt[e] * Wem[0] + bem[0];
    v = v > 0.f ? v : 0.01f * v;
    asm volatile("red.global.add.v2.f32 [%0], {%1, %2};"
                 :: "l"(&g_degew[d]), "f"(1.0f), "f"(v) : "memory");
}

// ---------------- counting-sort scan trio --------------------------------------
__global__ void scan1_kernel() {
    __shared__ int red[256];
    int t = threadIdx.x;
    int i = blockIdx.x * 256 + t;
    int c = (i < NN) ? (int)g_degew[i].x : 0;
    red[t] = c;
    __syncthreads();
#pragma unroll
    for (int o = 128; o > 0; o >>= 1) {
        if (t < o) red[t] += red[t + o];
        __syncthreads();
    }
    if (t == 0) g_blk[blockIdx.x] = red[0];
}

__global__ void scan2_kernel() {
    __shared__ int s[512];
    int t = threadIdx.x;
    int c = (t < SCAN_B) ? g_blk[t] : 0;
    s[t] = c;
    __syncthreads();
    for (int o = 1; o < 512; o <<= 1) {
        int v = (t >= o) ? s[t - o] : 0;
        __syncthreads();
        s[t] += v;
        __syncthreads();
    }
    if (t < SCAN_B) g_blk[t] = s[t] - c;
}

__global__ void scan3_kernel() {
    __shared__ int s[256];
    int t = threadIdx.x;
    int i = blockIdx.x * 256 + t;
    int c = (i < NN) ? (int)g_degew[i].x : 0;
    s[t] = c;
    __syncthreads();
    for (int o = 1; o < 256; o <<= 1) {
        int v = (t >= o) ? s[t - o] : 0;
        __syncthreads();
        s[t] += v;
        __syncthreads();
    }
    if (i < NN) {
        int off = g_blk[blockIdx.x] + s[t] - c;
        g_off[i] = off;
        g_cursor[i] = off;
    }
    if (i == 0) g_off[NN] = ESEE;
}

__global__ void placement_kernel() {
    int i = blockIdx.x * blockDim.x + threadIdx.x;
    if (i >= ESEE) return;
    int d = g_dst[i];
    int pos = atomicAdd(&g_cursor[d], 1);
    g_esrc[pos] = g_src[i];
}

// ---------------- gather aggregation -> fp16 output ----------------------------
__device__ __forceinline__ float4 bn_lrelu4(float4 v, float4 s4, float4 h4) {
    v.x = fmaf(v.x, s4.x, h4.x); v.x = v.x > 0.f ? v.x : 0.01f * v.x;
    v.y = fmaf(v.y, s4.y, h4.y); v.y = v.y > 0.f ? v.y : 0.01f * v.y;
    v.z = fmaf(v.z, s4.z, h4.z); v.z = v.z > 0.f ? v.z : 0.01f * v.z;
    v.w = fmaf(v.w, s4.w, h4.w); v.w = v.w > 0.f ? v.w : 0.01f * v.w;
    return v;
}
__global__ void __launch_bounds__(256) gather_kernel(const float* __restrict__ x,
                                                     __half* __restrict__ outh,
                                                     const float* __restrict__ sc,
                                                     const float* __restrict__ sh,
                                                     int bn) {
    int wid = threadIdx.x >> 5;
    int lane = threadIdx.x & 31;
    int node = blockIdx.x * 8 + wid;
    if (node >= NN) return;
    int o0 = g_off[node];
    int o1 = g_off[node + 1];
    float4 s4 = make_float4(1.f, 1.f, 1.f, 1.f);
    float4 h4 = make_float4(0.f, 0.f, 0.f, 0.f);
    if (bn) {
        s4 = *(const float4*)&sc[lane * 4];
        h4 = *(const float4*)&sh[lane * 4];
    }
    float4 a0 = make_float4(0.f, 0.f, 0.f, 0.f);
    float4 a1 = make_float4(0.f, 0.f, 0.f, 0.f);
    float4 a2 = make_float4(0.f, 0.f, 0.f, 0.f);
    float4 a3 = make_float4(0.f, 0.f, 0.f, 0.f);
    int e = o0;
    for (; e + 4 <= o1; e += 4) {
        int s0 = g_esrc[e], s1 = g_esrc[e + 1], s2 = g_esrc[e + 2], s3 = g_esrc[e + 3];
        float4 v0 = *(const float4*)&x[(long)s0 * H + lane * 4];
        float4 v1 = *(const float4*)&x[(long)s1 * H + lane * 4];
        float4 v2 = *(const float4*)&x[(long)s2 * H + lane * 4];
        float4 v3 = *(const float4*)&x[(long)s3 * H + lane * 4];
        if (bn) {
            v0 = bn_lrelu4(v0, s4, h4); v1 = bn_lrelu4(v1, s4, h4);
            v2 = bn_lrelu4(v2, s4, h4); v3 = bn_lrelu4(v3, s4, h4);
        }
        a0.x += v0.x; a0.y += v0.y; a0.z += v0.z; a0.w += v0.w;
        a1.x += v1.x; a1.y += v1.y; a1.z += v1.z; a1.w += v1.w;
        a2.x += v2.x; a2.y += v2.y; a2.z += v2.z; a2.w += v2.w;
        a3.x += v3.x; a3.y += v3.y; a3.z += v3.z; a3.w += v3.w;
    }
    for (; e < o1; e++) {
        int s0 = g_esrc[e];
        float4 v0 = *(const float4*)&x[(long)s0 * H + lane * 4];
        if (bn) v0 = bn_lrelu4(v0, s4, h4);
        a0.x += v0.x; a0.y += v0.y; a0.z += v0.z; a0.w += v0.w;
    }
    a0.x += a1.x + a2.x + a3.x;
    a0.y += a1.y + a2.y + a3.y;
    a0.z += a1.z + a2.z + a3.z;
    a0.w += a1.w + a2.w + a3.w;
    uint2 o;
    o.x = pack_h2(a0.x, a0.y);
    o.y = pack_h2(a0.z, a0.w);
    *(uint2*)&outh[(long)node * H + lane * 4] = o;
}

// ---------------- proj_q via mma.sync fp16 (A hi; B hi+lo) --------------------
__global__ void __launch_bounds__(256, 2) proj_q_mma(const float* __restrict__ A,
                                                     const float* __restrict__ bias,
                                                     float* __restrict__ out) {
    extern __shared__ char sm[];
    uint32_t sb = smem_u32(sm);
    char* smg = sm;
    int tid = threadIdx.x;
    int wid = tid >> 5;
    int lane = tid & 31;
    int wm = wid & 3;
    int wn = wid >> 2;
    int row0 = blockIdx.x * BM;

    float acc[2][8][4];
#pragma unroll
    for (int mt = 0; mt < 2; mt++)
#pragma unroll
        for (int nt = 0; nt < 8; nt++)
#pragma unroll
            for (int j = 0; j < 4; j++) acc[mt][nt][j] = 0.f;

    int af_row[4], af_c4[4];
#pragma unroll
    for (int i = 0; i < 4; i++) {
        int f = tid + i * 256;
        af_row[i] = f >> 3;
        af_c4[i] = f & 7;
    }

    float4 av[4];
#pragma unroll
    for (int i = 0; i < 4; i++) {
        int grow = row0 + af_row[i];
        if (grow >= NQ) grow = 0;
        av[i] = *(const float4*)&A[(long)grow * QD + af_c4[i] * 4];
    }
#pragma unroll
    for (int i = 0; i < 2; i++) {
        int seg = tid + i * 256;
        int br = seg >> 4, c16 = seg & 15;
        cp16(sb + BH_OFF + br * B_STRIDE_B + c16 * 16, g_wqhi + br * H + c16 * 8);
        cp16(sb + BL_OFF + br * B_STRIDE_B + c16 * 16, g_wqlo + br * H + c16 * 8);
    }
    CP_COMMIT();
#pragma unroll
    for (int i = 0; i < 4; i++)
        a_store_h(smg, AH_OFF, af_row[i], af_c4[i], av[i]);

    const int TST = QD / BK;  // 12
    for (int t = 0; t < TST; t++) {
        int buf = t & 1;
        int have_next = (t + 1 < TST);
        if (have_next) {
            int k0 = (t + 1) * BK;
            int nb = buf ^ 1;
#pragma unroll
            for (int i = 0; i < 4; i++) {
                int grow = row0 + af_row[i];
                if (grow >= NQ) grow = 0;
                av[i] = *(const float4*)&A[(long)grow * QD + k0 + af_c4[i] * 4];
            }
#pragma unroll
            for (int i = 0; i < 2; i++) {
                int seg = tid + i * 256;
                int br = seg >> 4, c16 = seg & 15;
                cp16(sb + BH_OFF + nb * BBUF + br * B_STRIDE_B + c16 * 16,
                     g_wqhi + (k0 + br) * H + c16 * 8);
                cp16(sb + BL_OFF + nb * BBUF + br * B_STRIDE_B + c16 * 16,
                     g_wqlo + (k0 + br) * H + c16 * 8);
            }
            CP_COMMIT();
            asm volatile("cp.async.wait_group 1;");
        } else {
            asm volatile("cp.async.wait_group 0;");
        }
        __syncthreads();

        uint32_t abase = sb + AH_OFF + buf * ABUF;
        uint32_t bbase_hi = sb + BH_OFF + buf * BBUF;
        uint32_t bbase_lo = sb + BL_OFF + buf * BBUF;
#pragma unroll
        for (int ks = 0; ks < 2; ks++) {
            uint32_t ah[2][4], bh[8][2], bl[8][2];
#pragma unroll
            for (int mt = 0; mt < 2; mt++) {
                uint32_t roff = (uint32_t)((wm * 32 + mt * 16 + (lane & 15)) * A_STRIDE_B
                                           + ks * 32 + (lane >> 4) * 16);
                LDSM_X4(ah[mt][0], ah[mt][1], ah[mt][2], ah[mt][3], abase + roff);
            }
#pragma unroll
            for (int np = 0; np < 4; np++) {
                uint32_t boff = (uint32_t)((ks * 16 + (lane & 15)) * B_STRIDE_B
                                           + (wn * 64 + np * 16 + (lane >> 4) * 8) * 2);
                LDSM_X4T(bh[np * 2][0], bh[np * 2][1], bh[np * 2 + 1][0], bh[np * 2 + 1][1],
                         bbase_hi + boff);
                LDSM_X4T(bl[np * 2][0], bl[np * 2][1], bl[np * 2 + 1][0], bl[np * 2 + 1][1],
                         bbase_lo + boff);
            }
#pragma unroll
            for (int mt = 0; mt < 2; mt++)
#pragma unroll
                for (int nt = 0; nt < 8; nt++) {
                    MMA_F16(acc[mt][nt], ah[mt], bh[nt]);
                    MMA_F16(acc[mt][nt], ah[mt], bl[nt]);
                }
        }
        __syncthreads();

        if (have_next) {
            int nb = buf ^ 1;
#pragma unroll
            for (int i = 0; i < 4; i++)
                a_store_h(smg, AH_OFF + nb * ABUF, af_row[i], af_c4[i], av[i]);
        }
    }

#pragma unroll
    for (int mt = 0; mt < 2; mt++) {
        int m0r = row0 + wm * 32 + mt * 16 + (lane >> 2);
        int m1r = m0r + 8;
#pragma unroll
        for (int nt = 0; nt < 8; nt++) {
            int n = wn * 64 + nt * 8 + (lane & 3) * 2;
            float2 bv = *(const float2*)&bias[n];
            if (m0r < NQ) {
                float2 o = make_float2(acc[mt][nt][0] + bv.x, acc[mt][nt][1] + bv.y);
                *(float2*)&out[(long)m0r * H + n] = o;
            }
            if (m1r < NQ) {
                float2 o = make_float2(acc[mt][nt][2] + bv.x, acc[mt][nt][3] + bv.y);
                *(float2*)&out[(long)m1r * H + n] = o;
            }
        }
    }
}

// ---------------- layer GEMM via mma.sync fp16 (A half direct cp.async) --------
__global__ void __launch_bounds__(256, 2) layer_gemm_mma(
        const __half* __restrict__ Ah,
        const __half* __restrict__ Whi,
        const __half* __restrict__ Wlo,
        const float* __restrict__ bm, const float* __restrict__ be,
        const float* __restrict__ We,
        const float* __restrict__ xprev,
        const float* __restrict__ psc, const float* __restrict__ psh,
        int prev_bn,
        float* __restrict__ out) {
    extern __shared__ char sm[];
    uint32_t sb = smem_u32(sm);
    int tid = threadIdx.x;
    int wid = tid >> 5;
    int lane = tid & 31;
    int wm = wid & 3;
    int wn = wid >> 2;
    int row0 = blockIdx.x * BM;

    float acc[2][8][4];
#pragma unroll
    for (int mt = 0; mt < 2; mt++)
#pragma unroll
        for (int nt = 0; nt < 8; nt++)
#pragma unroll
            for (int j = 0; j < 4; j++) acc[mt][nt][j] = 0.f;

    // A loader: per stage 128 rows x 64B = 512 x 16B chunks, 2 per thread
    int ar[2], ac[2];
#pragma unroll
    for (int i = 0; i < 2; i++) {
        int c = tid + i * 256;
        int r = c >> 2;
        ar[i] = (row0 + r < NN) ? (row0 + r) : 0;
        ac[i] = (c & 3) * 8;    // half-element offset within 32
    }

    // prologue stage 0 (A + B)
#pragma unroll
    for (int i = 0; i < 2; i++) {
        int c = tid + i * 256;
        cp16(sb + AH_OFF + (c >> 2) * A_STRIDE_B + (c & 3) * 16,
             Ah + (long)ar[i] * H + ac[i]);
    }
#pragma unroll
    for (int i = 0; i < 2; i++) {
        int seg = tid + i * 256;
        int br = seg >> 4, c16 = seg & 15;
        cp16(sb + BH_OFF + br * B_STRIDE_B + c16 * 16, Whi + br * H + c16 * 8);
        cp16(sb + BL_OFF + br * B_STRIDE_B + c16 * 16, Wlo + br * H + c16 * 8);
    }
    CP_COMMIT();

    const int TST = H / BK;  // 4
    for (int t = 0; t < TST; t++) {
        int buf = t & 1;
        int have_next = (t + 1 < TST);
        if (have_next) {
            int k0 = (t + 1) * BK;
            int nb = buf ^ 1;
#pragma unroll
            for (int i = 0; i < 2; i++) {
                int c = tid + i * 256;
                cp16(sb + AH_OFF + nb * ABUF + (c >> 2) * A_STRIDE_B + (c & 3) * 16,
                     Ah + (long)ar[i] * H + k0 + ac[i]);
            }
#pragma unroll
            for (int i = 0; i < 2; i++) {
                int seg = tid + i * 256;
                int br = seg >> 4, c16 = seg & 15;
                cp16(sb + BH_OFF + nb * BBUF + br * B_STRIDE_B + c16 * 16,
                     Whi + (k0 + br) * H + c16 * 8);
                cp16(sb + BL_OFF + nb * BBUF + br * B_STRIDE_B + c16 * 16,
                     Wlo + (k0 + br) * H + c16 * 8);
            }
            CP_COMMIT();
            asm volatile("cp.async.wait_group 1;");
        } else {
            asm volatile("cp.async.wait_group 0;");
        }
        __syncthreads();

        uint32_t abase = sb + AH_OFF + buf * ABUF;
        uint32_t bbase_hi = sb + BH_OFF + buf * BBUF;
        uint32_t bbase_lo = sb + BL_OFF + buf * BBUF;
#pragma unroll
        for (int ks = 0; ks < 2; ks++) {
            uint32_t ah[2][4], bh[8][2], bl[8][2];
#pragma unroll
            for (int mt = 0; mt < 2; mt++) {
                uint32_t roff = (uint32_t)((wm * 32 + mt * 16 + (lane & 15)) * A_STRIDE_B
                                           + ks * 32 + (lane >> 4) * 16);
                LDSM_X4(ah[mt][0], ah[mt][1], ah[mt][2], ah[mt][3], abase + roff);
            }
#pragma unroll
            for (int np = 0; np < 4; np++) {
                uint32_t boff = (uint32_t)((ks * 16 + (lane & 15)) * B_STRIDE_B
                                           + (wn * 64 + np * 16 + (lane >> 4) * 8) * 2);
                LDSM_X4T(bh[np * 2][0], bh[np * 2][1], bh[np * 2 + 1][0], bh[np * 2 + 1][1],
                         bbase_hi + boff);
                LDSM_X4T(bl[np * 2][0], bl[np * 2][1], bl[np * 2 + 1][0], bl[np * 2 + 1][1],
                         bbase_lo + boff);
            }
#pragma unroll
            for (int mt = 0; mt < 2; mt++)
#pragma unroll
                for (int nt = 0; nt < 8; nt++) {
                    MMA_F16(acc[mt][nt], ah[mt], bh[nt]);
                    MMA_F16(acc[mt][nt], ah[mt], bl[nt]);
                }
        }
        __syncthreads();
    }

    // ---- fused epilogue ----
    int lq = lane & 3;
    int lr = lane >> 2;
    float2 ds[2][2];
    bool rv[2][2];
#pragma unroll
    for (int mt = 0; mt < 2; mt++)
#pragma unroll
        for (int hf = 0; hf < 2; hf++) {
            int row = row0 + wm * 32 + mt * 16 + hf * 8 + lr;
            rv[mt][hf] = (row < NN);
            ds[mt][hf] = rv[mt][hf] ? g_degew[row] : make_float2(0.f, 0.f);
        }

#pragma unroll
    for (int nt = 0; nt < 8; nt++) {
        int n = wn * 64 + nt * 8 + lq * 2;
        float2 cb2 = make_float2(bm[n] + be[n], bm[n + 1] + be[n + 1]);
        float2 we2 = *(const float2*)&We[n];
        float2 sc2 = make_float2(0.f, 0.f), sh2 = make_float2(0.f, 0.f);
        if (prev_bn) {
            sc2 = make_float2(psc[n], psc[n + 1]);
            sh2 = make_float2(psh[n], psh[n + 1]);
        }
        float cs0 = 0.f, cs1 = 0.f, cq0 = 0.f, cq1 = 0.f;
#pragma unroll
        for (int mt = 0; mt < 2; mt++)
#pragma unroll
            for (int hf = 0; hf < 2; hf++) {
                if (rv[mt][hf]) {
                    int row = row0 + wm * 32 + mt * 16 + hf * 8 + lr;
                    float2 xp = *(const float2*)&xprev[(long)row * H + n];
                    if (prev_bn) {
                        float u0 = fmaf(xp.x, sc2.x, sh2.x);
                        float u1 = fmaf(xp.y, sc2.y, sh2.y);
                        xp.x = u0 > 0.f ? u0 : 0.01f * u0;
                        xp.y = u1 > 0.f ? u1 : 0.01f * u1;
                    }
                    float2 dd = ds[mt][hf];
                    float v0 = acc[mt][nt][hf * 2 + 0] + dd.x * cb2.x + dd.y * we2.x + xp.x;
                    float v1 = acc[mt][nt][hf * 2 + 1] + dd.x * cb2.y + dd.y * we2.y + xp.y;
                    *(float2*)&out[(long)row * H + n] = make_float2(v0, v1);
                    cs0 += v0; cq0 += v0 * v0;
                    cs1 += v1; cq1 += v1 * v1;
                }
            }
#pragma unroll
        for (int off = 4; off <= 16; off <<= 1) {
            cs0 += __shfl_xor_sync(0xffffffffu, cs0, off);
            cq0 += __shfl_xor_sync(0xffffffffu, cq0, off);
            cs1 += __shfl_xor_sync(0xffffffffu, cs1, off);
            cq1 += __shfl_xor_sync(0xffffffffu, cq1, off);
        }
        if (lr == 0) {
            asm volatile("red.global.add.v2.f32 [%0], {%1, %2};"
                         :: "l"(&g_colstats2[n]), "f"(cs0), "f"(cq0) : "memory");
            asm volatile("red.global.add.v2.f32 [%0], {%1, %2};"
                         :: "l"(&g_colstats2[n + 1]), "f"(cs1), "f"(cq1) : "memory");
        }
    }
}

// ---------------- BN stat finalize (+ self-zero) -------------------------------
__global__ void finalize_kernel(const float* __restrict__ g,
                                const float* __restrict__ beta,
                                float* __restrict__ sc_out,
                                float* __restrict__ sh_out) {
    int j = threadIdx.x;
    float2 s = g_colstats2[j];
    float mu = s.x * (1.f / (float)NN);
    float var = s.y * (1.f / (float)NN) - mu * mu;
    float rstd = rsqrtf(var + BN_EPS);
    float sc = g[j] * rstd;
    sc_out[j] = sc;
    sh_out[j] = beta[j] - mu * sc;
    g_colstats2[j] = make_float2(0.f, 0.f);
}

// ---------------- edge prediction (BN2 inline) ----------------------------------
__global__ void predict_kernel(const int* __restrict__ ei,
                               const int* __restrict__ em,
                               const float* __restrict__ x2raw,
                               const float* __restrict__ sc,
                               const float* __restrict__ sh,
                               float* __restrict__ out) {
    int warp = (blockIdx.x * blockDim.x + threadIdx.x) >> 5;
    int lane = threadIdx.x & 31;
    if (warp >= EPRED) return;
    float4 s2 = *(const float4*)&sc[lane * 4];
    float4 h2 = *(const float4*)&sh[lane * 4];
    int e = em[warp];
    int s = ei[e];
    int t = ei[EE + e];
    float4 a = *(const float4*)&g_xini[s * H + lane * 4];
    float4 b = *(const float4*)&x2raw[t * H + lane * 4];
    b.x = fmaf(b.x, s2.x, h2.x);
    b.y = fmaf(b.y, s2.y, h2.y);
    b.z = fmaf(b.z, s2.z, h2.z);
    b.w = fmaf(b.w, s2.w, h2.w);
    float d = a.x * b.x + a.y * b.y + a.z * b.z + a.w * b.w;
#pragma unroll
    for (int o = 16; o; o >>= 1) d += __shfl_xor_sync(0xffffffffu, d, o);
    if (lane == 0) out[warp] = 1.f / (1.f + expf(-d * (1.f / 128.f)));
}

// ---------------- launch -----------------------------------------------------
extern "C" void kernel_launch(void* const* d_in, const int* in_sizes, int n_in,
                              void* d_out, int out_size) {
    const float* qf  = (const float*)d_in[0];
    const float* lf  = (const float*)d_in[1];
    const int*   ei  = (const int*)d_in[2];
    const int*   em  = (const int*)d_in[3];
    const int*   ecs = (const int*)d_in[4];
    const float* ewt = (const float*)d_in[5];
    const float* Wq  = (const float*)d_in[6];
    const float* bq  = (const float*)d_in[7];
    const float* Wl  = (const float*)d_in[8];
    const float* bl  = (const float*)d_in[9];
    const float* Wem = (const float*)d_in[10];
    const float* bem = (const float*)d_in[11];
    const float* W1m = (const float*)d_in[12];
    const float* b1m = (const float*)d_in[13];
    const float* W1e = (const float*)d_in[14];
    const float* b1e = (const float*)d_in[15];
    const float* W2m = (const float*)d_in[16];
    const float* b2m = (const float*)d_in[17];
    const float* W2e = (const float*)d_in[18];
    const float* b2e = (const float*)d_in[19];
    const float* g1    = (const float*)d_in[20];
    const float* beta1 = (const float*)d_in[21];
    const float* g2    = (const float*)d_in[22];
    const float* beta2 = (const float*)d_in[23];
    float* out = (float*)d_out;

    void *p_agg, *p_xini, *p_x1, *p_aggh, *p_degew;
    void *p_sc1, *p_sh1, *p_sc2, *p_sh2;
    void *p_w1hi, *p_w1lo, *p_w2hi, *p_w2lo;
    cudaGetSymbolAddress(&p_agg, g_agg);
    cudaGetSymbolAddress(&p_xini, g_xini);
    cudaGetSymbolAddress(&p_x1, g_x1);
    cudaGetSymbolAddress(&p_aggh, g_aggh);
    cudaGetSymbolAddress(&p_degew, g_degew);
    cudaGetSymbolAddress(&p_sc1, g_scale1);
    cudaGetSymbolAddress(&p_sh1, g_shift1);
    cudaGetSymbolAddress(&p_sc2, g_scale2);
    cudaGetSymbolAddress(&p_sh2, g_shift2);
    cudaGetSymbolAddress(&p_w1hi, g_w1hi);
    cudaGetSymbolAddress(&p_w1lo, g_w1lo);
    cudaGetSymbolAddress(&p_w2hi, g_w2hi);
    cudaGetSymbolAddress(&p_w2lo, g_w2lo);

    static int init_done = 0;
    static cudaStream_t s_edge;
    static cudaEvent_t ev_fork, ev_edge;
    if (!init_done) {
        cudaFuncSetAttribute(proj_q_mma, cudaFuncAttributeMaxDynamicSharedMemorySize,
                             SMEM_MMA);
        cudaFuncSetAttribute(layer_gemm_mma, cudaFuncAttributeMaxDynamicSharedMemorySize,
                             SMEM_MMA);
        cudaStreamCreateWithFlags(&s_edge, cudaStreamNonBlocking);
        cudaEventCreateWithFlags(&ev_fork, cudaEventDisableTiming);
        cudaEventCreateWithFlags(&ev_edge, cudaEventDisableTiming);
        init_done = 1;
    }

    cudaMemsetAsync(p_degew, 0, NN * sizeof(float2));

    // ---- fork edge-sort chain onto side stream ----
    cudaEventRecord(ev_fork, 0);
    cudaStreamWaitEvent(s_edge, ev_fork, 0);
    edge_prep_kernel<<<(ESEE + 255) / 256, 256, 0, s_edge>>>(ei, ecs, ewt, Wem, bem);
    scan1_kernel<<<SCAN_B, 256, 0, s_edge>>>();
    scan2_kernel<<<1, 512, 0, s_edge>>>();
    scan3_kernel<<<SCAN_B, 256, 0, s_edge>>>();
    placement_kernel<<<(ESEE + 255) / 256, 256, 0, s_edge>>>();
    cudaEventRecord(ev_edge, s_edge);

    // ---- main stream: projection chain ----
    prep_all_kernel<<<(QD * H + 2 * H * H + 255) / 256, 256>>>(Wq, W1m, W2m);
    proj_l_kernel<<<NL, 512>>>(lf, Wl, bl);
    proj_q_mma<<<GRID_TC, 256, SMEM_MMA>>>(qf, bq, (float*)p_xini);

    // ---- join ----
    cudaStreamWaitEvent(0, ev_edge, 0);

    // ---- layer 1 ----
    gather_kernel<<<(NN + 7) / 8, 256>>>((const float*)p_xini, (__half*)p_aggh,
                                         nullptr, nullptr, 0);
    layer_gemm_mma<<<GRID_TC, 256, SMEM_MMA>>>(
        (const __half*)p_aggh, (const __half*)p_w1hi, (const __half*)p_w1lo,
        b1m, b1e, W1e, (const float*)p_xini,
        nullptr, nullptr, 0, (float*)p_agg);
    finalize_kernel<<<1, H>>>(g1, beta1, (float*)p_sc1, (float*)p_sh1);

    // ---- layer 2 ----
    gather_kernel<<<(NN + 7) / 8, 256>>>((const float*)p_agg, (__half*)p_aggh,
                                         (const float*)p_sc1, (const float*)p_sh1, 1);
    layer_gemm_mma<<<GRID_TC, 256, SMEM_MMA>>>(
        (const __half*)p_aggh, (const __half*)p_w2hi, (const __half*)p_w2lo,
        b2m, b2e, W2e, (const float*)p_agg,
        (const float*)p_sc1, (const float*)p_sh1, 1, (float*)p_x1);
    finalize_kernel<<<1, H>>>(g2, beta2, (float*)p_sc2, (float*)p_sh2);
    predict_kernel<<<EPRED / 8, 256>>>(ei, em, (const float*)p_x1,
                                       (const float*)p_sc2, (const float*)p_sh2, out);
}

// round 14
// speedup vs baseline: 1.4198x; 1.0315x over previous
#include <cuda_runtime.h>
#include <cuda_fp16.h>
#include <math.h>
#include <stdint.h>

#define NQ    100000
#define NL    32
#define NN    100032
#define QD    384
#define LD    1024
#define H     128
#define EE    1000000
#define ESEE  750000
#define EPRED 250000
#define BN_EPS 1e-5f
#define SCAN_B 391               // ceil(NN/256)

// mma tile config: BM=128 x BN=128, 8 warps (4m x 2n), warp tile 32x64
// pure fp16 GEMM, fp32 accum: 1 MMA per (mt,nt) per ks.
#define BM 128
#define BK 32
#define GRID_TC 782
#define A_STRIDE_B 80            // (32+8) fp16 * 2
#define B_STRIDE_B 272           // (128+8) fp16 * 2
#define ABUF 10240               // 128 * 80
#define BBUF 8704                // 32 * 272
#define AH_OFF 0                 // 2 bufs
#define BH_OFF 20480             // 2 bufs
#define SMEM_MMA 37888

// ---------------- scratch ------------------------------------------------
__device__ __align__(16) float g_xini[NN * H];
__device__ __align__(16) float g_agg [NN * H];      // t1 (fp32 layer-1 out)
__device__ __align__(16) float g_x1  [NN * H];      // t2 (fp32 layer-2 out)
__device__ __align__(16) __half g_aggh[NN * H];     // fp16 gather output (GEMM A)
__device__ int    g_src[ESEE];
__device__ int    g_dst[ESEE];
__device__ int    g_esrc[ESEE];
__device__ int    g_off[NN + 1];
__device__ int    g_cursor[NN];
__device__ int    g_blk[SCAN_B];
__device__ __align__(8) float2 g_degew[NN];
__device__ __align__(8) float2 g_colstats2[H];
__device__ float g_scale1[H], g_shift1[H];
__device__ float g_scale2[H], g_shift2[H];
__device__ __align__(16) __half g_wqhi[QD * H];
__device__ __align__(16) __half g_w1hi[H * H];
__device__ __align__(16) __half g_w2hi[H * H];

// ---------------- ptx helpers ----------------------------------------------
__device__ __forceinline__ unsigned smem_u32(const void* p) {
    return (unsigned)__cvta_generic_to_shared(p);
}
__device__ __forceinline__ void cp16(unsigned dst, const void* src) {
    asm volatile("cp.async.ca.shared.global [%0], [%1], 16;" :: "r"(dst), "l"(src));
}
#define CP_COMMIT() asm volatile("cp.async.commit_group;")

#define LDSM_X4(r0, r1, r2, r3, addr) \
    asm volatile("ldmatrix.sync.aligned.m8n8.x4.shared.b16 {%0,%1,%2,%3}, [%4];" \
                 : "=r"(r0), "=r"(r1), "=r"(r2), "=r"(r3) : "r"(addr))
#define LDSM_X4T(r0, r1, r2, r3, addr) \
    asm volatile("ldmatrix.sync.aligned.m8n8.x4.trans.shared.b16 {%0,%1,%2,%3}, [%4];" \
                 : "=r"(r0), "=r"(r1), "=r"(r2), "=r"(r3) : "r"(addr))
#define MMA_F16(c, a, b) \
    asm volatile("mma.sync.aligned.m16n8k16.row.col.f32.f16.f16.f32 " \
                 "{%0,%1,%2,%3}, {%4,%5,%6,%7}, {%8,%9}, {%0,%1,%2,%3};" \
                 : "+f"((c)[0]), "+f"((c)[1]), "+f"((c)[2]), "+f"((c)[3]) \
                 : "r"((a)[0]), "r"((a)[1]), "r"((a)[2]), "r"((a)[3]), \
                   "r"((b)[0]), "r"((b)[1]))

__device__ __forceinline__ uint32_t pack_h2(float x, float y) {
    __half hx = __float2half_rn(x);
    __half hy = __float2half_rn(y);
    return ((uint32_t)__half_as_ushort(hy) << 16) | __half_as_ushort(hx);
}
__device__ __forceinline__ void a_store_h(char* smg, int off, int row, int c4, float4 v) {
    uint2 hp;
    hp.x = pack_h2(v.x, v.y);
    hp.y = pack_h2(v.z, v.w);
    *(uint2*)(smg + off + row * A_STRIDE_B + c4 * 8) = hp;
}

// ---------------- W prep: fp32 -> fp16 ------------------------------------------
__global__ void prep_all_kernel(const float* __restrict__ Wq,
                                const float* __restrict__ W1,
                                const float* __restrict__ W2) {
    int idx = blockIdx.x * blockDim.x + threadIdx.x;
    const int NQW = QD * H, NW = H * H;
    if (idx < NQW)                g_wqhi[idx] = __float2half_rn(Wq[idx]);
    else if (idx < NQW + NW)      g_w1hi[idx - NQW] = __float2half_rn(W1[idx - NQW]);
    else if (idx < NQW + 2 * NW)  g_w2hi[idx - NQW - NW] = __float2half_rn(W2[idx - NQW - NW]);
}

// ---------------- llm projection (split-K, 512 thr) ---------------------------
__global__ void proj_l_kernel(const float* __restrict__ A,
                              const float* __restrict__ W,
                              const float* __restrict__ b) {
    __shared__ float red[4][H];
    int i = blockIdx.x;
    int t = threadIdx.x;
    int j = t & 127;
    int seg = t >> 7;
    float acc = 0.f;
    const float* arow = A + i * LD + seg * 256;
    const float* wcol = W + (seg * 256) * H + j;
    for (int k = 0; k < 256; k++) acc += arow[k] * wcol[k * H];
    red[seg][j] = acc;
    __syncthreads();
    if (seg == 0)
        g_xini[(NQ + i) * H + j] = red[0][j] + red[1][j] + red[2][j] + red[3][j] + b[j];
}

// ---------------- edge prep (+ zero colstats) ---------------------------------
__global__ void edge_prep_kernel(const int* __restrict__ ei,
                                 const int* __restrict__ ecs,
                                 const float* __restrict__ ewt,
                                 const float* __restrict__ Wem,
                                 const float* __restrict__ bem) {
    int i = blockIdx.x * blockDim.x + threadIdx.x;
    if (blockIdx.x == 0 && threadIdx.x < H)
        g_colstats2[threadIdx.x] = make_float2(0.f, 0.f);
    if (i >= ESEE) return;
    int e = ecs[i];
    int s = ei[e];
    int d = ei[EE + e];
    g_src[i] = s;
    g_dst[i] = d;
    float v = ewt[e] * Wem[0] + bem[0];
    v = v > 0.f ? v : 0.01f * v;
    asm volatile("red.global.add.v2.f32 [%0], {%1, %2};"
                 :: "l"(&g_degew[d]), "f"(1.0f), "f"(v) : "memory");
}

// ---------------- counting-sort scan trio --------------------------------------
__global__ void scan1_kernel() {
    __shared__ int red[256];
    int t = threadIdx.x;
    int i = blockIdx.x * 256 + t;
    int c = (i < NN) ? (int)g_degew[i].x : 0;
    red[t] = c;
    __syncthreads();
#pragma unroll
    for (int o = 128; o > 0; o >>= 1) {
        if (t < o) red[t] += red[t + o];
        __syncthreads();
    }
    if (t == 0) g_blk[blockIdx.x] = red[0];
}

__global__ void scan2_kernel() {
    __shared__ int s[512];
    int t = threadIdx.x;
    int c = (t < SCAN_B) ? g_blk[t] : 0;
    s[t] = c;
    __syncthreads();
    for (int o = 1; o < 512; o <<= 1) {
        int v = (t >= o) ? s[t - o] : 0;
        __syncthreads();
        s[t] += v;
        __syncthreads();
    }
    if (t < SCAN_B) g_blk[t] = s[t] - c;
}

__global__ void scan3_kernel() {
    __shared__ int s[256];
    int t = threadIdx.x;
    int i = blockIdx.x * 256 + t;
    int c = (i < NN) ? (int)g_degew[i].x : 0;
    s[t] = c;
    __syncthreads();
    for (int o = 1; o < 256; o <<= 1) {
        int v = (t >= o) ? s[t - o] : 0;
        __syncthreads();
        s[t] += v;
        __syncthreads();
    }
    if (i < NN) {
        int off = g_blk[blockIdx.x] + s[t] - c;
        g_off[i] = off;
        g_cursor[i] = off;
    }
    if (i == 0) g_off[NN] = ESEE;
}

__global__ void placement_kernel() {
    int i = blockIdx.x * blockDim.x + threadIdx.x;
    if (i >= ESEE) return;
    int d = g_dst[i];
    int pos = atomicAdd(&g_cursor[d], 1);
    g_esrc[pos] = g_src[i];
}

// ---------------- gather aggregation -> fp16 output ----------------------------
__device__ __forceinline__ float4 bn_lrelu4(float4 v, float4 s4, float4 h4) {
    v.x = fmaf(v.x, s4.x, h4.x); v.x = v.x > 0.f ? v.x : 0.01f * v.x;
    v.y = fmaf(v.y, s4.y, h4.y); v.y = v.y > 0.f ? v.y : 0.01f * v.y;
    v.z = fmaf(v.z, s4.z, h4.z); v.z = v.z > 0.f ? v.z : 0.01f * v.z;
    v.w = fmaf(v.w, s4.w, h4.w); v.w = v.w > 0.f ? v.w : 0.01f * v.w;
    return v;
}
__global__ void __launch_bounds__(256) gather_kernel(const float* __restrict__ x,
                                                     __half* __restrict__ outh,
                                                     const float* __restrict__ sc,
                                                     const float* __restrict__ sh,
                                                     int bn) {
    int wid = threadIdx.x >> 5;
    int lane = threadIdx.x & 31;
    int node = blockIdx.x * 8 + wid;
    if (node >= NN) return;
    int o0 = g_off[node];
    int o1 = g_off[node + 1];
    float4 s4 = make_float4(1.f, 1.f, 1.f, 1.f);
    float4 h4 = make_float4(0.f, 0.f, 0.f, 0.f);
    if (bn) {
        s4 = *(const float4*)&sc[lane * 4];
        h4 = *(const float4*)&sh[lane * 4];
    }
    float4 a0 = make_float4(0.f, 0.f, 0.f, 0.f);
    float4 a1 = make_float4(0.f, 0.f, 0.f, 0.f);
    float4 a2 = make_float4(0.f, 0.f, 0.f, 0.f);
    float4 a3 = make_float4(0.f, 0.f, 0.f, 0.f);
    int e = o0;
    for (; e + 4 <= o1; e += 4) {
        int s0 = g_esrc[e], s1 = g_esrc[e + 1], s2 = g_esrc[e + 2], s3 = g_esrc[e + 3];
        float4 v0 = *(const float4*)&x[(long)s0 * H + lane * 4];
        float4 v1 = *(const float4*)&x[(long)s1 * H + lane * 4];
        float4 v2 = *(const float4*)&x[(long)s2 * H + lane * 4];
        float4 v3 = *(const float4*)&x[(long)s3 * H + lane * 4];
        if (bn) {
            v0 = bn_lrelu4(v0, s4, h4); v1 = bn_lrelu4(v1, s4, h4);
            v2 = bn_lrelu4(v2, s4, h4); v3 = bn_lrelu4(v3, s4, h4);
        }
        a0.x += v0.x; a0.y += v0.y; a0.z += v0.z; a0.w += v0.w;
        a1.x += v1.x; a1.y += v1.y; a1.z += v1.z; a1.w += v1.w;
        a2.x += v2.x; a2.y += v2.y; a2.z += v2.z; a2.w += v2.w;
        a3.x += v3.x; a3.y += v3.y; a3.z += v3.z; a3.w += v3.w;
    }
    for (; e < o1; e++) {
        int s0 = g_esrc[e];
        float4 v0 = *(const float4*)&x[(long)s0 * H + lane * 4];
        if (bn) v0 = bn_lrelu4(v0, s4, h4);
        a0.x += v0.x; a0.y += v0.y; a0.z += v0.z; a0.w += v0.w;
    }
    a0.x += a1.x + a2.x + a3.x;
    a0.y += a1.y + a2.y + a3.y;
    a0.z += a1.z + a2.z + a3.z;
    a0.w += a1.w + a2.w + a3.w;
    uint2 o;
    o.x = pack_h2(a0.x, a0.y);
    o.y = pack_h2(a0.z, a0.w);
    *(uint2*)&outh[(long)node * H + lane * 4] = o;
}

// ---------------- proj_q via mma.sync pure fp16 --------------------------------
__global__ void __launch_bounds__(256, 2) proj_q_mma(const float* __restrict__ A,
                                                     const float* __restrict__ bias,
                                                     float* __restrict__ out) {
    extern __shared__ char sm[];
    uint32_t sb = smem_u32(sm);
    char* smg = sm;
    int tid = threadIdx.x;
    int wid = tid >> 5;
    int lane = tid & 31;
    int wm = wid & 3;
    int wn = wid >> 2;
    int row0 = blockIdx.x * BM;

    float acc[2][8][4];
#pragma unroll
    for (int mt = 0; mt < 2; mt++)
#pragma unroll
        for (int nt = 0; nt < 8; nt++)
#pragma unroll
            for (int j = 0; j < 4; j++) acc[mt][nt][j] = 0.f;

    int af_row[4], af_c4[4];
#pragma unroll
    for (int i = 0; i < 4; i++) {
        int f = tid + i * 256;
        af_row[i] = f >> 3;
        af_c4[i] = f & 7;
    }

    float4 av[4];
#pragma unroll
    for (int i = 0; i < 4; i++) {
        int grow = row0 + af_row[i];
        if (grow >= NQ) grow = 0;
        av[i] = *(const float4*)&A[(long)grow * QD + af_c4[i] * 4];
    }
    {
        int seg = tid;
        int br = seg >> 3, c16 = seg & 7;   // 256 thr covers 32 rows x 8 chunks? no:
    }
    // B loader: 32 rows x 256B data = 512 x 16B chunks, 2 per thread
#pragma unroll
    for (int i = 0; i < 2; i++) {
        int seg = tid + i * 256;
        int br = seg >> 4, c16 = seg & 15;
        cp16(sb + BH_OFF + br * B_STRIDE_B + c16 * 16, g_wqhi + br * H + c16 * 8);
    }
    CP_COMMIT();
#pragma unroll
    for (int i = 0; i < 4; i++)
        a_store_h(smg, AH_OFF, af_row[i], af_c4[i], av[i]);

    const int TST = QD / BK;  // 12
    for (int t = 0; t < TST; t++) {
        int buf = t & 1;
        int have_next = (t + 1 < TST);
        if (have_next) {
            int k0 = (t + 1) * BK;
            int nb = buf ^ 1;
#pragma unroll
            for (int i = 0; i < 4; i++) {
                int grow = row0 + af_row[i];
                if (grow >= NQ) grow = 0;
                av[i] = *(const float4*)&A[(long)grow * QD + k0 + af_c4[i] * 4];
            }
#pragma unroll
            for (int i = 0; i < 2; i++) {
                int seg = tid + i * 256;
                int br = seg >> 4, c16 = seg & 15;
                cp16(sb + BH_OFF + nb * BBUF + br * B_STRIDE_B + c16 * 16,
                     g_wqhi + (k0 + br) * H + c16 * 8);
            }
            CP_COMMIT();
            asm volatile("cp.async.wait_group 1;");
        } else {
            asm volatile("cp.async.wait_group 0;");
        }
        __syncthreads();

        uint32_t abase = sb + AH_OFF + buf * ABUF;
        uint32_t bbase = sb + BH_OFF + buf * BBUF;
#pragma unroll
        for (int ks = 0; ks < 2; ks++) {
            uint32_t ah[2][4], bh[8][2];
#pragma unroll
            for (int mt = 0; mt < 2; mt++) {
                uint32_t roff = (uint32_t)((wm * 32 + mt * 16 + (lane & 15)) * A_STRIDE_B
                                           + ks * 32 + (lane >> 4) * 16);
                LDSM_X4(ah[mt][0], ah[mt][1], ah[mt][2], ah[mt][3], abase + roff);
            }
#pragma unroll
            for (int np = 0; np < 4; np++) {
                uint32_t boff = (uint32_t)((ks * 16 + (lane & 15)) * B_STRIDE_B
                                           + (wn * 64 + np * 16 + (lane >> 4) * 8) * 2);
                LDSM_X4T(bh[np * 2][0], bh[np * 2][1], bh[np * 2 + 1][0], bh[np * 2 + 1][1],
                         bbase + boff);
            }
#pragma unroll
            for (int mt = 0; mt < 2; mt++)
#pragma unroll
                for (int nt = 0; nt < 8; nt++)
                    MMA_F16(acc[mt][nt], ah[mt], bh[nt]);
        }
        __syncthreads();

        if (have_next) {
            int nb = buf ^ 1;
#pragma unroll
            for (int i = 0; i < 4; i++)
                a_store_h(smg, AH_OFF + nb * ABUF, af_row[i], af_c4[i], av[i]);
        }
    }

#pragma unroll
    for (int mt = 0; mt < 2; mt++) {
        int m0r = row0 + wm * 32 + mt * 16 + (lane >> 2);
        int m1r = m0r + 8;
#pragma unroll
        for (int nt = 0; nt < 8; nt++) {
            int n = wn * 64 + nt * 8 + (lane & 3) * 2;
            float2 bv = *(const float2*)&bias[n];
            if (m0r < NQ) {
                float2 o = make_float2(acc[mt][nt][0] + bv.x, acc[mt][nt][1] + bv.y);
                *(float2*)&out[(long)m0r * H + n] = o;
            }
            if (m1r < NQ) {
                float2 o = make_float2(acc[mt][nt][2] + bv.x, acc[mt][nt][3] + bv.y);
                *(float2*)&out[(long)m1r * H + n] = o;
            }
        }
    }
}

// ---------------- layer GEMM via mma.sync pure fp16 ----------------------------
__global__ void __launch_bounds__(256, 2) layer_gemm_mma(
        const __half* __restrict__ Ah,
        const __half* __restrict__ Whi,
        const float* __restrict__ bm, const float* __restrict__ be,
        const float* __restrict__ We,
        const float* __restrict__ xprev,
        const float* __restrict__ psc, const float* __restrict__ psh,
        int prev_bn,
        float* __restrict__ out) {
    extern __shared__ char sm[];
    uint32_t sb = smem_u32(sm);
    int tid = threadIdx.x;
    int wid = tid >> 5;
    int lane = tid & 31;
    int wm = wid & 3;
    int wn = wid >> 2;
    int row0 = blockIdx.x * BM;

    float acc[2][8][4];
#pragma unroll
    for (int mt = 0; mt < 2; mt++)
#pragma unroll
        for (int nt = 0; nt < 8; nt++)
#pragma unroll
            for (int j = 0; j < 4; j++) acc[mt][nt][j] = 0.f;

    int ar[2], ac[2];
#pragma unroll
    for (int i = 0; i < 2; i++) {
        int c = tid + i * 256;
        int r = c >> 2;
        ar[i] = (row0 + r < NN) ? (row0 + r) : 0;
        ac[i] = (c & 3) * 8;
    }

#pragma unroll
    for (int i = 0; i < 2; i++) {
        int c = tid + i * 256;
        cp16(sb + AH_OFF + (c >> 2) * A_STRIDE_B + (c & 3) * 16,
             Ah + (long)ar[i] * H + ac[i]);
    }
#pragma unroll
    for (int i = 0; i < 2; i++) {
        int seg = tid + i * 256;
        int br = seg >> 4, c16 = seg & 15;
        cp16(sb + BH_OFF + br * B_STRIDE_B + c16 * 16, Whi + br * H + c16 * 8);
    }
    CP_COMMIT();

    const int TST = H / BK;  // 4
    for (int t = 0; t < TST; t++) {
        int buf = t & 1;
        int have_next = (t + 1 < TST);
        if (have_next) {
            int k0 = (t + 1) * BK;
            int nb = buf ^ 1;
#pragma unroll
            for (int i = 0; i < 2; i++) {
                int c = tid + i * 256;
                cp16(sb + AH_OFF + nb * ABUF + (c >> 2) * A_STRIDE_B + (c & 3) * 16,
                     Ah + (long)ar[i] * H + k0 + ac[i]);
            }
#pragma unroll
            for (int i = 0; i < 2; i++) {
                int seg = tid + i * 256;
                int br = seg >> 4, c16 = seg & 15;
                cp16(sb + BH_OFF + nb * BBUF + br * B_STRIDE_B + c16 * 16,
                     Whi + (k0 + br) * H + c16 * 8);
            }
            CP_COMMIT();
            asm volatile("cp.async.wait_group 1;");
        } else {
            asm volatile("cp.async.wait_group 0;");
        }
        __syncthreads();

        uint32_t abase = sb + AH_OFF + buf * ABUF;
        uint32_t bbase = sb + BH_OFF + buf * BBUF;
#pragma unroll
        for (int ks = 0; ks < 2; ks++) {
            uint32_t ah[2][4], bh[8][2];
#pragma unroll
            for (int mt = 0; mt < 2; mt++) {
                uint32_t roff = (uint32_t)((wm * 32 + mt * 16 + (lane & 15)) * A_STRIDE_B
                                           + ks * 32 + (lane >> 4) * 16);
                LDSM_X4(ah[mt][0], ah[mt][1], ah[mt][2], ah[mt][3], abase + roff);
            }
#pragma unroll
            for (int np = 0; np < 4; np++) {
                uint32_t boff = (uint32_t)((ks * 16 + (lane & 15)) * B_STRIDE_B
                                           + (wn * 64 + np * 16 + (lane >> 4) * 8) * 2);
                LDSM_X4T(bh[np * 2][0], bh[np * 2][1], bh[np * 2 + 1][0], bh[np * 2 + 1][1],
                         bbase + boff);
            }
#pragma unroll
            for (int mt = 0; mt < 2; mt++)
#pragma unroll
                for (int nt = 0; nt < 8; nt++)
                    MMA_F16(acc[mt][nt], ah[mt], bh[nt]);
        }
        __syncthreads();
    }

    // ---- fused epilogue ----
    int lq = lane & 3;
    int lr = lane >> 2;
    float2 ds[2][2];
    bool rv[2][2];
#pragma unroll
    for (int mt = 0; mt < 2; mt++)
#pragma unroll
        for (int hf = 0; hf < 2; hf++) {
            int row = row0 + wm * 32 + mt * 16 + hf * 8 + lr;
            rv[mt][hf] = (row < NN);
            ds[mt][hf] = rv[mt][hf] ? g_degew[row] : make_float2(0.f, 0.f);
        }

#pragma unroll
    for (int nt = 0; nt < 8; nt++) {
        int n = wn * 64 + nt * 8 + lq * 2;
        float2 cb2 = make_float2(bm[n] + be[n], bm[n + 1] + be[n + 1]);
        float2 we2 = *(const float2*)&We[n];
        float2 sc2 = make_float2(0.f, 0.f), sh2 = make_float2(0.f, 0.f);
        if (prev_bn) {
            sc2 = make_float2(psc[n], psc[n + 1]);
            sh2 = make_float2(psh[n], psh[n + 1]);
        }
        float cs0 = 0.f, cs1 = 0.f, cq0 = 0.f, cq1 = 0.f;
#pragma unroll
        for (int mt = 0; mt < 2; mt++)
#pragma unroll
            for (int hf = 0; hf < 2; hf++) {
                if (rv[mt][hf]) {
                    int row = row0 + wm * 32 + mt * 16 + hf * 8 + lr;
                    float2 xp = *(const float2*)&xprev[(long)row * H + n];
                    if (prev_bn) {
                        float u0 = fmaf(xp.x, sc2.x, sh2.x);
                        float u1 = fmaf(xp.y, sc2.y, sh2.y);
                        xp.x = u0 > 0.f ? u0 : 0.01f * u0;
                        xp.y = u1 > 0.f ? u1 : 0.01f * u1;
                    }
                    float2 dd = ds[mt][hf];
                    float v0 = acc[mt][nt][hf * 2 + 0] + dd.x * cb2.x + dd.y * we2.x + xp.x;
                    float v1 = acc[mt][nt][hf * 2 + 1] + dd.x * cb2.y + dd.y * we2.y + xp.y;
                    *(float2*)&out[(long)row * H + n] = make_float2(v0, v1);
                    cs0 += v0; cq0 += v0 * v0;
                    cs1 += v1; cq1 += v1 * v1;
                }
            }
#pragma unroll
        for (int off = 4; off <= 16; off <<= 1) {
            cs0 += __shfl_xor_sync(0xffffffffu, cs0, off);
            cq0 += __shfl_xor_sync(0xffffffffu, cq0, off);
            cs1 += __shfl_xor_sync(0xffffffffu, cs1, off);
            cq1 += __shfl_xor_sync(0xffffffffu, cq1, off);
        }
        if (lr == 0) {
            asm volatile("red.global.add.v2.f32 [%0], {%1, %2};"
                         :: "l"(&g_colstats2[n]), "f"(cs0), "f"(cq0) : "memory");
            asm volatile("red.global.add.v2.f32 [%0], {%1, %2};"
                         :: "l"(&g_colstats2[n + 1]), "f"(cs1), "f"(cq1) : "memory");
        }
    }
}

// ---------------- BN stat finalize (+ self-zero) -------------------------------
__global__ void finalize_kernel(const float* __restrict__ g,
                                const float* __restrict__ beta,
                                float* __restrict__ sc_out,
                                float* __restrict__ sh_out) {
    int j = threadIdx.x;
    float2 s = g_colstats2[j];
    float mu = s.x * (1.f / (float)NN);
    float var = s.y * (1.f / (float)NN) - mu * mu;
    float rstd = rsqrtf(var + BN_EPS);
    float sc = g[j] * rstd;
    sc_out[j] = sc;
    sh_out[j] = beta[j] - mu * sc;
    g_colstats2[j] = make_float2(0.f, 0.f);
}

// ---------------- edge prediction (BN2 inline) ----------------------------------
__global__ void predict_kernel(const int* __restrict__ ei,
                               const int* __restrict__ em,
                               const float* __restrict__ x2raw,
                               const float* __restrict__ sc,
                               const float* __restrict__ sh,
                               float* __restrict__ out) {
    int warp = (blockIdx.x * blockDim.x + threadIdx.x) >> 5;
    int lane = threadIdx.x & 31;
    if (warp >= EPRED) return;
    float4 s2 = *(const float4*)&sc[lane * 4];
    float4 h2 = *(const float4*)&sh[lane * 4];
    int e = em[warp];
    int s = ei[e];
    int t = ei[EE + e];
    float4 a = *(const float4*)&g_xini[s * H + lane * 4];
    float4 b = *(const float4*)&x2raw[t * H + lane * 4];
    b.x = fmaf(b.x, s2.x, h2.x);
    b.y = fmaf(b.y, s2.y, h2.y);
    b.z = fmaf(b.z, s2.z, h2.z);
    b.w = fmaf(b.w, s2.w, h2.w);
    float d = a.x * b.x + a.y * b.y + a.z * b.z + a.w * b.w;
#pragma unroll
    for (int o = 16; o; o >>= 1) d += __shfl_xor_sync(0xffffffffu, d, o);
    if (lane == 0) out[warp] = 1.f / (1.f + expf(-d * (1.f / 128.f)));
}

// ---------------- launch -----------------------------------------------------
extern "C" void kernel_launch(void* const* d_in, const int* in_sizes, int n_in,
                              void* d_out, int out_size) {
    const float* qf  = (const float*)d_in[0];
    const float* lf  = (const float*)d_in[1];
    const int*   ei  = (const int*)d_in[2];
    const int*   em  = (const int*)d_in[3];
    const int*   ecs = (const int*)d_in[4];
    const float* ewt = (const float*)d_in[5];
    const float* Wq  = (const float*)d_in[6];
    const float* bq  = (const float*)d_in[7];
    const float* Wl  = (const float*)d_in[8];
    const float* bl  = (const float*)d_in[9];
    const float* Wem = (const float*)d_in[10];
    const float* bem = (const float*)d_in[11];
    const float* W1m = (const float*)d_in[12];
    const float* b1m = (const float*)d_in[13];
    const float* W1e = (const float*)d_in[14];
    const float* b1e = (const float*)d_in[15];
    const float* W2m = (const float*)d_in[16];
    const float* b2m = (const float*)d_in[17];
    const float* W2e = (const float*)d_in[18];
    const float* b2e = (const float*)d_in[19];
    const float* g1    = (const float*)d_in[20];
    const float* beta1 = (const float*)d_in[21];
    const float* g2    = (const float*)d_in[22];
    const float* beta2 = (const float*)d_in[23];
    float* out = (float*)d_out;

    void *p_agg, *p_xini, *p_x1, *p_aggh, *p_degew;
    void *p_sc1, *p_sh1, *p_sc2, *p_sh2;
    void *p_w1hi, *p_w2hi;
    cudaGetSymbolAddress(&p_agg, g_agg);
    cudaGetSymbolAddress(&p_xini, g_xini);
    cudaGetSymbolAddress(&p_x1, g_x1);
    cudaGetSymbolAddress(&p_aggh, g_aggh);
    cudaGetSymbolAddress(&p_degew, g_degew);
    cudaGetSymbolAddress(&p_sc1, g_scale1);
    cudaGetSymbolAddress(&p_sh1, g_shift1);
    cudaGetSymbolAddress(&p_sc2, g_scale2);
    cudaGetSymbolAddress(&p_sh2, g_shift2);
    cudaGetSymbolAddress(&p_w1hi, g_w1hi);
    cudaGetSymbolAddress(&p_w2hi, g_w2hi);

    static int init_done = 0;
    static cudaStream_t s_edge;
    static cudaEvent_t ev_fork, ev_edge;
    if (!init_done) {
        cudaFuncSetAttribute(proj_q_mma, cudaFuncAttributeMaxDynamicSharedMemorySize,
                             SMEM_MMA);
        cudaFuncSetAttribute(layer_gemm_mma, cudaFuncAttributeMaxDynamicSharedMemorySize,
                             SMEM_MMA);
        cudaStreamCreateWithFlags(&s_edge, cudaStreamNonBlocking);
        cudaEventCreateWithFlags(&ev_fork, cudaEventDisableTiming);
        cudaEventCreateWithFlags(&ev_edge, cudaEventDisableTiming);
        init_done = 1;
    }

    cudaMemsetAsync(p_degew, 0, NN * sizeof(float2));

    // ---- fork edge-sort chain onto side stream ----
    cudaEventRecord(ev_fork, 0);
    cudaStreamWaitEvent(s_edge, ev_fork, 0);
    edge_prep_kernel<<<(ESEE + 255) / 256, 256, 0, s_edge>>>(ei, ecs, ewt, Wem, bem);
    scan1_kernel<<<SCAN_B, 256, 0, s_edge>>>();
    scan2_kernel<<<1, 512, 0, s_edge>>>();
    scan3_kernel<<<SCAN_B, 256, 0, s_edge>>>();
    placement_kernel<<<(ESEE + 255) / 256, 256, 0, s_edge>>>();
    cudaEventRecord(ev_edge, s_edge);

    // ---- main stream: projection chain ----
    prep_all_kernel<<<(QD * H + 2 * H * H + 255) / 256, 256>>>(Wq, W1m, W2m);
    proj_l_kernel<<<NL, 512>>>(lf, Wl, bl);
    proj_q_mma<<<GRID_TC, 256, SMEM_MMA>>>(qf, bq, (float*)p_xini);

    // ---- join ----
    cudaStreamWaitEvent(0, ev_edge, 0);

    // ---- layer 1 ----
    gather_kernel<<<(NN + 7) / 8, 256>>>((const float*)p_xini, (__half*)p_aggh,
                                         nullptr, nullptr, 0);
    layer_gemm_mma<<<GRID_TC, 256, SMEM_MMA>>>(
        (const __half*)p_aggh, (const __half*)p_w1hi,
        b1m, b1e, W1e, (const float*)p_xini,
        nullptr, nullptr, 0, (float*)p_agg);
    finalize_kernel<<<1, H>>>(g1, beta1, (float*)p_sc1, (float*)p_sh1);

    // ---- layer 2 ----
    gather_kernel<<<(NN + 7) / 8, 256>>>((const float*)p_agg, (__half*)p_aggh,
                                         (const float*)p_sc1, (const float*)p_sh1, 1);
    layer_gemm_mma<<<GRID_TC, 256, SMEM_MMA>>>(
        (const __half*)p_aggh, (const __half*)p_w2hi,
        b2m, b2e, W2e, (const float*)p_agg,
        (const float*)p_sc1, (const float*)p_sh1, 1, (float*)p_x1);
    finalize_kernel<<<1, H>>>(g2, beta2, (float*)p_sc2, (float*)p_sh2);
    predict_kernel<<<EPRED / 8, 256>>>(ei, em, (const float*)p_x1,
                                       (const float*)p_sc2, (const float*)p_sh2, out);
}

// round 15
// speedup vs baseline: 1.5980x; 1.1255x over previous
#include <cuda_runtime.h>
#include <cuda_fp16.h>
#include <math.h>
#include <stdint.h>

#define NQ    100000
#define NL    32
#define NN    100032
#define QD    384
#define LD    1024
#define H     128
#define EE    1000000
#define ESEE  750000
#define EPRED 250000
#define BN_EPS 1e-5f
#define SCAN_B 391               // ceil(NN/256)

// mma tile config: BM=128 x BN=128, 8 warps (4m x 2n), warp tile 32x64, pure fp16
#define BM 128
#define BK 32
#define GRID_TC 782
#define A_STRIDE_B 80            // (32+8) fp16 * 2
#define B_STRIDE_B 272           // (128+8) fp16 * 2
#define ABUF 10240               // 128 * 80
#define BBUF 8704                // 32 * 272
#define AH_OFF 0                 // 2 bufs
#define BH_OFF 20480             // 2 bufs
#define SMEM_MMA 37888

// ---------------- scratch (fp16 node features everywhere) --------------------
__device__ __align__(16) __half g_xh [NN * H];      // xini fp16
__device__ __align__(16) __half g_t1h[NN * H];      // layer-1 raw out fp16
__device__ __align__(16) __half g_x2h[NN * H];      // layer-2 raw out fp16
__device__ __align__(16) __half g_aggh[NN * H];     // gather output (GEMM A)
__device__ int    g_src[ESEE];
__device__ int    g_dst[ESEE];
__device__ int    g_esrc[ESEE];
__device__ int    g_off[NN + 1];
__device__ int    g_cursor[NN];
__device__ int    g_blk[SCAN_B];
__device__ __align__(8) float2 g_degew[NN];
__device__ __align__(8) float2 g_colstats2[H];
__device__ float g_scale1[H], g_shift1[H];
__device__ float g_scale2[H], g_shift2[H];
__device__ __align__(16) __half g_wqhi[QD * H];
__device__ __align__(16) __half g_w1hi[H * H];
__device__ __align__(16) __half g_w2hi[H * H];

// ---------------- ptx helpers ----------------------------------------------
__device__ __forceinline__ unsigned smem_u32(const void* p) {
    return (unsigned)__cvta_generic_to_shared(p);
}
__device__ __forceinline__ void cp16(unsigned dst, const void* src) {
    asm volatile("cp.async.ca.shared.global [%0], [%1], 16;" :: "r"(dst), "l"(src));
}
#define CP_COMMIT() asm volatile("cp.async.commit_group;")

#define LDSM_X4(r0, r1, r2, r3, addr) \
    asm volatile("ldmatrix.sync.aligned.m8n8.x4.shared.b16 {%0,%1,%2,%3}, [%4];" \
                 : "=r"(r0), "=r"(r1), "=r"(r2), "=r"(r3) : "r"(addr))
#define LDSM_X4T(r0, r1, r2, r3, addr) \
    asm volatile("ldmatrix.sync.aligned.m8n8.x4.trans.shared.b16 {%0,%1,%2,%3}, [%4];" \
                 : "=r"(r0), "=r"(r1), "=r"(r2), "=r"(r3) : "r"(addr))
#define MMA_F16(c, a, b) \
    asm volatile("mma.sync.aligned.m16n8k16.row.col.f32.f16.f16.f32 " \
                 "{%0,%1,%2,%3}, {%4,%5,%6,%7}, {%8,%9}, {%0,%1,%2,%3};" \
                 : "+f"((c)[0]), "+f"((c)[1]), "+f"((c)[2]), "+f"((c)[3]) \
                 : "r"((a)[0]), "r"((a)[1]), "r"((a)[2]), "r"((a)[3]), \
                   "r"((b)[0]), "r"((b)[1]))

__device__ __forceinline__ uint32_t pack_h2(float x, float y) {
    __half hx = __float2half_rn(x);
    __half hy = __float2half_rn(y);
    return ((uint32_t)__half_as_ushort(hy) << 16) | __half_as_ushort(hx);
}
__device__ __forceinline__ float4 h4_to_f4(uint2 p) {
    __half2 h0 = *(__half2*)&p.x;
    __half2 h1 = *(__half2*)&p.y;
    float2 f0 = __half22float2(h0);
    float2 f1 = __half22float2(h1);
    return make_float4(f0.x, f0.y, f1.x, f1.y);
}
__device__ __forceinline__ void a_store_h(char* smg, int off, int row, int c4, float4 v) {
    uint2 hp;
    hp.x = pack_h2(v.x, v.y);
    hp.y = pack_h2(v.z, v.w);
    *(uint2*)(smg + off + row * A_STRIDE_B + c4 * 8) = hp;
}

// ---------------- W prep: fp32 -> fp16 ------------------------------------------
__global__ void prep_all_kernel(const float* __restrict__ Wq,
                                const float* __restrict__ W1,
                                const float* __restrict__ W2) {
    int idx = blockIdx.x * blockDim.x + threadIdx.x;
    const int NQW = QD * H, NW = H * H;
    if (idx < NQW)                g_wqhi[idx] = __float2half_rn(Wq[idx]);
    else if (idx < NQW + NW)      g_w1hi[idx - NQW] = __float2half_rn(W1[idx - NQW]);
    else if (idx < NQW + 2 * NW)  g_w2hi[idx - NQW - NW] = __float2half_rn(W2[idx - NQW - NW]);
}

// ---------------- llm projection (split-K, 512 thr, fp16 out) ------------------
__global__ void proj_l_kernel(const float* __restrict__ A,
                              const float* __restrict__ W,
                              const float* __restrict__ b) {
    __shared__ float red[4][H];
    int i = blockIdx.x;
    int t = threadIdx.x;
    int j = t & 127;
    int seg = t >> 7;
    float acc = 0.f;
    const float* arow = A + i * LD + seg * 256;
    const float* wcol = W + (seg * 256) * H + j;
    for (int k = 0; k < 256; k++) acc += arow[k] * wcol[k * H];
    red[seg][j] = acc;
    __syncthreads();
    if (seg == 0) {
        float v = red[0][j] + red[1][j] + red[2][j] + red[3][j] + b[j];
        g_xh[(NQ + i) * H + j] = __float2half_rn(v);
    }
}

// ---------------- edge prep (+ zero colstats) ---------------------------------
__global__ void edge_prep_kernel(const int* __restrict__ ei,
                                 const int* __restrict__ ecs,
                                 const float* __restrict__ ewt,
                                 const float* __restrict__ Wem,
                                 const float* __restrict__ bem) {
    int i = blockIdx.x * blockDim.x + threadIdx.x;
    if (blockIdx.x == 0 && threadIdx.x < H)
        g_colstats2[threadIdx.x] = make_float2(0.f, 0.f);
    if (i >= ESEE) return;
    int e = ecs[i];
    int s = ei[e];
    int d = ei[EE + e];
    g_src[i] = s;
    g_dst[i] = d;
    float v = ewt[e] * Wem[0] + bem[0];
    v = v > 0.f ? v : 0.01f * v;
    asm volatile("red.global.add.v2.f32 [%0], {%1, %2};"
                 :: "l"(&g_degew[d]), "f"(1.0f), "f"(v) : "memory");
}

// ---------------- counting-sort scan trio --------------------------------------
__global__ void scan1_kernel() {
    __shared__ int red[256];
    int t = threadIdx.x;
    int i = blockIdx.x * 256 + t;
    int c = (i < NN) ? (int)g_degew[i].x : 0;
    red[t] = c;
    __syncthreads();
#pragma unroll
    for (int o = 128; o > 0; o >>= 1) {
        if (t < o) red[t] += red[t + o];
        __syncthreads();
    }
    if (t == 0) g_blk[blockIdx.x] = red[0];
}

__global__ void scan2_kernel() {
    __shared__ int s[512];
    int t = threadIdx.x;
    int c = (t < SCAN_B) ? g_blk[t] : 0;
    s[t] = c;
    __syncthreads();
    for (int o = 1; o < 512; o <<= 1) {
        int v = (t >= o) ? s[t - o] : 0;
        __syncthreads();
        s[t] += v;
        __syncthreads();
    }
    if (t < SCAN_B) g_blk[t] = s[t] - c;
}

__global__ void scan3_kernel() {
    __shared__ int s[256];
    int t = threadIdx.x;
    int i = blockIdx.x * 256 + t;
    int c = (i < NN) ? (int)g_degew[i].x : 0;
    s[t] = c;
    __syncthreads();
    for (int o = 1; o < 256; o <<= 1) {
        int v = (t >= o) ? s[t - o] : 0;
        __syncthreads();
        s[t] += v;
        __syncthreads();
    }
    if (i < NN) {
        int off = g_blk[blockIdx.x] + s[t] - c;
        g_off[i] = off;
        g_cursor[i] = off;
    }
    if (i == 0) g_off[NN] = ESEE;
}

__global__ void placement_kernel() {
    int i = blockIdx.x * blockDim.x + threadIdx.x;
    if (i >= ESEE) return;
    int d = g_dst[i];
    int pos = atomicAdd(&g_cursor[d], 1);
    g_esrc[pos] = g_src[i];
}

// ---------------- gather aggregation (fp16 in, fp16 out, fp32 accum) -----------
__device__ __forceinline__ float4 bn_lrelu4(float4 v, float4 s4, float4 h4) {
    v.x = fmaf(v.x, s4.x, h4.x); v.x = v.x > 0.f ? v.x : 0.01f * v.x;
    v.y = fmaf(v.y, s4.y, h4.y); v.y = v.y > 0.f ? v.y : 0.01f * v.y;
    v.z = fmaf(v.z, s4.z, h4.z); v.z = v.z > 0.f ? v.z : 0.01f * v.z;
    v.w = fmaf(v.w, s4.w, h4.w); v.w = v.w > 0.f ? v.w : 0.01f * v.w;
    return v;
}
__global__ void __launch_bounds__(256) gather_kernel(const __half* __restrict__ x,
                                                     __half* __restrict__ outh,
                                                     const float* __restrict__ sc,
                                                     const float* __restrict__ sh,
                                                     int bn) {
    int wid = threadIdx.x >> 5;
    int lane = threadIdx.x & 31;
    int node = blockIdx.x * 8 + wid;
    if (node >= NN) return;
    int o0 = g_off[node];
    int o1 = g_off[node + 1];
    float4 s4 = make_float4(1.f, 1.f, 1.f, 1.f);
    float4 h4 = make_float4(0.f, 0.f, 0.f, 0.f);
    if (bn) {
        s4 = *(const float4*)&sc[lane * 4];
        h4 = *(const float4*)&sh[lane * 4];
    }
    float4 a0 = make_float4(0.f, 0.f, 0.f, 0.f);
    float4 a1 = make_float4(0.f, 0.f, 0.f, 0.f);
    float4 a2 = make_float4(0.f, 0.f, 0.f, 0.f);
    float4 a3 = make_float4(0.f, 0.f, 0.f, 0.f);
    int e = o0;
    for (; e + 4 <= o1; e += 4) {
        int s0 = g_esrc[e], s1 = g_esrc[e + 1], s2 = g_esrc[e + 2], s3 = g_esrc[e + 3];
        float4 v0 = h4_to_f4(*(const uint2*)&x[(long)s0 * H + lane * 4]);
        float4 v1 = h4_to_f4(*(const uint2*)&x[(long)s1 * H + lane * 4]);
        float4 v2 = h4_to_f4(*(const uint2*)&x[(long)s2 * H + lane * 4]);
        float4 v3 = h4_to_f4(*(const uint2*)&x[(long)s3 * H + lane * 4]);
        if (bn) {
            v0 = bn_lrelu4(v0, s4, h4); v1 = bn_lrelu4(v1, s4, h4);
            v2 = bn_lrelu4(v2, s4, h4); v3 = bn_lrelu4(v3, s4, h4);
        }
        a0.x += v0.x; a0.y += v0.y; a0.z += v0.z; a0.w += v0.w;
        a1.x += v1.x; a1.y += v1.y; a1.z += v1.z; a1.w += v1.w;
        a2.x += v2.x; a2.y += v2.y; a2.z += v2.z; a2.w += v2.w;
        a3.x += v3.x; a3.y += v3.y; a3.z += v3.z; a3.w += v3.w;
    }
    for (; e < o1; e++) {
        int s0 = g_esrc[e];
        float4 v0 = h4_to_f4(*(const uint2*)&x[(long)s0 * H + lane * 4]);
        if (bn) v0 = bn_lrelu4(v0, s4, h4);
        a0.x += v0.x; a0.y += v0.y; a0.z += v0.z; a0.w += v0.w;
    }
    a0.x += a1.x + a2.x + a3.x;
    a0.y += a1.y + a2.y + a3.y;
    a0.z += a1.z + a2.z + a3.z;
    a0.w += a1.w + a2.w + a3.w;
    uint2 o;
    o.x = pack_h2(a0.x, a0.y);
    o.y = pack_h2(a0.z, a0.w);
    *(uint2*)&outh[(long)node * H + lane * 4] = o;
}

// ---------------- proj_q via mma.sync fp16, fp16 out ----------------------------
__global__ void __launch_bounds__(256, 2) proj_q_mma(const float* __restrict__ A,
                                                     const float* __restrict__ bias,
                                                     __half* __restrict__ out) {
    extern __shared__ char sm[];
    uint32_t sb = smem_u32(sm);
    char* smg = sm;
    int tid = threadIdx.x;
    int wid = tid >> 5;
    int lane = tid & 31;
    int wm = wid & 3;
    int wn = wid >> 2;
    int row0 = blockIdx.x * BM;

    float acc[2][8][4];
#pragma unroll
    for (int mt = 0; mt < 2; mt++)
#pragma unroll
        for (int nt = 0; nt < 8; nt++)
#pragma unroll
            for (int j = 0; j < 4; j++) acc[mt][nt][j] = 0.f;

    int af_row[4], af_c4[4];
#pragma unroll
    for (int i = 0; i < 4; i++) {
        int f = tid + i * 256;
        af_row[i] = f >> 3;
        af_c4[i] = f & 7;
    }

    float4 av[4];
#pragma unroll
    for (int i = 0; i < 4; i++) {
        int grow = row0 + af_row[i];
        if (grow >= NQ) grow = 0;
        av[i] = *(const float4*)&A[(long)grow * QD + af_c4[i] * 4];
    }
#pragma unroll
    for (int i = 0; i < 2; i++) {
        int seg = tid + i * 256;
        int br = seg >> 4, c16 = seg & 15;
        cp16(sb + BH_OFF + br * B_STRIDE_B + c16 * 16, g_wqhi + br * H + c16 * 8);
    }
    CP_COMMIT();
#pragma unroll
    for (int i = 0; i < 4; i++)
        a_store_h(smg, AH_OFF, af_row[i], af_c4[i], av[i]);

    const int TST = QD / BK;  // 12
    for (int t = 0; t < TST; t++) {
        int buf = t & 1;
        int have_next = (t + 1 < TST);
        if (have_next) {
            int k0 = (t + 1) * BK;
            int nb = buf ^ 1;
#pragma unroll
            for (int i = 0; i < 4; i++) {
                int grow = row0 + af_row[i];
                if (grow >= NQ) grow = 0;
                av[i] = *(const float4*)&A[(long)grow * QD + k0 + af_c4[i] * 4];
            }
#pragma unroll
            for (int i = 0; i < 2; i++) {
                int seg = tid + i * 256;
                int br = seg >> 4, c16 = seg & 15;
                cp16(sb + BH_OFF + nb * BBUF + br * B_STRIDE_B + c16 * 16,
                     g_wqhi + (k0 + br) * H + c16 * 8);
            }
            CP_COMMIT();
            asm volatile("cp.async.wait_group 1;");
        } else {
            asm volatile("cp.async.wait_group 0;");
        }
        __syncthreads();

        uint32_t abase = sb + AH_OFF + buf * ABUF;
        uint32_t bbase = sb + BH_OFF + buf * BBUF;
#pragma unroll
        for (int ks = 0; ks < 2; ks++) {
            uint32_t ah[2][4], bh[8][2];
#pragma unroll
            for (int mt = 0; mt < 2; mt++) {
                uint32_t roff = (uint32_t)((wm * 32 + mt * 16 + (lane & 15)) * A_STRIDE_B
                                           + ks * 32 + (lane >> 4) * 16);
                LDSM_X4(ah[mt][0], ah[mt][1], ah[mt][2], ah[mt][3], abase + roff);
            }
#pragma unroll
            for (int np = 0; np < 4; np++) {
                uint32_t boff = (uint32_t)((ks * 16 + (lane & 15)) * B_STRIDE_B
                                           + (wn * 64 + np * 16 + (lane >> 4) * 8) * 2);
                LDSM_X4T(bh[np * 2][0], bh[np * 2][1], bh[np * 2 + 1][0], bh[np * 2 + 1][1],
                         bbase + boff);
            }
#pragma unroll
            for (int mt = 0; mt < 2; mt++)
#pragma unroll
                for (int nt = 0; nt < 8; nt++)
                    MMA_F16(acc[mt][nt], ah[mt], bh[nt]);
        }
        __syncthreads();

        if (have_next) {
            int nb = buf ^ 1;
#pragma unroll
            for (int i = 0; i < 4; i++)
                a_store_h(smg, AH_OFF + nb * ABUF, af_row[i], af_c4[i], av[i]);
        }
    }

#pragma unroll
    for (int mt = 0; mt < 2; mt++) {
        int m0r = row0 + wm * 32 + mt * 16 + (lane >> 2);
        int m1r = m0r + 8;
#pragma unroll
        for (int nt = 0; nt < 8; nt++) {
            int n = wn * 64 + nt * 8 + (lane & 3) * 2;
            float2 bv = *(const float2*)&bias[n];
            if (m0r < NQ)
                *(uint32_t*)&out[(long)m0r * H + n] =
                    pack_h2(acc[mt][nt][0] + bv.x, acc[mt][nt][1] + bv.y);
            if (m1r < NQ)
                *(uint32_t*)&out[(long)m1r * H + n] =
                    pack_h2(acc[mt][nt][2] + bv.x, acc[mt][nt][3] + bv.y);
        }
    }
}

// ---------------- layer GEMM via mma.sync fp16 (fp16 in/out) --------------------
__global__ void __launch_bounds__(256, 2) layer_gemm_mma(
        const __half* __restrict__ Ah,
        const __half* __restrict__ Whi,
        const float* __restrict__ bm, const float* __restrict__ be,
        const float* __restrict__ We,
        const __half* __restrict__ xprev,
        const float* __restrict__ psc, const float* __restrict__ psh,
        int prev_bn,
        __half* __restrict__ out) {
    extern __shared__ char sm[];
    uint32_t sb = smem_u32(sm);
    int tid = threadIdx.x;
    int wid = tid >> 5;
    int lane = tid & 31;
    int wm = wid & 3;
    int wn = wid >> 2;
    int row0 = blockIdx.x * BM;

    float acc[2][8][4];
#pragma unroll
    for (int mt = 0; mt < 2; mt++)
#pragma unroll
        for (int nt = 0; nt < 8; nt++)
#pragma unroll
            for (int j = 0; j < 4; j++) acc[mt][nt][j] = 0.f;

    int ar[2], ac[2];
#pragma unroll
    for (int i = 0; i < 2; i++) {
        int c = tid + i * 256;
        int r = c >> 2;
        ar[i] = (row0 + r < NN) ? (row0 + r) : 0;
        ac[i] = (c & 3) * 8;
    }

#pragma unroll
    for (int i = 0; i < 2; i++) {
        int c = tid + i * 256;
        cp16(sb + AH_OFF + (c >> 2) * A_STRIDE_B + (c & 3) * 16,
             Ah + (long)ar[i] * H + ac[i]);
    }
#pragma unroll
    for (int i = 0; i < 2; i++) {
        int seg = tid + i * 256;
        int br = seg >> 4, c16 = seg & 15;
        cp16(sb + BH_OFF + br * B_STRIDE_B + c16 * 16, Whi + br * H + c16 * 8);
    }
    CP_COMMIT();

    const int TST = H / BK;  // 4
    for (int t = 0; t < TST; t++) {
        int buf = t & 1;
        int have_next = (t + 1 < TST);
        if (have_next) {
            int k0 = (t + 1) * BK;
            int nb = buf ^ 1;
#pragma unroll
            for (int i = 0; i < 2; i++) {
                int c = tid + i * 256;
                cp16(sb + AH_OFF + nb * ABUF + (c >> 2) * A_STRIDE_B + (c & 3) * 16,
                     Ah + (long)ar[i] * H + k0 + ac[i]);
            }
#pragma unroll
            for (int i = 0; i < 2; i++) {
                int seg = tid + i * 256;
                int br = seg >> 4, c16 = seg & 15;
                cp16(sb + BH_OFF + nb * BBUF + br * B_STRIDE_B + c16 * 16,
                     Whi + (k0 + br) * H + c16 * 8);
            }
            CP_COMMIT();
            asm volatile("cp.async.wait_group 1;");
        } else {
            asm volatile("cp.async.wait_group 0;");
        }
        __syncthreads();

        uint32_t abase = sb + AH_OFF + buf * ABUF;
        uint32_t bbase = sb + BH_OFF + buf * BBUF;
#pragma unroll
        for (int ks = 0; ks < 2; ks++) {
            uint32_t ah[2][4], bh[8][2];
#pragma unroll
            for (int mt = 0; mt < 2; mt++) {
                uint32_t roff = (uint32_t)((wm * 32 + mt * 16 + (lane & 15)) * A_STRIDE_B
                                           + ks * 32 + (lane >> 4) * 16);
                LDSM_X4(ah[mt][0], ah[mt][1], ah[mt][2], ah[mt][3], abase + roff);
            }
#pragma unroll
            for (int np = 0; np < 4; np++) {
                uint32_t boff = (uint32_t)((ks * 16 + (lane & 15)) * B_STRIDE_B
                                           + (wn * 64 + np * 16 + (lane >> 4) * 8) * 2);
                LDSM_X4T(bh[np * 2][0], bh[np * 2][1], bh[np * 2 + 1][0], bh[np * 2 + 1][1],
                         bbase + boff);
            }
#pragma unroll
            for (int mt = 0; mt < 2; mt++)
#pragma unroll
                for (int nt = 0; nt < 8; nt++)
                    MMA_F16(acc[mt][nt], ah[mt], bh[nt]);
        }
        __syncthreads();
    }

    // ---- fused epilogue: deg/sumew/residual + BN column stats (fp32 math) -----
    int lq = lane & 3;
    int lr = lane >> 2;
    float2 ds[2][2];
    bool rv[2][2];
#pragma unroll
    for (int mt = 0; mt < 2; mt++)
#pragma unroll
        for (int hf = 0; hf < 2; hf++) {
            int row = row0 + wm * 32 + mt * 16 + hf * 8 + lr;
            rv[mt][hf] = (row < NN);
            ds[mt][hf] = rv[mt][hf] ? g_degew[row] : make_float2(0.f, 0.f);
        }

#pragma unroll
    for (int nt = 0; nt < 8; nt++) {
        int n = wn * 64 + nt * 8 + lq * 2;
        float2 cb2 = make_float2(bm[n] + be[n], bm[n + 1] + be[n + 1]);
        float2 we2 = *(const float2*)&We[n];
        float2 sc2 = make_float2(0.f, 0.f), sh2 = make_float2(0.f, 0.f);
        if (prev_bn) {
            sc2 = make_float2(psc[n], psc[n + 1]);
            sh2 = make_float2(psh[n], psh[n + 1]);
        }
        float cs0 = 0.f, cs1 = 0.f, cq0 = 0.f, cq1 = 0.f;
#pragma unroll
        for (int mt = 0; mt < 2; mt++)
#pragma unroll
            for (int hf = 0; hf < 2; hf++) {
                if (rv[mt][hf]) {
                    int row = row0 + wm * 32 + mt * 16 + hf * 8 + lr;
                    __half2 hp = *(const __half2*)&xprev[(long)row * H + n];
                    float2 xp = __half22float2(hp);
                    if (prev_bn) {
                        float u0 = fmaf(xp.x, sc2.x, sh2.x);
                        float u1 = fmaf(xp.y, sc2.y, sh2.y);
                        xp.x = u0 > 0.f ? u0 : 0.01f * u0;
                        xp.y = u1 > 0.f ? u1 : 0.01f * u1;
                    }
                    float2 dd = ds[mt][hf];
                    float v0 = acc[mt][nt][hf * 2 + 0] + dd.x * cb2.x + dd.y * we2.x + xp.x;
                    float v1 = acc[mt][nt][hf * 2 + 1] + dd.x * cb2.y + dd.y * we2.y + xp.y;
                    *(uint32_t*)&out[(long)row * H + n] = pack_h2(v0, v1);
                    cs0 += v0; cq0 += v0 * v0;
                    cs1 += v1; cq1 += v1 * v1;
                }
            }
#pragma unroll
        for (int off = 4; off <= 16; off <<= 1) {
            cs0 += __shfl_xor_sync(0xffffffffu, cs0, off);
            cq0 += __shfl_xor_sync(0xffffffffu, cq0, off);
            cs1 += __shfl_xor_sync(0xffffffffu, cs1, off);
            cq1 += __shfl_xor_sync(0xffffffffu, cq1, off);
        }
        if (lr == 0) {
            asm volatile("red.global.add.v2.f32 [%0], {%1, %2};"
                         :: "l"(&g_colstats2[n]), "f"(cs0), "f"(cq0) : "memory");
            asm volatile("red.global.add.v2.f32 [%0], {%1, %2};"
                         :: "l"(&g_colstats2[n + 1]), "f"(cs1), "f"(cq1) : "memory");
        }
    }
}

// ---------------- BN stat finalize (+ self-zero) -------------------------------
__global__ void finalize_kernel(const float* __restrict__ g,
                                const float* __restrict__ beta,
                                float* __restrict__ sc_out,
                                float* __restrict__ sh_out) {
    int j = threadIdx.x;
    float2 s = g_colstats2[j];
    float mu = s.x * (1.f / (float)NN);
    float var = s.y * (1.f / (float)NN) - mu * mu;
    float rstd = rsqrtf(var + BN_EPS);
    float sc = g[j] * rstd;
    sc_out[j] = sc;
    sh_out[j] = beta[j] - mu * sc;
    g_colstats2[j] = make_float2(0.f, 0.f);
}

// ---------------- edge prediction (fp16 features, BN2 inline) -------------------
__global__ void predict_kernel(const int* __restrict__ ei,
                               const int* __restrict__ em,
                               const __half* __restrict__ x2h,
                               const float* __restrict__ sc,
                               const float* __restrict__ sh,
                               float* __restrict__ out) {
    int warp = (blockIdx.x * blockDim.x + threadIdx.x) >> 5;
    int lane = threadIdx.x & 31;
    if (warp >= EPRED) return;
    float4 s2 = *(const float4*)&sc[lane * 4];
    float4 h2 = *(const float4*)&sh[lane * 4];
    int e = em[warp];
    int s = ei[e];
    int t = ei[EE + e];
    float4 a = h4_to_f4(*(const uint2*)&g_xh[(long)s * H + lane * 4]);
    float4 b = h4_to_f4(*(const uint2*)&x2h[(long)t * H + lane * 4]);
    b.x = fmaf(b.x, s2.x, h2.x);
    b.y = fmaf(b.y, s2.y, h2.y);
    b.z = fmaf(b.z, s2.z, h2.z);
    b.w = fmaf(b.w, s2.w, h2.w);
    float d = a.x * b.x + a.y * b.y + a.z * b.z + a.w * b.w;
#pragma unroll
    for (int o = 16; o; o >>= 1) d += __shfl_xor_sync(0xffffffffu, d, o);
    if (lane == 0) out[warp] = 1.f / (1.f + expf(-d * (1.f / 128.f)));
}

// ---------------- launch -----------------------------------------------------
extern "C" void kernel_launch(void* const* d_in, const int* in_sizes, int n_in,
                              void* d_out, int out_size) {
    const float* qf  = (const float*)d_in[0];
    const float* lf  = (const float*)d_in[1];
    const int*   ei  = (const int*)d_in[2];
    const int*   em  = (const int*)d_in[3];
    const int*   ecs = (const int*)d_in[4];
    const float* ewt = (const float*)d_in[5];
    const float* Wq  = (const float*)d_in[6];
    const float* bq  = (const float*)d_in[7];
    const float* Wl  = (const float*)d_in[8];
    const float* bl  = (const float*)d_in[9];
    const float* Wem = (const float*)d_in[10];
    const float* bem = (const float*)d_in[11];
    const float* W1m = (const float*)d_in[12];
    const float* b1m = (const float*)d_in[13];
    const float* W1e = (const float*)d_in[14];
    const float* b1e = (const float*)d_in[15];
    const float* W2m = (const float*)d_in[16];
    const float* b2m = (const float*)d_in[17];
    const float* W2e = (const float*)d_in[18];
    const float* b2e = (const float*)d_in[19];
    const float* g1    = (const float*)d_in[20];
    const float* beta1 = (const float*)d_in[21];
    const float* g2    = (const float*)d_in[22];
    const float* beta2 = (const float*)d_in[23];
    float* out = (float*)d_out;

    void *p_xh, *p_t1h, *p_x2h, *p_aggh, *p_degew;
    void *p_sc1, *p_sh1, *p_sc2, *p_sh2;
    void *p_w1hi, *p_w2hi;
    cudaGetSymbolAddress(&p_xh, g_xh);
    cudaGetSymbolAddress(&p_t1h, g_t1h);
    cudaGetSymbolAddress(&p_x2h, g_x2h);
    cudaGetSymbolAddress(&p_aggh, g_aggh);
    cudaGetSymbolAddress(&p_degew, g_degew);
    cudaGetSymbolAddress(&p_sc1, g_scale1);
    cudaGetSymbolAddress(&p_sh1, g_shift1);
    cudaGetSymbolAddress(&p_sc2, g_scale2);
    cudaGetSymbolAddress(&p_sh2, g_shift2);
    cudaGetSymbolAddress(&p_w1hi, g_w1hi);
    cudaGetSymbolAddress(&p_w2hi, g_w2hi);

    static int init_done = 0;
    static cudaStream_t s_edge;
    static cudaEvent_t ev_fork, ev_edge;
    if (!init_done) {
        cudaFuncSetAttribute(proj_q_mma, cudaFuncAttributeMaxDynamicSharedMemorySize,
                             SMEM_MMA);
        cudaFuncSetAttribute(layer_gemm_mma, cudaFuncAttributeMaxDynamicSharedMemorySize,
                             SMEM_MMA);
        cudaStreamCreateWithFlags(&s_edge, cudaStreamNonBlocking);
        cudaEventCreateWithFlags(&ev_fork, cudaEventDisableTiming);
        cudaEventCreateWithFlags(&ev_edge, cudaEventDisableTiming);
        init_done = 1;
    }

    cudaMemsetAsync(p_degew, 0, NN * sizeof(float2));

    // ---- fork edge-sort chain onto side stream ----
    cudaEventRecord(ev_fork, 0);
    cudaStreamWaitEvent(s_edge, ev_fork, 0);
    edge_prep_kernel<<<(ESEE + 255) / 256, 256, 0, s_edge>>>(ei, ecs, ewt, Wem, bem);
    scan1_kernel<<<SCAN_B, 256, 0, s_edge>>>();
    scan2_kernel<<<1, 512, 0, s_edge>>>();
    scan3_kernel<<<SCAN_B, 256, 0, s_edge>>>();
    placement_kernel<<<(ESEE + 255) / 256, 256, 0, s_edge>>>();
    cudaEventRecord(ev_edge, s_edge);

    // ---- main stream: projection chain ----
    prep_all_kernel<<<(QD * H + 2 * H * H + 255) / 256, 256>>>(Wq, W1m, W2m);
    proj_l_kernel<<<NL, 512>>>(lf, Wl, bl);
    proj_q_mma<<<GRID_TC, 256, SMEM_MMA>>>(qf, bq, (__half*)p_xh);

    // ---- join ----
    cudaStreamWaitEvent(0, ev_edge, 0);

    // ---- layer 1 ----
    gather_kernel<<<(NN + 7) / 8, 256>>>((const __half*)p_xh, (__half*)p_aggh,
                                         nullptr, nullptr, 0);
    layer_gemm_mma<<<GRID_TC, 256, SMEM_MMA>>>(
        (const __half*)p_aggh, (const __half*)p_w1hi,
        b1m, b1e, W1e, (const __half*)p_xh,
        nullptr, nullptr, 0, (__half*)p_t1h);
    finalize_kernel<<<1, H>>>(g1, beta1, (float*)p_sc1, (float*)p_sh1);

    // ---- layer 2 ----
    gather_kernel<<<(NN + 7) / 8, 256>>>((const __half*)p_t1h, (__half*)p_aggh,
                                         (const float*)p_sc1, (const float*)p_sh1, 1);
    layer_gemm_mma<<<GRID_TC, 256, SMEM_MMA>>>(
        (const __half*)p_aggh, (const __half*)p_w2hi,
        b2m, b2e, W2e, (const __half*)p_t1h,
        (const float*)p_sc1, (const float*)p_sh1, 1, (__half*)p_x2h);
    finalize_kernel<<<1, H>>>(g2, beta2, (float*)p_sc2, (float*)p_sh2);
    predict_kernel<<<EPRED / 8, 256>>>(ei, em, (const __half*)p_x2h,
                                       (const float*)p_sc2, (const float*)p_sh2, out);
}